// round 10
// baseline (speedup 1.0000x reference)
#include <cuda_runtime.h>
#include <cuda_bf16.h>
#include <math.h>

#define BQ   32768
#define NND  5
#define HDIM 128
#define NE   10

#define OFF_V    (BQ*NND*32)
#define OFF_HID  (2*BQ*NND*32)
#define OFF_LOSS (OFF_HID + 2*BQ*HDIM)

#define ZALPHA 1.959963984540054f

// fragment arena offsets (uint4 units): each uint4 = {bh.x,bh.y,bl.x,bl.y}
#define WF_ENC1 0
#define WF_ENC2 5120
#define WF_GCN  25600
#define WF_MU   33792
#define WF_SIG  37888
#define WF_CM1  41984
#define WF_CM2  46080
#define WF_DEC1 50176
#define WF_DEC2 70656
#define WF_GI   80896
#define WF_GH   105472
#define WF_TOT  130048

// ----------------------------- device scratch -----------------------------
__device__ float g_bufA[BQ*NND*HDIM];
__device__ float g_bufB[BQ*NND*HDIM];
__device__ float g_mean[BQ*NND*HDIM];
__device__ float g_z  [BQ*NND*HDIM];
__device__ uint4 g_Wf [WF_TOT];
__device__ float g_klpart[5120];
__device__ float g_lzpart[5120];
__device__ float g_losspart[5120*132];
__device__ float g_facc[134];

// ------------------------------- helpers ----------------------------------
__device__ __forceinline__ float warp_sum(float v){
#pragma unroll
  for (int o=16;o>0;o>>=1) v += __shfl_xor_sync(0xffffffffu, v, o);
  return v;
}
__device__ __forceinline__ float softplusf(float x){
  return fmaxf(x,0.f) + log1pf(expf(-fabsf(x)));
}
__device__ __forceinline__ float mishf(float x){ return x*tanhf(softplusf(x)); }
__device__ __forceinline__ float sigmf(float x){ return 1.f/(1.f+expf(-x)); }

#define BLOCK_REDUCE8_TO(part, val)                                     \
  do {                                                                  \
    float _v = warp_sum(val);                                           \
    __shared__ float _sred[8];                                          \
    if ((threadIdx.x & 31) == 0) _sred[threadIdx.x >> 5] = _v;          \
    __syncthreads();                                                    \
    if (threadIdx.x == 0)                                               \
      part[blockIdx.x] = ((_sred[0]+_sred[1]) + (_sred[2]+_sred[3]))    \
                       + ((_sred[4]+_sred[5]) + (_sred[6]+_sred[7]));   \
  } while (0)

__device__ __forceinline__ unsigned pkh(float x, float y){
  unsigned short a = __bfloat16_as_ushort(__float2bfloat16_rn(x));
  unsigned short b = __bfloat16_as_ushort(__float2bfloat16_rn(y));
  return ((unsigned)b<<16) | (unsigned)a;
}
__device__ __forceinline__ float bf16f(float x){
  return __bfloat162float(__float2bfloat16_rn(x));
}
__device__ __forceinline__ unsigned sptr(const void* p){
  return (unsigned)__cvta_generic_to_shared(p);
}
__device__ __forceinline__ void ldsm4(unsigned a, unsigned &r0, unsigned &r1,
                                      unsigned &r2, unsigned &r3){
  asm volatile("ldmatrix.sync.aligned.m8n8.x4.shared.b16 {%0,%1,%2,%3}, [%4];"
               : "=r"(r0),"=r"(r1),"=r"(r2),"=r"(r3) : "r"(a));
}
__device__ __forceinline__ void mma16816(float* c, const unsigned* a,
                                         unsigned b0, unsigned b1){
  asm volatile("mma.sync.aligned.m16n8k16.row.col.f32.bf16.bf16.f32 "
      "{%0,%1,%2,%3},{%4,%5,%6,%7},{%8,%9},{%0,%1,%2,%3};"
      : "+f"(c[0]),"+f"(c[1]),"+f"(c[2]),"+f"(c[3])
      : "r"(a[0]),"r"(a[1]),"r"(a[2]),"r"(a[3]),"r"(b0),"r"(b1));
}
__device__ __forceinline__ void mma3(float* c, const unsigned* ah,
    const unsigned* al, uint4 b){
  mma16816(c, ah, b.x, b.y);
  mma16816(c, al, b.x, b.y);
  mma16816(c, ah, b.z, b.w);
}

__device__ __forceinline__ void split_st(float4 v, __nv_bfloat16* sh,
    __nv_bfloat16* sl, int off){
  *(uint2*)&sh[off] = make_uint2(pkh(v.x,v.y), pkh(v.z,v.w));
  *(uint2*)&sl[off] = make_uint2(pkh(v.x-bf16f(v.x), v.y-bf16f(v.y)),
                                 pkh(v.z-bf16f(v.z), v.w-bf16f(v.w)));
}

template<int ROWS, int KC, int LDA, int NT_>
__device__ __forceinline__ void stage_split(const float* __restrict__ A, int arst,
    __nv_bfloat16* sh, __nv_bfloat16* sl, int t){
  const int C4 = KC/4;
  for (int f=t; f<ROWS*C4; f+=NT_){
    int r = f/C4, c4 = (f%C4)*4;
    float4 v = *(const float4*)&A[(long)r*arst + c4];
    split_st(v, sh, sl, r*LDA+c4);
  }
}

// 3-term bf16 split mainloop, 1 m16-tile per warp, NT n8-tiles, uint4 frags
template<int KT, int NT, int NTOT, int LDA>
__device__ __forceinline__ void hmma_row(const __nv_bfloat16* sh,
    const __nv_bfloat16* sl, const uint4* __restrict__ Wf,
    int n8base, int rowbase, int lane, float (&c)[NT][4]){
#pragma unroll
  for (int nt=0;nt<NT;nt++)
#pragma unroll
    for (int i=0;i<4;i++) c[nt][i] = 0.f;
  int sub = lane>>3;
  int m_off = ((sub&1)<<3) + (lane&7);
  int k_off = (sub>>1)<<3;
#pragma unroll 1
  for (int kt=0; kt<KT; kt++){
    uint4 b[NT];
#pragma unroll
    for (int nt=0;nt<NT;nt++)
      b[nt] = Wf[((kt*NTOT + n8base + nt)<<5) + lane];
    unsigned ah[4], al[4];
    int ro = (rowbase + m_off)*LDA + kt*16 + k_off;
    ldsm4(sptr(&sh[ro]), ah[0],ah[1],ah[2],ah[3]);
    ldsm4(sptr(&sl[ro]), al[0],al[1],al[2],al[3]);
#pragma unroll
    for (int nt=0;nt<NT;nt++)
      mma3(c[nt], ah, al, b[nt]);
  }
}

// --------------------------- single pack kernel ----------------------------
__global__ void k_packall(
    const float* __restrict__ encW1, const float* __restrict__ encW2,
    const float* __restrict__ gcnW,  const float* __restrict__ muW,
    const float* __restrict__ sigW,  const float* __restrict__ cmW1,
    const float* __restrict__ cmW2,  const float* __restrict__ decW1,
    const float* __restrict__ decW2, const float* __restrict__ giW,
    const float* __restrict__ ghW){
  int idx = blockIdx.x*256 + threadIdx.x;
  if (idx >= WF_TOT) return;
  const float* src; int K, N, trans, base, per, mst;
  if      (idx < WF_ENC2){ src=encW1; K=32; N=128; trans=0; base=WF_ENC1; per=1024; mst=4096; }
  else if (idx < WF_GCN ){ src=encW2; K=128;N=128; trans=0; base=WF_ENC2; per=4096; mst=16384;}
  else if (idx < WF_MU  ){ src=gcnW;  K=128;N=128; trans=0; base=WF_GCN;  per=4096; mst=16384;}
  else if (idx < WF_SIG ){ src=muW;   K=128;N=128; trans=0; base=WF_MU;   per=4096; mst=16384;}
  else if (idx < WF_CM1 ){ src=sigW;  K=128;N=128; trans=0; base=WF_SIG;  per=4096; mst=16384;}
  else if (idx < WF_CM2 ){ src=cmW1;  K=128;N=128; trans=0; base=WF_CM1;  per=4096; mst=16384;}
  else if (idx < WF_DEC1){ src=cmW2;  K=128;N=128; trans=0; base=WF_CM2;  per=4096; mst=16384;}
  else if (idx < WF_DEC2){ src=decW1; K=128;N=128; trans=0; base=WF_DEC1; per=4096; mst=16384;}
  else if (idx < WF_GI  ){ src=decW2; K=128;N=64;  trans=0; base=WF_DEC2; per=2048; mst=8192; }
  else if (idx < WF_GH  ){ src=giW;   K=128;N=128; trans=1; base=WF_GI;   per=4096; mst=16384;}
  else                   { src=ghW;   K=128;N=128; trans=1; base=WF_GH;   per=4096; mst=16384;}
  int rr = idx - base;
  int m = rr / per, r = rr % per;
  int lane = r & 31;
  int n8 = (r>>5) % (N>>3);
  int kt = (r>>5) / (N>>3);
  int n = n8*8 + (lane>>2);
  int k0 = kt*16 + ((lane&3)<<1);
  const float* S = src + (long)m*mst;
  float w0,w1,w2,w3;
  if (trans){
    w0=S[n*K+k0]; w1=S[n*K+k0+1]; w2=S[n*K+k0+8]; w3=S[n*K+k0+9];
  } else {
    w0=S[k0*N+n]; w1=S[(k0+1)*N+n]; w2=S[(k0+8)*N+n]; w3=S[(k0+9)*N+n];
  }
  uint4 o;
  o.x = pkh(w0,w1);
  o.y = pkh(w2,w3);
  o.z = pkh(w0-bf16f(w0), w1-bf16f(w1));
  o.w = pkh(w2-bf16f(w2), w3-bf16f(w3));
  g_Wf[idx] = o;
}

// ------------------------------ encoder ------------------------------------
__global__ __launch_bounds__(256,4) void k_enc(
    const float* __restrict__ x, const float* __restrict__ b1,
    const float* __restrict__ b2){
  __shared__ __align__(16) __nv_bfloat16 xh[32*40], xl[32*40];
  __shared__ __align__(16) __nv_bfloat16 hh[32*136], hl[32*136];
  int t = threadIdx.x, lane = t&31, warp = t>>5;
  int wrow = warp>>2, wcol = warp&3;
  int n = blockIdx.y;
  long b0 = (long)blockIdx.x*32;
  stage_split<32,32,40,256>(x + b0*160 + n*32, 160, xh, xl, t);
  __syncthreads();
  float c[4][4];
  hmma_row<2,4,16,40>(xh, xl, &g_Wf[WF_ENC1 + n*1024], wcol*4, wrow*16, lane, c);
  __syncthreads();
  {
    int r0 = wrow*16 + (lane>>2);
#pragma unroll
    for (int nt=0;nt<4;nt++){
      int col = (wcol*4+nt)*8 + ((lane&3)<<1);
      float2 bb = *(const float2*)&b1[n*128 + col];
      float v00=fmaxf(c[nt][0]+bb.x,0.f), v01=fmaxf(c[nt][1]+bb.y,0.f);
      float v10=fmaxf(c[nt][2]+bb.x,0.f), v11=fmaxf(c[nt][3]+bb.y,0.f);
      *(unsigned*)&hh[r0*136+col] = pkh(v00,v01);
      *(unsigned*)&hl[r0*136+col] = pkh(v00-bf16f(v00), v01-bf16f(v01));
      *(unsigned*)&hh[(r0+8)*136+col] = pkh(v10,v11);
      *(unsigned*)&hl[(r0+8)*136+col] = pkh(v10-bf16f(v10), v11-bf16f(v11));
    }
  }
  __syncthreads();
  hmma_row<8,4,16,136>(hh, hl, &g_Wf[WF_ENC2 + n*4096], wcol*4, wrow*16, lane, c);
  {
    long r0 = b0 + wrow*16 + (lane>>2);
#pragma unroll
    for (int nt=0;nt<4;nt++){
      int col = (wcol*4+nt)*8 + ((lane&3)<<1);
      float2 bb = *(const float2*)&b2[n*128 + col];
      *(float2*)&g_bufA[r0*640 + n*128 + col] =
          make_float2(c[nt][0]+bb.x, c[nt][1]+bb.y);
      *(float2*)&g_bufA[(r0+8)*640 + n*128 + col] =
          make_float2(c[nt][2]+bb.x, c[nt][3]+bb.y);
    }
  }
}

// ------------------- GCN: fused aggregation + GEMM -------------------------
__global__ __launch_bounds__(256,4) void k_gcn(
    int l, const float* __restrict__ ew,
    const int* __restrict__ esrc, const int* __restrict__ edst,
    const float* __restrict__ bias){
  __shared__ __align__(16) __nv_bfloat16 sh[32*136], sl[32*136];
  __shared__ int s_src[NE], s_dst[NE];
  int t = threadIdx.x, lane = t&31, warp = t>>5;
  int wrow = warp>>2, wcol = warp&3;
  const float* gin  = (l==0) ? g_bufA : g_bufB;
  float*       gout = (l==0) ? g_bufB : g_bufA;
  long b0 = (long)blockIdx.x*32;
  if (t < NE){ s_src[t] = esrc[t]; s_dst[t] = edst[t]; }
  __syncthreads();
  for (int f=t; f<32*32; f+=256){
    int r = f>>5, c4 = (f&31)<<2;
    long R = b0 + r;
    int b = (int)(R/5), v = (int)(R - 5l*b);
    const float* row = gin + (long)b*640;
    float4 a = *(const float4*)&row[v*128 + c4];
#pragma unroll
    for (int e=0;e<NE;e++){
      if (s_dst[e] == v){
        float w = __ldg(&ew[b*NE + e]);
        float4 g = *(const float4*)&row[s_src[e]*128 + c4];
        a.x += w*g.x; a.y += w*g.y; a.z += w*g.z; a.w += w*g.w;
      }
    }
    split_st(a, sh, sl, r*136+c4);
  }
  __syncthreads();
  float c[4][4];
  hmma_row<8,4,16,136>(sh, sl, &g_Wf[WF_GCN + l*4096], wcol*4, wrow*16, lane, c);
  {
    long r0 = b0 + wrow*16 + (lane>>2);
#pragma unroll
    for (int nt=0;nt<4;nt++){
      int col = (wcol*4+nt)*8 + ((lane&3)<<1);
      float2 bb = *(const float2*)&bias[l*128 + col];
      *(float2*)&gout[r0*128 + col] = make_float2(
          fmaxf(c[nt][0]+bb.x,0.f), fmaxf(c[nt][1]+bb.y,0.f));
      *(float2*)&gout[(r0+8)*128 + col] = make_float2(
          fmaxf(c[nt][2]+bb.x,0.f), fmaxf(c[nt][3]+bb.y,0.f));
    }
  }
}

// ----------------------- mu/sig heads + KL ---------------------------------
__global__ __launch_bounds__(256,4) void k_musig(
    const float* __restrict__ mub, const float* __restrict__ sigb){
  __shared__ __align__(16) __nv_bfloat16 sh[32*136], sl[32*136];
  int t = threadIdx.x, lane = t&31, warp = t>>5;
  int wrow = warp>>2, wcol = warp&3;
  long b0 = (long)blockIdx.x*32;
  stage_split<32,128,136,256>(g_bufA + b0*128, 128, sh, sl, t);
  __syncthreads();
  float c[4][4];
  float kll = 0.f;
  hmma_row<8,4,16,136>(sh, sl, &g_Wf[WF_MU], wcol*4, wrow*16, lane, c);
  {
    long r0 = b0 + wrow*16 + (lane>>2);
#pragma unroll
    for (int nt=0;nt<4;nt++){
      int col = (wcol*4+nt)*8 + ((lane&3)<<1);
      float2 bb = *(const float2*)&mub[col];
      float m00=c[nt][0]+bb.x, m01=c[nt][1]+bb.y;
      float m10=c[nt][2]+bb.x, m11=c[nt][3]+bb.y;
      *(float2*)&g_mean[r0*128 + col]     = make_float2(m00,m01);
      *(float2*)&g_mean[(r0+8)*128 + col] = make_float2(m10,m11);
      kll += m00*m00 + m01*m01 + m10*m10 + m11*m11;
    }
  }
  hmma_row<8,4,16,136>(sh, sl, &g_Wf[WF_SIG], wcol*4, wrow*16, lane, c);
#pragma unroll
  for (int nt=0;nt<4;nt++){
    int col = (wcol*4+nt)*8 + ((lane&3)<<1);
    float2 bb = *(const float2*)&sigb[col];
#pragma unroll
    for (int i=0;i<4;i++){
      float sp = softplusf(c[nt][i] + ((i&1)?bb.y:bb.x));
      float var = sp*sp;
      kll += var - logf(var + 1e-8f) - 1.f;
    }
  }
  BLOCK_REDUCE8_TO(g_klpart, kll);
}

// ------------- GRU: fused dual-GEMM + gates (one kernel per layer) ---------
__global__ __launch_bounds__(256) void k_gru(
    int l, const float* __restrict__ xin, const float* __restrict__ hist,
    const float* __restrict__ bih, const float* __restrict__ bhh,
    float* __restrict__ hout){
  __shared__ __align__(16) __nv_bfloat16 xh[32*136], xl[32*136];
  __shared__ __align__(16) __nv_bfloat16 hhs[32*136], hls[32*136];
  int t = threadIdx.x, lane = t&31, warp = t>>5;   // 8 warps
  long b0 = (long)blockIdx.x*32;
  for (int f=t; f<32*32; f+=256){
    int r = f>>5, c4 = (f&31)<<2;
    long b = b0 + r;
    float4 v;
    if (xin){
      v = *(const float4*)&xin[b*128 + c4];
    } else {
      v = *(const float4*)&g_mean[b*640 + c4];
#pragma unroll
      for (int vv=1; vv<5; vv++){
        float4 m = *(const float4*)&g_mean[b*640 + vv*128 + c4];
        v.x+=m.x; v.y+=m.y; v.z+=m.z; v.w+=m.w;
      }
      v.x*=0.2f; v.y*=0.2f; v.z*=0.2f; v.w*=0.2f;
    }
    split_st(v, xh, xl, r*136+c4);
    float4 hv = *(const float4*)&hist[((long)l*BQ + b)*128 + c4];
    split_st(hv, hhs, hls, r*136+c4);
  }
  __syncthreads();
  float cr[2][2][4], cz[2][2][4], cin[2][2][4], chn[2][2][4];
#pragma unroll
  for (int mt=0;mt<2;mt++)
#pragma unroll
    for (int nt=0;nt<2;nt++)
#pragma unroll
      for (int i=0;i<4;i++){ cr[mt][nt][i]=0.f; cz[mt][nt][i]=0.f;
                             cin[mt][nt][i]=0.f; chn[mt][nt][i]=0.f; }
  int sub = lane>>3;
  int m_off = ((sub&1)<<3) + (lane&7);
  int k_off = (sub>>1)<<3;
  const uint4* Wi = &g_Wf[WF_GI + l*3*4096];
  const uint4* Wh = &g_Wf[WF_GH + l*3*4096];
#pragma unroll 1
  for (int kt=0; kt<8; kt++){
    unsigned axh[2][4], axl[2][4], ahh[2][4], ahl[2][4];
#pragma unroll
    for (int mt=0;mt<2;mt++){
      int ro = (mt*16 + m_off)*136 + kt*16 + k_off;
      ldsm4(sptr(&xh[ro]),  axh[mt][0],axh[mt][1],axh[mt][2],axh[mt][3]);
      ldsm4(sptr(&xl[ro]),  axl[mt][0],axl[mt][1],axl[mt][2],axl[mt][3]);
      ldsm4(sptr(&hhs[ro]), ahh[mt][0],ahh[mt][1],ahh[mt][2],ahh[mt][3]);
      ldsm4(sptr(&hls[ro]), ahl[mt][0],ahl[mt][1],ahl[mt][2],ahl[mt][3]);
    }
#pragma unroll
    for (int nt=0;nt<2;nt++){
      int fo = ((kt*16 + warp*2 + nt)<<5) + lane;
      { uint4 bi=Wi[fo], bhq=Wh[fo];
#pragma unroll
        for (int mt=0;mt<2;mt++){
          mma3(cr[mt][nt], axh[mt], axl[mt], bi);
          mma3(cr[mt][nt], ahh[mt], ahl[mt], bhq);
        } }
      { uint4 bi=Wi[4096+fo], bhq=Wh[4096+fo];
#pragma unroll
        for (int mt=0;mt<2;mt++){
          mma3(cz[mt][nt], axh[mt], axl[mt], bi);
          mma3(cz[mt][nt], ahh[mt], ahl[mt], bhq);
        } }
      { uint4 bi=Wi[8192+fo], bhq=Wh[8192+fo];
#pragma unroll
        for (int mt=0;mt<2;mt++){
          mma3(cin[mt][nt], axh[mt], axl[mt], bi);
          mma3(chn[mt][nt], ahh[mt], ahl[mt], bhq);
        } }
    }
  }
#pragma unroll
  for (int mt=0;mt<2;mt++){
    long gb = b0 + mt*16 + (lane>>2);
#pragma unroll
    for (int nt=0;nt<2;nt++){
      int col = warp*16 + nt*8 + ((lane&3)<<1);
      float2 bir = *(const float2*)&bih[l*384 + col];
      float2 biz = *(const float2*)&bih[l*384 + 128 + col];
      float2 bin_= *(const float2*)&bih[l*384 + 256 + col];
      float2 bhr = *(const float2*)&bhh[l*384 + col];
      float2 bhz = *(const float2*)&bhh[l*384 + 128 + col];
      float2 bhn = *(const float2*)&bhh[l*384 + 256 + col];
      float2 hp0 = *(const float2*)&hist[((long)l*BQ + gb)*128 + col];
      float2 hp1 = *(const float2*)&hist[((long)l*BQ + gb + 8)*128 + col];
      float r0=sigmf(cr[mt][nt][0]+bir.x+bhr.x);
      float r1=sigmf(cr[mt][nt][1]+bir.y+bhr.y);
      float r2=sigmf(cr[mt][nt][2]+bir.x+bhr.x);
      float r3=sigmf(cr[mt][nt][3]+bir.y+bhr.y);
      float z0=sigmf(cz[mt][nt][0]+biz.x+bhz.x);
      float z1=sigmf(cz[mt][nt][1]+biz.y+bhz.y);
      float z2=sigmf(cz[mt][nt][2]+biz.x+bhz.x);
      float z3=sigmf(cz[mt][nt][3]+biz.y+bhz.y);
      float n0=tanhf(cin[mt][nt][0]+bin_.x + r0*(chn[mt][nt][0]+bhn.x));
      float n1=tanhf(cin[mt][nt][1]+bin_.y + r1*(chn[mt][nt][1]+bhn.y));
      float n2=tanhf(cin[mt][nt][2]+bin_.x + r2*(chn[mt][nt][2]+bhn.x));
      float n3=tanhf(cin[mt][nt][3]+bin_.y + r3*(chn[mt][nt][3]+bhn.y));
      *(float2*)&hout[gb*128 + col] =
          make_float2((1.f-z0)*n0 + z0*hp0.x, (1.f-z1)*n1 + z1*hp0.y);
      *(float2*)&hout[(gb+8)*128 + col] =
          make_float2((1.f-z2)*n2 + z2*hp1.x, (1.f-z3)*n3 + z3*hp1.y);
    }
  }
}

// ---- cm MLP fused (2 GEMMs) + causal solve in staging + l_z ---------------
__global__ __launch_bounds__(256,4) void k_cm(
    const float* __restrict__ b1, const float* __restrict__ b2,
    const float* __restrict__ ew, const float* __restrict__ cmw,
    const int* __restrict__ esrc, const int* __restrict__ edst){
  __shared__ __align__(16) __nv_bfloat16 sh[32*136], sl[32*136];
  __shared__ float s_cm[NND*NND];
  __shared__ int s_src[NE], s_dst[NE];
  int t = threadIdx.x, lane = t&31, warp = t>>5;
  int wrow = warp>>2, wcol = warp&3;
  long r0g = (long)blockIdx.x*32;
  if (t < NE){ s_src[t] = esrc[t]; s_dst[t] = edst[t]; }
  if (t < NND*NND) s_cm[t] = cmw[t];
  __syncthreads();
  // staging: forward-substitution causal solve + parent_sum on the fly
  for (int f=t; f<32*32; f+=256){
    int r = f>>5, c4 = (f&31)<<2;
    long R = r0g + r;
    int b = (int)(R/5), v = (int)(R - 5l*b);
    const float* mb = g_mean + (long)b*640;
    float4 z[NND];
#pragma unroll
    for (int j=0;j<NND;j++) z[j] = *(const float4*)&mb[j*128 + c4];
#pragma unroll
    for (int j=1;j<NND;j++){
      float4 add = make_float4(0.f,0.f,0.f,0.f);
#pragma unroll
      for (int e=0;e<NE;e++){
        if (s_dst[e] == j){
          int s = s_src[e];
          float w = __ldg(&ew[b*NE + e]) * s_cm[s*NND + j];
          float4 zs = (s==0)?z[0]:((s==1)?z[1]:((s==2)?z[2]:z[3]));
          add.x += w*zs.x; add.y += w*zs.y; add.z += w*zs.z; add.w += w*zs.w;
        }
      }
      z[j].x += add.x; z[j].y += add.y; z[j].z += add.z; z[j].w += add.w;
    }
    *(float4*)&g_z[R*128 + c4] = z[v];
    float4 ps = make_float4(0.f,0.f,0.f,0.f);
#pragma unroll
    for (int i=0;i<NND;i++){
      if (s_cm[i*NND + v] != 0.f){
        ps.x += z[i].x; ps.y += z[i].y; ps.z += z[i].z; ps.w += z[i].w;
      }
    }
    split_st(ps, sh, sl, r*136+c4);
  }
  __syncthreads();
  float c[4][4];
  hmma_row<8,4,16,136>(sh, sl, &g_Wf[WF_CM1], wcol*4, wrow*16, lane, c);
  __syncthreads();
  {
    int r0 = wrow*16 + (lane>>2);
#pragma unroll
    for (int nt=0;nt<4;nt++){
      int col = (wcol*4+nt)*8 + ((lane&3)<<1);
      float2 bb = *(const float2*)&b1[col];
      float v00=mishf(c[nt][0]+bb.x), v01=mishf(c[nt][1]+bb.y);
      float v10=mishf(c[nt][2]+bb.x), v11=mishf(c[nt][3]+bb.y);
      *(unsigned*)&sh[r0*136+col] = pkh(v00,v01);
      *(unsigned*)&sl[r0*136+col] = pkh(v00-bf16f(v00), v01-bf16f(v01));
      *(unsigned*)&sh[(r0+8)*136+col] = pkh(v10,v11);
      *(unsigned*)&sl[(r0+8)*136+col] = pkh(v10-bf16f(v10), v11-bf16f(v11));
    }
  }
  __syncthreads();
  hmma_row<8,4,16,136>(sh, sl, &g_Wf[WF_CM2], wcol*4, wrow*16, lane, c);
  float lz = 0.f;
  {
    long r0 = r0g + wrow*16 + (lane>>2);
#pragma unroll
    for (int nt=0;nt<4;nt++){
      int col = (wcol*4+nt)*8 + ((lane&3)<<1);
      float2 bb = *(const float2*)&b2[col];
      float2 z0 = *(const float2*)&g_z[r0*128 + col];
      float2 z1 = *(const float2*)&g_z[(r0+8)*128 + col];
      float d0 = z0.x - (c[nt][0]+bb.x);
      float d1 = z0.y - (c[nt][1]+bb.y);
      float d2 = z1.x - (c[nt][2]+bb.x);
      float d3 = z1.y - (c[nt][3]+bb.y);
      lz += d0*d0 + d1*d1 + d2*d2 + d3*d3;
    }
  }
  BLOCK_REDUCE8_TO(g_lzpart, lz);
}

// ----------------- decoder fused (2 GEMMs) + losses ------------------------
__global__ __launch_bounds__(256,4) void k_dec(
    const float* __restrict__ b1, const float* __restrict__ b2,
    const float* __restrict__ yt_g, float* __restrict__ out){
  __shared__ __align__(16) __nv_bfloat16 sh[32*136], sl[32*136];
  __shared__ float s_piw[8][32], s_kd[8][32], s_mn[8][32], s_mx[8][32];
  __shared__ float s_sc[3][8];
  float* s_out = (float*)sh;     // 32*66 floats = 8448B <= 8704B ✓
  int t = threadIdx.x, lane = t&31, warp = t>>5;
  int wrow = warp>>2, wcol = warp&3;
  int n = blockIdx.y;
  long b0 = (long)blockIdx.x*32;
  stage_split<32,128,136,256>(g_z + b0*640 + n*128, 640, sh, sl, t);
  __syncthreads();
  float c[4][4];
  hmma_row<8,4,16,136>(sh, sl, &g_Wf[WF_DEC1 + n*4096], wcol*4, wrow*16, lane, c);
  __syncthreads();
  {
    int r0 = wrow*16 + (lane>>2);
#pragma unroll
    for (int nt=0;nt<4;nt++){
      int col = (wcol*4+nt)*8 + ((lane&3)<<1);
      float2 bb = *(const float2*)&b1[n*128 + col];
      float v00=mishf(c[nt][0]+bb.x), v01=mishf(c[nt][1]+bb.y);
      float v10=mishf(c[nt][2]+bb.x), v11=mishf(c[nt][3]+bb.y);
      *(unsigned*)&sh[r0*136+col] = pkh(v00,v01);
      *(unsigned*)&sl[r0*136+col] = pkh(v00-bf16f(v00), v01-bf16f(v01));
      *(unsigned*)&sh[(r0+8)*136+col] = pkh(v10,v11);
      *(unsigned*)&sl[(r0+8)*136+col] = pkh(v10-bf16f(v10), v11-bf16f(v11));
    }
  }
  __syncthreads();
  float c2[2][4];
  hmma_row<8,2,8,136>(sh, sl, &g_Wf[WF_DEC2 + n*2048], wcol*2, wrow*16, lane, c2);
  __syncthreads();   // all reads of sh done before aliasing as s_out
  {
    int r = wrow*16 + (lane>>2);
#pragma unroll
    for (int nt=0;nt<2;nt++){
      int col = (wcol*2+nt)*8 + ((lane&3)<<1);
      float2 bb = *(const float2*)&b2[n*64 + col];
      float v00=c2[nt][0]+bb.x, v01=c2[nt][1]+bb.y;
      float v10=c2[nt][2]+bb.x, v11=c2[nt][3]+bb.y;
      if (col >= 32){ v00=expf(v00); v01=expf(v01); v10=expf(v10); v11=expf(v11); }
      s_out[r*66+col]=v00;     s_out[r*66+col+1]=v01;
      s_out[(r+8)*66+col]=v10; s_out[(r+8)*66+col+1]=v11;
      long gb0, gb1;
      if (col < 32){
        gb0 = (b0+r)*160 + n*32 + col;
        gb1 = (b0+r+8)*160 + n*32 + col;
      } else {
        gb0 = (long)OFF_V + (b0+r)*160 + n*32 + col-32;
        gb1 = (long)OFF_V + (b0+r+8)*160 + n*32 + col-32;
      }
      *(float2*)&out[gb0] = make_float2(v00,v01);
      *(float2*)&out[gb1] = make_float2(v10,v11);
    }
  }
  __syncthreads();
  int d = lane;
  float ll=0.f, sq4=0.f, bce=0.f;
  float piw=0.f, kd=0.f, mn=1e30f, mx=-1e30f;
#pragma unroll
  for (int i=0;i<4;i++){
    int row = warp + 8*i;
    float ym = s_out[row*66 + d];
    float yv = s_out[row*66 + 32 + d];
    float yt = yt_g[(b0+row)*160 + n*32 + d];
    float vs = yv + 1e-6f;
    float df = yt - ym;
    ll += -0.5f*(df*df/vs + logf(6.2831853071795864f*vs));
    if (n < 4) sq4 += df*df;
    if (n == 4) bce += fmaxf(ym,0.f) - ym*yt + log1pf(expf(-fabsf(ym)));
    float s  = sqrtf(vs);
    float lo_ = ym - ZALPHA*s, up_ = ym + ZALPHA*s;
    float kf = (yt >= lo_ && yt <= up_) ? 1.f : 0.f;
    kd  += kf;
    piw += (up_-lo_)*kf;
    mn = fminf(mn, yt);
    mx = fmaxf(mx, yt);
  }
  ll  = warp_sum(ll);
  sq4 = warp_sum(sq4);
  bce = warp_sum(bce);
  if (lane == 0){ s_sc[0][warp]=ll; s_sc[1][warp]=sq4; s_sc[2][warp]=bce; }
  s_piw[warp][d]=piw; s_kd[warp][d]=kd; s_mn[warp][d]=mn; s_mx[warp][d]=mx;
  __syncthreads();
  int blk = blockIdx.y*gridDim.x + blockIdx.x;
  float* P = g_losspart + blk*132;
  if (t == 0){
    P[0] = ((s_sc[0][0]+s_sc[0][1]) + (s_sc[0][2]+s_sc[0][3]))
         + ((s_sc[0][4]+s_sc[0][5]) + (s_sc[0][6]+s_sc[0][7]));
    P[1] = ((s_sc[1][0]+s_sc[1][1]) + (s_sc[1][2]+s_sc[1][3]))
         + ((s_sc[1][4]+s_sc[1][5]) + (s_sc[1][6]+s_sc[1][7]));
    P[2] = ((s_sc[2][0]+s_sc[2][1]) + (s_sc[2][2]+s_sc[2][3]))
         + ((s_sc[2][4]+s_sc[2][5]) + (s_sc[2][6]+s_sc[2][7]));
    P[3] = 0.f;
  }
  if (t < 32){
    float p=0.f, k=0.f, m=1e30f, xx=-1e30f;
#pragma unroll
    for (int g=0; g<8; g++){
      p += s_piw[g][t]; k += s_kd[g][t];
      m = fminf(m, s_mn[g][t]); xx = fmaxf(xx, s_mx[g][t]);
    }
    P[4+t] = p; P[36+t] = k; P[68+t] = m; P[100+t] = xx;
  }
}

// ---------------------- stage-1 reduce + final -----------------------------
__global__ void k_reduce1(){
  int col = blockIdx.x, t = threadIdx.x;
  bool ismin = (col >= 68 && col < 100);
  bool ismax = (col >= 100 && col < 132);
  float v = ismin ? 1e30f : (ismax ? -1e30f : 0.f);
  if (col < 132){
    for (int i=t; i<5120; i+=256){
      float x = g_losspart[i*132 + col];
      v = ismin ? fminf(v,x) : (ismax ? fmaxf(v,x) : v + x);
    }
  } else if (col == 132){
    for (int i=t; i<5120; i+=256) v += g_klpart[i];
  } else {
    for (int i=t; i<5120; i+=256) v += g_lzpart[i];
  }
  __shared__ float sm[256];
  sm[t] = v;
  __syncthreads();
  for (int s=128; s>0; s>>=1){
    if (t < s){
      float a = sm[t], b = sm[t+s];
      sm[t] = ismin ? fminf(a,b) : (ismax ? fmaxf(a,b) : a + b);
    }
    __syncthreads();
  }
  if (t == 0) g_facc[col] = sm[0];
}

__global__ void k_final(float* __restrict__ out){
  if (threadIdx.x != 0 || blockIdx.x != 0) return;
  float S_ll = g_facc[0], S_sq4 = g_facc[1], S_bce = g_facc[2];
  float kl = 0.5f*g_facc[132];
  float S_lz = g_facc[133];
  float mean_ll = S_ll / 5242880.0f;
  float elbo = kl/32768.0f - mean_ll;
  float l_reg = (S_sq4/32.0f) / (4.0f*32768.0f + 1e-6f);
  float l_cls = (S_bce/32.0f) / (32768.0f + 1e-6f);
  float l_rec = l_reg + l_cls;
  float Sk = 0.f, pin = 0.f;
  for (int d=0; d<32; d++){
    float kdv = g_facc[36+d];
    Sk += kdv;
    pin += g_facc[4+d] / (kdv + 1e-6f) / (g_facc[100+d] - g_facc[68+d] + 1e-6f);
  }
  float picp  = Sk / 5242880.0f;
  float pinaw = pin / 32.0f;
  float l_pi  = pinaw - sqrtf(5.0f)*picp;
  float l_z   = S_lz / 20971520.0f;
  float dag   = 0.0f;  // exact: diag((I+ac)^5)==1 for strictly-upper ac
  float total = powf(elbo*l_rec*l_pi*l_z*(dag + 1e-6f), 0.2f);
  out[OFF_LOSS+0] = total;
  out[OFF_LOSS+1] = elbo;
  out[OFF_LOSS+2] = l_rec;
  out[OFF_LOSS+3] = l_pi;
  out[OFF_LOSS+4] = l_z;
  out[OFF_LOSS+5] = dag;
}

// ------------------------------ launcher -----------------------------------
extern "C" void kernel_launch(void* const* d_in, const int* in_sizes, int n_in,
                              void* d_out, int out_size){
  const float* x       = (const float*)d_in[0];
  const float* y_true  = (const float*)d_in[1];
  const float* ew      = (const float*)d_in[2];
  const float* hist    = (const float*)d_in[3];
  const float* enc_W1  = (const float*)d_in[4];
  const float* enc_b1  = (const float*)d_in[5];
  const float* enc_W2  = (const float*)d_in[6];
  const float* enc_b2  = (const float*)d_in[7];
  const float* gcn_W   = (const float*)d_in[8];
  const float* gcn_b   = (const float*)d_in[9];
  const float* mu_W    = (const float*)d_in[10];
  const float* mu_b    = (const float*)d_in[11];
  const float* sig_W   = (const float*)d_in[12];
  const float* sig_b   = (const float*)d_in[13];
  const float* gru_Wih = (const float*)d_in[14];
  const float* gru_Whh = (const float*)d_in[15];
  const float* gru_bih = (const float*)d_in[16];
  const float* gru_bhh = (const float*)d_in[17];
  const float* cm      = (const float*)d_in[18];
  const float* cm_W1   = (const float*)d_in[19];
  const float* cm_b1   = (const float*)d_in[20];
  const float* cm_W2   = (const float*)d_in[21];
  const float* cm_b2   = (const float*)d_in[22];
  const float* dec_W1  = (const float*)d_in[23];
  const float* dec_b1  = (const float*)d_in[24];
  const float* dec_W2  = (const float*)d_in[25];
  const float* dec_b2  = (const float*)d_in[26];
  const int*   esrc    = (const int*)d_in[27];
  const int*   edst    = (const int*)d_in[28];
  float* out = (float*)d_out;

  k_packall<<<(WF_TOT+255)/256, 256>>>(enc_W1, enc_W2, gcn_W, mu_W, sig_W,
                                       cm_W1, cm_W2, dec_W1, dec_W2,
                                       gru_Wih, gru_Whh);
  k_enc<<<dim3(BQ/32, NND), 256>>>(x, enc_b1, enc_b2);
  k_gcn<<<5120, 256>>>(0, ew, esrc, edst, gcn_b);
  k_gcn<<<5120, 256>>>(1, ew, esrc, edst, gcn_b);
  k_musig<<<5120, 256>>>(mu_b, sig_b);
  k_gru<<<BQ/32, 256>>>(0, nullptr, hist, gru_bih, gru_bhh, out + OFF_HID);
  k_gru<<<BQ/32, 256>>>(1, out + OFF_HID, hist, gru_bih, gru_bhh,
                        out + OFF_HID + BQ*HDIM);
  k_cm<<<5120, 256>>>(cm_b1, cm_b2, ew, cm, esrc, edst);
  k_dec<<<dim3(BQ/32, NND), 256>>>(dec_b1, dec_b2, y_true, out);
  k_reduce1<<<134, 256>>>();
  k_final<<<1, 32>>>(out);
}

// round 11
// speedup vs baseline: 1.1415x; 1.1415x over previous
#include <cuda_runtime.h>
#include <cuda_bf16.h>
#include <math.h>

#define BQ   32768
#define NND  5
#define HDIM 128
#define NE   10

#define OFF_V    (BQ*NND*32)
#define OFF_HID  (2*BQ*NND*32)
#define OFF_LOSS (OFF_HID + 2*BQ*HDIM)

#define ZALPHA 1.959963984540054f

// fragment arena offsets (uint2 units)
#define WF_ENC1 0
#define WF_ENC2 10240
#define WF_GCN  51200
#define WF_MU   67584
#define WF_SIG  75776
#define WF_CM1  83968
#define WF_CM2  92160
#define WF_DEC1 100352
#define WF_DEC2 141312
#define WF_GI   161792
#define WF_GH   210944
#define WF_TOT  260096

// ----------------------------- device scratch -----------------------------
__device__ float g_bufA[BQ*NND*HDIM];
__device__ float g_bufB[BQ*NND*HDIM];
__device__ float g_mean[BQ*NND*HDIM];
__device__ float g_z  [BQ*NND*HDIM];
__device__ float g_ps [BQ*NND*HDIM];
__device__ uint2 g_Wf [WF_TOT];
__device__ float g_klpart[5120];
__device__ float g_lzpart[5120];
__device__ float g_losspart[5120*132];
__device__ float g_facc[134];

// ------------------------------- helpers ----------------------------------
__device__ __forceinline__ float warp_sum(float v){
#pragma unroll
  for (int o=16;o>0;o>>=1) v += __shfl_xor_sync(0xffffffffu, v, o);
  return v;
}
__device__ __forceinline__ float softplusf(float x){
  return fmaxf(x,0.f) + log1pf(expf(-fabsf(x)));
}
__device__ __forceinline__ float mishf(float x){ return x*tanhf(softplusf(x)); }
__device__ __forceinline__ float sigmf(float x){ return 1.f/(1.f+expf(-x)); }

#define BLOCK_REDUCE8_TO(part, val)                                     \
  do {                                                                  \
    float _v = warp_sum(val);                                           \
    __shared__ float _sred[8];                                          \
    if ((threadIdx.x & 31) == 0) _sred[threadIdx.x >> 5] = _v;          \
    __syncthreads();                                                    \
    if (threadIdx.x == 0)                                               \
      part[blockIdx.x] = ((_sred[0]+_sred[1]) + (_sred[2]+_sred[3]))    \
                       + ((_sred[4]+_sred[5]) + (_sred[6]+_sred[7]));   \
  } while (0)

__device__ __forceinline__ unsigned pkh(float x, float y){
  unsigned short a = __bfloat16_as_ushort(__float2bfloat16_rn(x));
  unsigned short b = __bfloat16_as_ushort(__float2bfloat16_rn(y));
  return ((unsigned)b<<16) | (unsigned)a;
}
__device__ __forceinline__ float bf16f(float x){
  return __bfloat162float(__float2bfloat16_rn(x));
}
__device__ __forceinline__ unsigned sptr(const void* p){
  return (unsigned)__cvta_generic_to_shared(p);
}
__device__ __forceinline__ void ldsm4(unsigned a, unsigned &r0, unsigned &r1,
                                      unsigned &r2, unsigned &r3){
  asm volatile("ldmatrix.sync.aligned.m8n8.x4.shared.b16 {%0,%1,%2,%3}, [%4];"
               : "=r"(r0),"=r"(r1),"=r"(r2),"=r"(r3) : "r"(a));
}
__device__ __forceinline__ void mma16816(float* c, const unsigned* a,
                                         unsigned b0, unsigned b1){
  asm volatile("mma.sync.aligned.m16n8k16.row.col.f32.bf16.bf16.f32 "
      "{%0,%1,%2,%3},{%4,%5,%6,%7},{%8,%9},{%0,%1,%2,%3};"
      : "+f"(c[0]),"+f"(c[1]),"+f"(c[2]),"+f"(c[3])
      : "r"(a[0]),"r"(a[1]),"r"(a[2]),"r"(a[3]),"r"(b0),"r"(b1));
}
__device__ __forceinline__ void mma3(float* c, const unsigned* ah,
    const unsigned* al, uint2 bh, uint2 bl){
  mma16816(c, ah, bh.x, bh.y);
  mma16816(c, al, bh.x, bh.y);
  mma16816(c, ah, bl.x, bl.y);
}

__device__ __forceinline__ void split_st(float4 v, __nv_bfloat16* sh,
    __nv_bfloat16* sl, int off){
  *(uint2*)&sh[off] = make_uint2(pkh(v.x,v.y), pkh(v.z,v.w));
  *(uint2*)&sl[off] = make_uint2(pkh(v.x-bf16f(v.x), v.y-bf16f(v.y)),
                                 pkh(v.z-bf16f(v.z), v.w-bf16f(v.w)));
}

template<int ROWS, int KC, int LDA, int NT_>
__device__ __forceinline__ void stage_split(const float* __restrict__ A, int arst,
    __nv_bfloat16* sh, __nv_bfloat16* sl, int t){
  const int C4 = KC/4;
  for (int f=t; f<ROWS*C4; f+=NT_){
    int r = f/C4, c4 = (f%C4)*4;
    float4 v = *(const float4*)&A[(long)r*arst + c4];
    split_st(v, sh, sl, r*LDA+c4);
  }
}

// 3-term bf16 split mainloop, 1 m16-tile per warp, NT n8-tiles
template<int KT, int NT, int NTOT, int LDA>
__device__ __forceinline__ void hmma_row(const __nv_bfloat16* sh,
    const __nv_bfloat16* sl, const uint2* __restrict__ Wf,
    int n8base, int rowbase, int lane, float (&c)[NT][4]){
#pragma unroll
  for (int nt=0;nt<NT;nt++)
#pragma unroll
    for (int i=0;i<4;i++) c[nt][i] = 0.f;
  int sub = lane>>3;
  int m_off = ((sub&1)<<3) + (lane&7);
  int k_off = (sub>>1)<<3;
#pragma unroll 1
  for (int kt=0; kt<KT; kt++){
    uint2 bh[NT], bl[NT];
#pragma unroll
    for (int nt=0;nt<NT;nt++){
      const uint2* wp = Wf + (((kt*NTOT + n8base + nt)*2)<<5) + lane;
      bh[nt] = wp[0];
      bl[nt] = wp[32];
    }
    unsigned ah[4], al[4];
    int ro = (rowbase + m_off)*LDA + kt*16 + k_off;
    ldsm4(sptr(&sh[ro]), ah[0],ah[1],ah[2],ah[3]);
    ldsm4(sptr(&sl[ro]), al[0],al[1],al[2],al[3]);
#pragma unroll
    for (int nt=0;nt<NT;nt++)
      mma3(c[nt], ah, al, bh[nt], bl[nt]);
  }
}

// --------------------------- single pack kernel ----------------------------
__global__ void k_packall(
    const float* __restrict__ encW1, const float* __restrict__ encW2,
    const float* __restrict__ gcnW,  const float* __restrict__ muW,
    const float* __restrict__ sigW,  const float* __restrict__ cmW1,
    const float* __restrict__ cmW2,  const float* __restrict__ decW1,
    const float* __restrict__ decW2, const float* __restrict__ giW,
    const float* __restrict__ ghW){
  int idx = blockIdx.x*256 + threadIdx.x;
  if (idx >= WF_TOT) return;
  const float* src; int K, N, trans, base, per, mst;
  if      (idx < WF_ENC2){ src=encW1; K=32; N=128; trans=0; base=WF_ENC1; per=2048; mst=4096; }
  else if (idx < WF_GCN ){ src=encW2; K=128;N=128; trans=0; base=WF_ENC2; per=8192; mst=16384;}
  else if (idx < WF_MU  ){ src=gcnW;  K=128;N=128; trans=0; base=WF_GCN;  per=8192; mst=16384;}
  else if (idx < WF_SIG ){ src=muW;   K=128;N=128; trans=0; base=WF_MU;   per=8192; mst=16384;}
  else if (idx < WF_CM1 ){ src=sigW;  K=128;N=128; trans=0; base=WF_SIG;  per=8192; mst=16384;}
  else if (idx < WF_CM2 ){ src=cmW1;  K=128;N=128; trans=0; base=WF_CM1;  per=8192; mst=16384;}
  else if (idx < WF_DEC1){ src=cmW2;  K=128;N=128; trans=0; base=WF_CM2;  per=8192; mst=16384;}
  else if (idx < WF_DEC2){ src=decW1; K=128;N=128; trans=0; base=WF_DEC1; per=8192; mst=16384;}
  else if (idx < WF_GI  ){ src=decW2; K=128;N=64;  trans=0; base=WF_DEC2; per=4096; mst=8192; }
  else if (idx < WF_GH  ){ src=giW;   K=128;N=128; trans=1; base=WF_GI;   per=8192; mst=16384;}
  else                   { src=ghW;   K=128;N=128; trans=1; base=WF_GH;   per=8192; mst=16384;}
  int rr = idx - base;
  int m = rr / per, r = rr % per;
  int lane = r & 31, term = (r>>5)&1;
  int n8 = (r>>6) % (N>>3);
  int kt = (r>>6) / (N>>3);
  int n = n8*8 + (lane>>2);
  int k0 = kt*16 + ((lane&3)<<1);
  const float* S = src + (long)m*mst;
  float w0,w1,w2,w3;
  if (trans){
    w0=S[n*K+k0]; w1=S[n*K+k0+1]; w2=S[n*K+k0+8]; w3=S[n*K+k0+9];
  } else {
    w0=S[k0*N+n]; w1=S[(k0+1)*N+n]; w2=S[(k0+8)*N+n]; w3=S[(k0+9)*N+n];
  }
  uint2 o;
  if (term==0){ o = make_uint2(pkh(w0,w1), pkh(w2,w3)); }
  else {
    o = make_uint2(pkh(w0-bf16f(w0), w1-bf16f(w1)),
                   pkh(w2-bf16f(w2), w3-bf16f(w3)));
  }
  g_Wf[idx] = o;
}

// ------------------------------ encoder ------------------------------------
__global__ __launch_bounds__(256,4) void k_enc(
    const float* __restrict__ x, const float* __restrict__ b1,
    const float* __restrict__ b2){
  __shared__ __align__(16) __nv_bfloat16 xh[32*40], xl[32*40];
  __shared__ __align__(16) __nv_bfloat16 hh[32*136], hl[32*136];
  int t = threadIdx.x, lane = t&31, warp = t>>5;
  int wrow = warp>>2, wcol = warp&3;
  int n = blockIdx.y;
  long b0 = (long)blockIdx.x*32;
  stage_split<32,32,40,256>(x + b0*160 + n*32, 160, xh, xl, t);
  __syncthreads();
  float c[4][4];
  hmma_row<2,4,16,40>(xh, xl, &g_Wf[WF_ENC1 + n*2048], wcol*4, wrow*16, lane, c);
  __syncthreads();
  {
    int r0 = wrow*16 + (lane>>2);
#pragma unroll
    for (int nt=0;nt<4;nt++){
      int col = (wcol*4+nt)*8 + ((lane&3)<<1);
      float2 bb = *(const float2*)&b1[n*128 + col];
      float v00=fmaxf(c[nt][0]+bb.x,0.f), v01=fmaxf(c[nt][1]+bb.y,0.f);
      float v10=fmaxf(c[nt][2]+bb.x,0.f), v11=fmaxf(c[nt][3]+bb.y,0.f);
      *(unsigned*)&hh[r0*136+col] = pkh(v00,v01);
      *(unsigned*)&hl[r0*136+col] = pkh(v00-bf16f(v00), v01-bf16f(v01));
      *(unsigned*)&hh[(r0+8)*136+col] = pkh(v10,v11);
      *(unsigned*)&hl[(r0+8)*136+col] = pkh(v10-bf16f(v10), v11-bf16f(v11));
    }
  }
  __syncthreads();
  hmma_row<8,4,16,136>(hh, hl, &g_Wf[WF_ENC2 + n*8192], wcol*4, wrow*16, lane, c);
  {
    long r0 = b0 + wrow*16 + (lane>>2);
#pragma unroll
    for (int nt=0;nt<4;nt++){
      int col = (wcol*4+nt)*8 + ((lane&3)<<1);
      float2 bb = *(const float2*)&b2[n*128 + col];
      *(float2*)&g_bufA[r0*640 + n*128 + col] =
          make_float2(c[nt][0]+bb.x, c[nt][1]+bb.y);
      *(float2*)&g_bufA[(r0+8)*640 + n*128 + col] =
          make_float2(c[nt][2]+bb.x, c[nt][3]+bb.y);
    }
  }
}

// ------------------- GCN: fused aggregation + GEMM -------------------------
__global__ __launch_bounds__(256,4) void k_gcn(
    int l, const float* __restrict__ ew,
    const int* __restrict__ esrc, const int* __restrict__ edst,
    const float* __restrict__ bias){
  __shared__ __align__(16) __nv_bfloat16 sh[32*136], sl[32*136];
  __shared__ int s_src[NE], s_dst[NE];
  int t = threadIdx.x, lane = t&31, warp = t>>5;
  int wrow = warp>>2, wcol = warp&3;
  const float* gin  = (l==0) ? g_bufA : g_bufB;
  float*       gout = (l==0) ? g_bufB : g_bufA;
  long b0 = (long)blockIdx.x*32;
  if (t < NE){ s_src[t] = esrc[t]; s_dst[t] = edst[t]; }
  __syncthreads();
  for (int f=t; f<32*32; f+=256){
    int r = f>>5, c4 = (f&31)<<2;
    long R = b0 + r;
    int b = (int)(R/5), v = (int)(R - 5l*b);
    const float* row = gin + (long)b*640;
    float4 a = *(const float4*)&row[v*128 + c4];
#pragma unroll
    for (int e=0;e<NE;e++){
      if (s_dst[e] == v){
        float w = __ldg(&ew[b*NE + e]);
        float4 g = *(const float4*)&row[s_src[e]*128 + c4];
        a.x += w*g.x; a.y += w*g.y; a.z += w*g.z; a.w += w*g.w;
      }
    }
    split_st(a, sh, sl, r*136+c4);
  }
  __syncthreads();
  float c[4][4];
  hmma_row<8,4,16,136>(sh, sl, &g_Wf[WF_GCN + l*8192], wcol*4, wrow*16, lane, c);
  {
    long r0 = b0 + wrow*16 + (lane>>2);
#pragma unroll
    for (int nt=0;nt<4;nt++){
      int col = (wcol*4+nt)*8 + ((lane&3)<<1);
      float2 bb = *(const float2*)&bias[l*128 + col];
      *(float2*)&gout[r0*128 + col] = make_float2(
          fmaxf(c[nt][0]+bb.x,0.f), fmaxf(c[nt][1]+bb.y,0.f));
      *(float2*)&gout[(r0+8)*128 + col] = make_float2(
          fmaxf(c[nt][2]+bb.x,0.f), fmaxf(c[nt][3]+bb.y,0.f));
    }
  }
}

// ----------------------- mu/sig heads + KL ---------------------------------
__global__ __launch_bounds__(256,4) void k_musig(
    const float* __restrict__ mub, const float* __restrict__ sigb){
  __shared__ __align__(16) __nv_bfloat16 sh[32*136], sl[32*136];
  int t = threadIdx.x, lane = t&31, warp = t>>5;
  int wrow = warp>>2, wcol = warp&3;
  long b0 = (long)blockIdx.x*32;
  stage_split<32,128,136,256>(g_bufA + b0*128, 128, sh, sl, t);
  __syncthreads();
  float c[4][4];
  float kll = 0.f;
  hmma_row<8,4,16,136>(sh, sl, &g_Wf[WF_MU], wcol*4, wrow*16, lane, c);
  {
    long r0 = b0 + wrow*16 + (lane>>2);
#pragma unroll
    for (int nt=0;nt<4;nt++){
      int col = (wcol*4+nt)*8 + ((lane&3)<<1);
      float2 bb = *(const float2*)&mub[col];
      float m00=c[nt][0]+bb.x, m01=c[nt][1]+bb.y;
      float m10=c[nt][2]+bb.x, m11=c[nt][3]+bb.y;
      *(float2*)&g_mean[r0*128 + col]     = make_float2(m00,m01);
      *(float2*)&g_mean[(r0+8)*128 + col] = make_float2(m10,m11);
      kll += m00*m00 + m01*m01 + m10*m10 + m11*m11;
    }
  }
  hmma_row<8,4,16,136>(sh, sl, &g_Wf[WF_SIG], wcol*4, wrow*16, lane, c);
#pragma unroll
  for (int nt=0;nt<4;nt++){
    int col = (wcol*4+nt)*8 + ((lane&3)<<1);
    float2 bb = *(const float2*)&sigb[col];
#pragma unroll
    for (int i=0;i<4;i++){
      float sp = softplusf(c[nt][i] + ((i&1)?bb.y:bb.x));
      float var = sp*sp;
      kll += var - logf(var + 1e-8f) - 1.f;
    }
  }
  BLOCK_REDUCE8_TO(g_klpart, kll);
}

// ------------- GRU: fused dual-GEMM + gates (one kernel per layer) ---------
__global__ __launch_bounds__(256) void k_gru(
    int l, const float* __restrict__ xin, const float* __restrict__ hist,
    const float* __restrict__ bih, const float* __restrict__ bhh,
    float* __restrict__ hout){
  __shared__ __align__(16) __nv_bfloat16 xh[32*136], xl[32*136];
  __shared__ __align__(16) __nv_bfloat16 hhs[32*136], hls[32*136];
  int t = threadIdx.x, lane = t&31, warp = t>>5;   // 8 warps
  long b0 = (long)blockIdx.x*32;
  for (int f=t; f<32*32; f+=256){
    int r = f>>5, c4 = (f&31)<<2;
    long b = b0 + r;
    float4 v;
    if (xin){
      v = *(const float4*)&xin[b*128 + c4];
    } else {
      v = *(const float4*)&g_mean[b*640 + c4];
#pragma unroll
      for (int vv=1; vv<5; vv++){
        float4 m = *(const float4*)&g_mean[b*640 + vv*128 + c4];
        v.x+=m.x; v.y+=m.y; v.z+=m.z; v.w+=m.w;
      }
      v.x*=0.2f; v.y*=0.2f; v.z*=0.2f; v.w*=0.2f;
    }
    split_st(v, xh, xl, r*136+c4);
    float4 hv = *(const float4*)&hist[((long)l*BQ + b)*128 + c4];
    split_st(hv, hhs, hls, r*136+c4);
  }
  __syncthreads();
  float cr[2][2][4], cz[2][2][4], cin[2][2][4], chn[2][2][4];
#pragma unroll
  for (int mt=0;mt<2;mt++)
#pragma unroll
    for (int nt=0;nt<2;nt++)
#pragma unroll
      for (int i=0;i<4;i++){ cr[mt][nt][i]=0.f; cz[mt][nt][i]=0.f;
                             cin[mt][nt][i]=0.f; chn[mt][nt][i]=0.f; }
  int sub = lane>>3;
  int m_off = ((sub&1)<<3) + (lane&7);
  int k_off = (sub>>1)<<3;
  const uint2* Wi = &g_Wf[WF_GI + l*3*8192];
  const uint2* Wh = &g_Wf[WF_GH + l*3*8192];
#pragma unroll 1
  for (int kt=0; kt<8; kt++){
    unsigned axh[2][4], axl[2][4], ahh[2][4], ahl[2][4];
#pragma unroll
    for (int mt=0;mt<2;mt++){
      int ro = (mt*16 + m_off)*136 + kt*16 + k_off;
      ldsm4(sptr(&xh[ro]),  axh[mt][0],axh[mt][1],axh[mt][2],axh[mt][3]);
      ldsm4(sptr(&xl[ro]),  axl[mt][0],axl[mt][1],axl[mt][2],axl[mt][3]);
      ldsm4(sptr(&hhs[ro]), ahh[mt][0],ahh[mt][1],ahh[mt][2],ahh[mt][3]);
      ldsm4(sptr(&hls[ro]), ahl[mt][0],ahl[mt][1],ahl[mt][2],ahl[mt][3]);
    }
#pragma unroll
    for (int nt=0;nt<2;nt++){
      int fo = (((kt*16 + warp*2 + nt)*2)<<5) + lane;
      { uint2 bh=Wi[fo], bl=Wi[fo+32];
        uint2 ch=Wh[fo], cl=Wh[fo+32];
#pragma unroll
        for (int mt=0;mt<2;mt++){
          mma3(cr[mt][nt], axh[mt], axl[mt], bh, bl);
          mma3(cr[mt][nt], ahh[mt], ahl[mt], ch, cl);
        } }
      { uint2 bh=Wi[8192+fo], bl=Wi[8192+fo+32];
        uint2 ch=Wh[8192+fo], cl=Wh[8192+fo+32];
#pragma unroll
        for (int mt=0;mt<2;mt++){
          mma3(cz[mt][nt], axh[mt], axl[mt], bh, bl);
          mma3(cz[mt][nt], ahh[mt], ahl[mt], ch, cl);
        } }
      { uint2 bh=Wi[16384+fo], bl=Wi[16384+fo+32];
        uint2 ch=Wh[16384+fo], cl=Wh[16384+fo+32];
#pragma unroll
        for (int mt=0;mt<2;mt++){
          mma3(cin[mt][nt], axh[mt], axl[mt], bh, bl);
          mma3(chn[mt][nt], ahh[mt], ahl[mt], ch, cl);
        } }
    }
  }
#pragma unroll
  for (int mt=0;mt<2;mt++){
    long gb = b0 + mt*16 + (lane>>2);
#pragma unroll
    for (int nt=0;nt<2;nt++){
      int col = warp*16 + nt*8 + ((lane&3)<<1);
      float2 bir = *(const float2*)&bih[l*384 + col];
      float2 biz = *(const float2*)&bih[l*384 + 128 + col];
      float2 bin_= *(const float2*)&bih[l*384 + 256 + col];
      float2 bhr = *(const float2*)&bhh[l*384 + col];
      float2 bhz = *(const float2*)&bhh[l*384 + 128 + col];
      float2 bhn = *(const float2*)&bhh[l*384 + 256 + col];
      float2 hp0 = *(const float2*)&hist[((long)l*BQ + gb)*128 + col];
      float2 hp1 = *(const float2*)&hist[((long)l*BQ + gb + 8)*128 + col];
      float r0=sigmf(cr[mt][nt][0]+bir.x+bhr.x);
      float r1=sigmf(cr[mt][nt][1]+bir.y+bhr.y);
      float r2=sigmf(cr[mt][nt][2]+bir.x+bhr.x);
      float r3=sigmf(cr[mt][nt][3]+bir.y+bhr.y);
      float z0=sigmf(cz[mt][nt][0]+biz.x+bhz.x);
      float z1=sigmf(cz[mt][nt][1]+biz.y+bhz.y);
      float z2=sigmf(cz[mt][nt][2]+biz.x+bhz.x);
      float z3=sigmf(cz[mt][nt][3]+biz.y+bhz.y);
      float n0=tanhf(cin[mt][nt][0]+bin_.x + r0*(chn[mt][nt][0]+bhn.x));
      float n1=tanhf(cin[mt][nt][1]+bin_.y + r1*(chn[mt][nt][1]+bhn.y));
      float n2=tanhf(cin[mt][nt][2]+bin_.x + r2*(chn[mt][nt][2]+bhn.x));
      float n3=tanhf(cin[mt][nt][3]+bin_.y + r3*(chn[mt][nt][3]+bhn.y));
      *(float2*)&hout[gb*128 + col] =
          make_float2((1.f-z0)*n0 + z0*hp0.x, (1.f-z1)*n1 + z1*hp0.y);
      *(float2*)&hout[(gb+8)*128 + col] =
          make_float2((1.f-z2)*n2 + z2*hp1.x, (1.f-z3)*n3 + z3*hp1.y);
    }
  }
}

// --------------------- causal solve + parent_sum ---------------------------
__global__ __launch_bounds__(128) void k_causal(
    const float* __restrict__ ew, const float* __restrict__ cm,
    const int* __restrict__ esrc, const int* __restrict__ edst){
  int b = blockIdx.x, t = threadIdx.x;
  __shared__ float s_ew[NE], s_cm[NND*NND];
  __shared__ int s_src[NE], s_dst[NE];
  if (t < NE){ s_ew[t] = ew[b*NE + t]; s_src[t] = esrc[t]; s_dst[t] = edst[t]; }
  if (t < NND*NND) s_cm[t] = cm[t];
  __syncthreads();
  int base = b*NND*HDIM + t;
  float z[NND];
#pragma unroll
  for (int j=0;j<NND;j++) z[j] = g_mean[base + j*HDIM];
#pragma unroll
  for (int j=1;j<NND;j++){
    float add = 0.f;
#pragma unroll
    for (int e=0;e<NE;e++){
      if (s_dst[e] == j){
        int s = s_src[e];
        float zs = (s==0)?z[0]:((s==1)?z[1]:((s==2)?z[2]:z[3]));
        add += s_ew[e]*s_cm[s*NND + j]*zs;
      }
    }
    z[j] += add;
  }
#pragma unroll
  for (int j=0;j<NND;j++) g_z[base + j*HDIM] = z[j];
#pragma unroll
  for (int j=0;j<NND;j++){
    float ps = 0.f;
#pragma unroll
    for (int i=0;i<NND;i++)
      if (s_cm[i*NND + j] != 0.f) ps += z[i];
    g_ps[base + j*HDIM] = ps;
  }
}

// ------------------- cm MLP fused (2 GEMMs) + l_z --------------------------
__global__ __launch_bounds__(256,4) void k_cm(
    const float* __restrict__ b1, const float* __restrict__ b2){
  __shared__ __align__(16) __nv_bfloat16 sh[32*136], sl[32*136];
  int t = threadIdx.x, lane = t&31, warp = t>>5;
  int wrow = warp>>2, wcol = warp&3;
  long b0 = (long)blockIdx.x*32;
  stage_split<32,128,136,256>(g_ps + b0*128, 128, sh, sl, t);
  __syncthreads();
  float c[4][4];
  hmma_row<8,4,16,136>(sh, sl, &g_Wf[WF_CM1], wcol*4, wrow*16, lane, c);
  __syncthreads();
  {
    int r0 = wrow*16 + (lane>>2);
#pragma unroll
    for (int nt=0;nt<4;nt++){
      int col = (wcol*4+nt)*8 + ((lane&3)<<1);
      float2 bb = *(const float2*)&b1[col];
      float v00=mishf(c[nt][0]+bb.x), v01=mishf(c[nt][1]+bb.y);
      float v10=mishf(c[nt][2]+bb.x), v11=mishf(c[nt][3]+bb.y);
      *(unsigned*)&sh[r0*136+col] = pkh(v00,v01);
      *(unsigned*)&sl[r0*136+col] = pkh(v00-bf16f(v00), v01-bf16f(v01));
      *(unsigned*)&sh[(r0+8)*136+col] = pkh(v10,v11);
      *(unsigned*)&sl[(r0+8)*136+col] = pkh(v10-bf16f(v10), v11-bf16f(v11));
    }
  }
  __syncthreads();
  hmma_row<8,4,16,136>(sh, sl, &g_Wf[WF_CM2], wcol*4, wrow*16, lane, c);
  float lz = 0.f;
  {
    long r0 = b0 + wrow*16 + (lane>>2);
#pragma unroll
    for (int nt=0;nt<4;nt++){
      int col = (wcol*4+nt)*8 + ((lane&3)<<1);
      float2 bb = *(const float2*)&b2[col];
      float2 z0 = *(const float2*)&g_z[r0*128 + col];
      float2 z1 = *(const float2*)&g_z[(r0+8)*128 + col];
      float d0 = z0.x - (c[nt][0]+bb.x);
      float d1 = z0.y - (c[nt][1]+bb.y);
      float d2 = z1.x - (c[nt][2]+bb.x);
      float d3 = z1.y - (c[nt][3]+bb.y);
      lz += d0*d0 + d1*d1 + d2*d2 + d3*d3;
    }
  }
  BLOCK_REDUCE8_TO(g_lzpart, lz);
}

// ----------------- decoder fused (2 GEMMs) + losses ------------------------
__global__ __launch_bounds__(256,4) void k_dec(
    const float* __restrict__ b1, const float* __restrict__ b2,
    const float* __restrict__ yt_g, float* __restrict__ out){
  __shared__ __align__(16) __nv_bfloat16 sh[32*136], sl[32*136];
  __shared__ float s_piw[8][32], s_kd[8][32], s_mn[8][32], s_mx[8][32];
  __shared__ float s_sc[3][8];
  float* s_out = (float*)sh;     // 32*66 floats = 8448B <= 8704B ✓
  int t = threadIdx.x, lane = t&31, warp = t>>5;
  int wrow = warp>>2, wcol = warp&3;
  int n = blockIdx.y;
  long b0 = (long)blockIdx.x*32;
  stage_split<32,128,136,256>(g_z + b0*640 + n*128, 640, sh, sl, t);
  __syncthreads();
  float c[4][4];
  hmma_row<8,4,16,136>(sh, sl, &g_Wf[WF_DEC1 + n*8192], wcol*4, wrow*16, lane, c);
  __syncthreads();
  {
    int r0 = wrow*16 + (lane>>2);
#pragma unroll
    for (int nt=0;nt<4;nt++){
      int col = (wcol*4+nt)*8 + ((lane&3)<<1);
      float2 bb = *(const float2*)&b1[n*128 + col];
      float v00=mishf(c[nt][0]+bb.x), v01=mishf(c[nt][1]+bb.y);
      float v10=mishf(c[nt][2]+bb.x), v11=mishf(c[nt][3]+bb.y);
      *(unsigned*)&sh[r0*136+col] = pkh(v00,v01);
      *(unsigned*)&sl[r0*136+col] = pkh(v00-bf16f(v00), v01-bf16f(v01));
      *(unsigned*)&sh[(r0+8)*136+col] = pkh(v10,v11);
      *(unsigned*)&sl[(r0+8)*136+col] = pkh(v10-bf16f(v10), v11-bf16f(v11));
    }
  }
  __syncthreads();
  float c2[2][4];
  hmma_row<8,2,8,136>(sh, sl, &g_Wf[WF_DEC2 + n*4096], wcol*2, wrow*16, lane, c2);
  __syncthreads();   // all reads of sh done before aliasing as s_out
  {
    int r = wrow*16 + (lane>>2);
#pragma unroll
    for (int nt=0;nt<2;nt++){
      int col = (wcol*2+nt)*8 + ((lane&3)<<1);
      float2 bb = *(const float2*)&b2[n*64 + col];
      float v00=c2[nt][0]+bb.x, v01=c2[nt][1]+bb.y;
      float v10=c2[nt][2]+bb.x, v11=c2[nt][3]+bb.y;
      if (col >= 32){ v00=expf(v00); v01=expf(v01); v10=expf(v10); v11=expf(v11); }
      s_out[r*66+col]=v00;     s_out[r*66+col+1]=v01;
      s_out[(r+8)*66+col]=v10; s_out[(r+8)*66+col+1]=v11;
      long gb0, gb1;
      if (col < 32){
        gb0 = (b0+r)*160 + n*32 + col;
        gb1 = (b0+r+8)*160 + n*32 + col;
      } else {
        gb0 = (long)OFF_V + (b0+r)*160 + n*32 + col-32;
        gb1 = (long)OFF_V + (b0+r+8)*160 + n*32 + col-32;
      }
      *(float2*)&out[gb0] = make_float2(v00,v01);
      *(float2*)&out[gb1] = make_float2(v10,v11);
    }
  }
  __syncthreads();
  int d = lane;
  float ll=0.f, sq4=0.f, bce=0.f;
  float piw=0.f, kd=0.f, mn=1e30f, mx=-1e30f;
#pragma unroll
  for (int i=0;i<4;i++){
    int row = warp + 8*i;
    float ym = s_out[row*66 + d];
    float yv = s_out[row*66 + 32 + d];
    float yt = yt_g[(b0+row)*160 + n*32 + d];
    float vs = yv + 1e-6f;
    float df = yt - ym;
    ll += -0.5f*(df*df/vs + logf(6.2831853071795864f*vs));
    if (n < 4) sq4 += df*df;
    if (n == 4) bce += fmaxf(ym,0.f) - ym*yt + log1pf(expf(-fabsf(ym)));
    float s  = sqrtf(vs);
    float lo_ = ym - ZALPHA*s, up_ = ym + ZALPHA*s;
    float kf = (yt >= lo_ && yt <= up_) ? 1.f : 0.f;
    kd  += kf;
    piw += (up_-lo_)*kf;
    mn = fminf(mn, yt);
    mx = fmaxf(mx, yt);
  }
  ll  = warp_sum(ll);
  sq4 = warp_sum(sq4);
  bce = warp_sum(bce);
  if (lane == 0){ s_sc[0][warp]=ll; s_sc[1][warp]=sq4; s_sc[2][warp]=bce; }
  s_piw[warp][d]=piw; s_kd[warp][d]=kd; s_mn[warp][d]=mn; s_mx[warp][d]=mx;
  __syncthreads();
  int blk = blockIdx.y*gridDim.x + blockIdx.x;
  float* P = g_losspart + blk*132;
  if (t == 0){
    P[0] = ((s_sc[0][0]+s_sc[0][1]) + (s_sc[0][2]+s_sc[0][3]))
         + ((s_sc[0][4]+s_sc[0][5]) + (s_sc[0][6]+s_sc[0][7]));
    P[1] = ((s_sc[1][0]+s_sc[1][1]) + (s_sc[1][2]+s_sc[1][3]))
         + ((s_sc[1][4]+s_sc[1][5]) + (s_sc[1][6]+s_sc[1][7]));
    P[2] = ((s_sc[2][0]+s_sc[2][1]) + (s_sc[2][2]+s_sc[2][3]))
         + ((s_sc[2][4]+s_sc[2][5]) + (s_sc[2][6]+s_sc[2][7]));
    P[3] = 0.f;
  }
  if (t < 32){
    float p=0.f, k=0.f, m=1e30f, xx=-1e30f;
#pragma unroll
    for (int g=0; g<8; g++){
      p += s_piw[g][t]; k += s_kd[g][t];
      m = fminf(m, s_mn[g][t]); xx = fmaxf(xx, s_mx[g][t]);
    }
    P[4+t] = p; P[36+t] = k; P[68+t] = m; P[100+t] = xx;
  }
}

// ---------------------- stage-1 reduce + final -----------------------------
__global__ void k_reduce1(){
  int col = blockIdx.x, t = threadIdx.x;
  bool ismin = (col >= 68 && col < 100);
  bool ismax = (col >= 100 && col < 132);
  float v = ismin ? 1e30f : (ismax ? -1e30f : 0.f);
  if (col < 132){
    for (int i=t; i<5120; i+=256){
      float x = g_losspart[i*132 + col];
      v = ismin ? fminf(v,x) : (ismax ? fmaxf(v,x) : v + x);
    }
  } else if (col == 132){
    for (int i=t; i<5120; i+=256) v += g_klpart[i];
  } else {
    for (int i=t; i<5120; i+=256) v += g_lzpart[i];
  }
  __shared__ float sm[256];
  sm[t] = v;
  __syncthreads();
  for (int s=128; s>0; s>>=1){
    if (t < s){
      float a = sm[t], b = sm[t+s];
      sm[t] = ismin ? fminf(a,b) : (ismax ? fmaxf(a,b) : a + b);
    }
    __syncthreads();
  }
  if (t == 0) g_facc[col] = sm[0];
}

__global__ void k_final(float* __restrict__ out){
  if (threadIdx.x != 0 || blockIdx.x != 0) return;
  float S_ll = g_facc[0], S_sq4 = g_facc[1], S_bce = g_facc[2];
  float kl = 0.5f*g_facc[132];
  float S_lz = g_facc[133];
  float mean_ll = S_ll / 5242880.0f;
  float elbo = kl/32768.0f - mean_ll;
  float l_reg = (S_sq4/32.0f) / (4.0f*32768.0f + 1e-6f);
  float l_cls = (S_bce/32.0f) / (32768.0f + 1e-6f);
  float l_rec = l_reg + l_cls;
  float Sk = 0.f, pin = 0.f;
  for (int d=0; d<32; d++){
    float kdv = g_facc[36+d];
    Sk += kdv;
    pin += g_facc[4+d] / (kdv + 1e-6f) / (g_facc[100+d] - g_facc[68+d] + 1e-6f);
  }
  float picp  = Sk / 5242880.0f;
  float pinaw = pin / 32.0f;
  float l_pi  = pinaw - sqrtf(5.0f)*picp;
  float l_z   = S_lz / 20971520.0f;
  float dag   = 0.0f;  // exact: diag((I+ac)^5)==1 for strictly-upper ac
  float total = powf(elbo*l_rec*l_pi*l_z*(dag + 1e-6f), 0.2f);
  out[OFF_LOSS+0] = total;
  out[OFF_LOSS+1] = elbo;
  out[OFF_LOSS+2] = l_rec;
  out[OFF_LOSS+3] = l_pi;
  out[OFF_LOSS+4] = l_z;
  out[OFF_LOSS+5] = dag;
}

// ------------------------------ launcher -----------------------------------
extern "C" void kernel_launch(void* const* d_in, const int* in_sizes, int n_in,
                              void* d_out, int out_size){
  const float* x       = (const float*)d_in[0];
  const float* y_true  = (const float*)d_in[1];
  const float* ew      = (const float*)d_in[2];
  const float* hist    = (const float*)d_in[3];
  const float* enc_W1  = (const float*)d_in[4];
  const float* enc_b1  = (const float*)d_in[5];
  const float* enc_W2  = (const float*)d_in[6];
  const float* enc_b2  = (const float*)d_in[7];
  const float* gcn_W   = (const float*)d_in[8];
  const float* gcn_b   = (const float*)d_in[9];
  const float* mu_W    = (const float*)d_in[10];
  const float* mu_b    = (const float*)d_in[11];
  const float* sig_W   = (const float*)d_in[12];
  const float* sig_b   = (const float*)d_in[13];
  const float* gru_Wih = (const float*)d_in[14];
  const float* gru_Whh = (const float*)d_in[15];
  const float* gru_bih = (const float*)d_in[16];
  const float* gru_bhh = (const float*)d_in[17];
  const float* cm      = (const float*)d_in[18];
  const float* cm_W1   = (const float*)d_in[19];
  const float* cm_b1   = (const float*)d_in[20];
  const float* cm_W2   = (const float*)d_in[21];
  const float* cm_b2   = (const float*)d_in[22];
  const float* dec_W1  = (const float*)d_in[23];
  const float* dec_b1  = (const float*)d_in[24];
  const float* dec_W2  = (const float*)d_in[25];
  const float* dec_b2  = (const float*)d_in[26];
  const int*   esrc    = (const int*)d_in[27];
  const int*   edst    = (const int*)d_in[28];
  float* out = (float*)d_out;

  // secondary stream + fork/join events (created once, outside capture; the
  // captured op sequence is identical on every call)
  static cudaStream_t s2 = 0;
  static cudaEvent_t evFork = 0, evJoin = 0;
  if (!s2){
    cudaStreamCreateWithFlags(&s2, cudaStreamNonBlocking);
    cudaEventCreateWithFlags(&evFork, cudaEventDisableTiming);
    cudaEventCreateWithFlags(&evJoin, cudaEventDisableTiming);
  }

  k_packall<<<(WF_TOT+255)/256, 256>>>(enc_W1, enc_W2, gcn_W, mu_W, sig_W,
                                       cm_W1, cm_W2, dec_W1, dec_W2,
                                       gru_Wih, gru_Whh);
  k_enc<<<dim3(BQ/32, NND), 256>>>(x, enc_b1, enc_b2);
  k_gcn<<<5120, 256>>>(0, ew, esrc, edst, gcn_b);
  k_gcn<<<5120, 256>>>(1, ew, esrc, edst, gcn_b);
  k_musig<<<5120, 256>>>(mu_b, sig_b);

  // fork: GRU chain on s2, causal/cm/dec on the default stream
  cudaEventRecord(evFork, 0);
  cudaStreamWaitEvent(s2, evFork, 0);
  k_gru<<<BQ/32, 256, 0, s2>>>(0, nullptr, hist, gru_bih, gru_bhh,
                               out + OFF_HID);
  k_gru<<<BQ/32, 256, 0, s2>>>(1, out + OFF_HID, hist, gru_bih, gru_bhh,
                               out + OFF_HID + BQ*HDIM);
  cudaEventRecord(evJoin, s2);

  k_causal<<<BQ, 128>>>(ew, cm, esrc, edst);
  k_cm<<<5120, 256>>>(cm_b1, cm_b2);
  k_dec<<<dim3(BQ/32, NND), 256>>>(dec_b1, dec_b2, y_true, out);

  // join before final reductions
  cudaStreamWaitEvent(0, evJoin, 0);
  k_reduce1<<<134, 256>>>();
  k_final<<<1, 32>>>(out);
}

// round 12
// speedup vs baseline: 1.1484x; 1.0060x over previous
#include <cuda_runtime.h>
#include <cuda_bf16.h>
#include <math.h>

#define BQ   32768
#define NND  5
#define HDIM 128
#define NE   10

#define OFF_V    (BQ*NND*32)
#define OFF_HID  (2*BQ*NND*32)
#define OFF_LOSS (OFF_HID + 2*BQ*HDIM)

#define ZALPHA 1.959963984540054f

// fragment arena offsets (uint2 units)
#define WF_ENC1 0
#define WF_ENC2 10240
#define WF_GCN  51200
#define WF_MU   67584
#define WF_SIG  75776
#define WF_CM1  83968
#define WF_CM2  92160
#define WF_DEC1 100352
#define WF_DEC2 141312
#define WF_GI   161792
#define WF_GH   210944
#define WF_TOT  260096

// ----------------------------- device scratch -----------------------------
__device__ float g_bufA[BQ*NND*HDIM];
__device__ float g_bufB[BQ*NND*HDIM];
__device__ float g_mean[BQ*NND*HDIM];
__device__ float g_z  [BQ*NND*HDIM];
__device__ float g_ps [BQ*NND*HDIM];
__device__ uint2 g_Wf [WF_TOT];
__device__ float g_klpart[5120];
__device__ float g_lzpart[5120];
__device__ float g_losspart[5120*132];
__device__ float g_facc[134];

// ------------------------------- helpers ----------------------------------
__device__ __forceinline__ float warp_sum(float v){
#pragma unroll
  for (int o=16;o>0;o>>=1) v += __shfl_xor_sync(0xffffffffu, v, o);
  return v;
}
__device__ __forceinline__ float softplusf(float x){
  return fmaxf(x,0.f) + log1pf(expf(-fabsf(x)));
}
__device__ __forceinline__ float mishf(float x){ return x*tanhf(softplusf(x)); }
__device__ __forceinline__ float sigmf(float x){ return 1.f/(1.f+expf(-x)); }

#define BLOCK_REDUCE8_TO(part, val)                                     \
  do {                                                                  \
    float _v = warp_sum(val);                                           \
    __shared__ float _sred[8];                                          \
    if ((threadIdx.x & 31) == 0) _sred[threadIdx.x >> 5] = _v;          \
    __syncthreads();                                                    \
    if (threadIdx.x == 0)                                               \
      part[blockIdx.x] = ((_sred[0]+_sred[1]) + (_sred[2]+_sred[3]))    \
                       + ((_sred[4]+_sred[5]) + (_sred[6]+_sred[7]));   \
  } while (0)

__device__ __forceinline__ unsigned pkh(float x, float y){
  unsigned short a = __bfloat16_as_ushort(__float2bfloat16_rn(x));
  unsigned short b = __bfloat16_as_ushort(__float2bfloat16_rn(y));
  return ((unsigned)b<<16) | (unsigned)a;
}
__device__ __forceinline__ float bf16f(float x){
  return __bfloat162float(__float2bfloat16_rn(x));
}
__device__ __forceinline__ unsigned sptr(const void* p){
  return (unsigned)__cvta_generic_to_shared(p);
}
__device__ __forceinline__ void ldsm4(unsigned a, unsigned &r0, unsigned &r1,
                                      unsigned &r2, unsigned &r3){
  asm volatile("ldmatrix.sync.aligned.m8n8.x4.shared.b16 {%0,%1,%2,%3}, [%4];"
               : "=r"(r0),"=r"(r1),"=r"(r2),"=r"(r3) : "r"(a));
}
__device__ __forceinline__ void mma16816(float* c, const unsigned* a,
                                         unsigned b0, unsigned b1){
  asm volatile("mma.sync.aligned.m16n8k16.row.col.f32.bf16.bf16.f32 "
      "{%0,%1,%2,%3},{%4,%5,%6,%7},{%8,%9},{%0,%1,%2,%3};"
      : "+f"(c[0]),"+f"(c[1]),"+f"(c[2]),"+f"(c[3])
      : "r"(a[0]),"r"(a[1]),"r"(a[2]),"r"(a[3]),"r"(b0),"r"(b1));
}
__device__ __forceinline__ void mma3(float* c, const unsigned* ah,
    const unsigned* al, uint2 bh, uint2 bl){
  mma16816(c, ah, bh.x, bh.y);
  mma16816(c, al, bh.x, bh.y);
  mma16816(c, ah, bl.x, bl.y);
}

__device__ __forceinline__ void split_st(float4 v, __nv_bfloat16* sh,
    __nv_bfloat16* sl, int off){
  *(uint2*)&sh[off] = make_uint2(pkh(v.x,v.y), pkh(v.z,v.w));
  *(uint2*)&sl[off] = make_uint2(pkh(v.x-bf16f(v.x), v.y-bf16f(v.y)),
                                 pkh(v.z-bf16f(v.z), v.w-bf16f(v.w)));
}

template<int ROWS, int KC, int LDA, int NT_>
__device__ __forceinline__ void stage_split(const float* __restrict__ A, int arst,
    __nv_bfloat16* sh, __nv_bfloat16* sl, int t){
  const int C4 = KC/4;
  for (int f=t; f<ROWS*C4; f+=NT_){
    int r = f/C4, c4 = (f%C4)*4;
    float4 v = *(const float4*)&A[(long)r*arst + c4];
    split_st(v, sh, sl, r*LDA+c4);
  }
}

// 3-term bf16 split mainloop, 1 m16-tile per warp, NT n8-tiles
template<int KT, int NT, int NTOT, int LDA>
__device__ __forceinline__ void hmma_row(const __nv_bfloat16* sh,
    const __nv_bfloat16* sl, const uint2* __restrict__ Wf,
    int n8base, int rowbase, int lane, float (&c)[NT][4]){
#pragma unroll
  for (int nt=0;nt<NT;nt++)
#pragma unroll
    for (int i=0;i<4;i++) c[nt][i] = 0.f;
  int sub = lane>>3;
  int m_off = ((sub&1)<<3) + (lane&7);
  int k_off = (sub>>1)<<3;
#pragma unroll 1
  for (int kt=0; kt<KT; kt++){
    uint2 bh[NT], bl[NT];
#pragma unroll
    for (int nt=0;nt<NT;nt++){
      const uint2* wp = Wf + (((kt*NTOT + n8base + nt)*2)<<5) + lane;
      bh[nt] = wp[0];
      bl[nt] = wp[32];
    }
    unsigned ah[4], al[4];
    int ro = (rowbase + m_off)*LDA + kt*16 + k_off;
    ldsm4(sptr(&sh[ro]), ah[0],ah[1],ah[2],ah[3]);
    ldsm4(sptr(&sl[ro]), al[0],al[1],al[2],al[3]);
#pragma unroll
    for (int nt=0;nt<NT;nt++)
      mma3(c[nt], ah, al, bh[nt], bl[nt]);
  }
}

// --------------------------- single pack kernel ----------------------------
__global__ void k_packall(
    const float* __restrict__ encW1, const float* __restrict__ encW2,
    const float* __restrict__ gcnW,  const float* __restrict__ muW,
    const float* __restrict__ sigW,  const float* __restrict__ cmW1,
    const float* __restrict__ cmW2,  const float* __restrict__ decW1,
    const float* __restrict__ decW2, const float* __restrict__ giW,
    const float* __restrict__ ghW){
  int idx = blockIdx.x*256 + threadIdx.x;
  if (idx >= WF_TOT) return;
  const float* src; int K, N, trans, base, per, mst;
  if      (idx < WF_ENC2){ src=encW1; K=32; N=128; trans=0; base=WF_ENC1; per=2048; mst=4096; }
  else if (idx < WF_GCN ){ src=encW2; K=128;N=128; trans=0; base=WF_ENC2; per=8192; mst=16384;}
  else if (idx < WF_MU  ){ src=gcnW;  K=128;N=128; trans=0; base=WF_GCN;  per=8192; mst=16384;}
  else if (idx < WF_SIG ){ src=muW;   K=128;N=128; trans=0; base=WF_MU;   per=8192; mst=16384;}
  else if (idx < WF_CM1 ){ src=sigW;  K=128;N=128; trans=0; base=WF_SIG;  per=8192; mst=16384;}
  else if (idx < WF_CM2 ){ src=cmW1;  K=128;N=128; trans=0; base=WF_CM1;  per=8192; mst=16384;}
  else if (idx < WF_DEC1){ src=cmW2;  K=128;N=128; trans=0; base=WF_CM2;  per=8192; mst=16384;}
  else if (idx < WF_DEC2){ src=decW1; K=128;N=128; trans=0; base=WF_DEC1; per=8192; mst=16384;}
  else if (idx < WF_GI  ){ src=decW2; K=128;N=64;  trans=0; base=WF_DEC2; per=4096; mst=8192; }
  else if (idx < WF_GH  ){ src=giW;   K=128;N=128; trans=1; base=WF_GI;   per=8192; mst=16384;}
  else                   { src=ghW;   K=128;N=128; trans=1; base=WF_GH;   per=8192; mst=16384;}
  int rr = idx - base;
  int m = rr / per, r = rr % per;
  int lane = r & 31, term = (r>>5)&1;
  int n8 = (r>>6) % (N>>3);
  int kt = (r>>6) / (N>>3);
  int n = n8*8 + (lane>>2);
  int k0 = kt*16 + ((lane&3)<<1);
  const float* S = src + (long)m*mst;
  float w0,w1,w2,w3;
  if (trans){
    w0=S[n*K+k0]; w1=S[n*K+k0+1]; w2=S[n*K+k0+8]; w3=S[n*K+k0+9];
  } else {
    w0=S[k0*N+n]; w1=S[(k0+1)*N+n]; w2=S[(k0+8)*N+n]; w3=S[(k0+9)*N+n];
  }
  uint2 o;
  if (term==0){ o = make_uint2(pkh(w0,w1), pkh(w2,w3)); }
  else {
    o = make_uint2(pkh(w0-bf16f(w0), w1-bf16f(w1)),
                   pkh(w2-bf16f(w2), w3-bf16f(w3)));
  }
  g_Wf[idx] = o;
}

// ------------------------------ encoder ------------------------------------
__global__ __launch_bounds__(256,5) void k_enc(
    const float* __restrict__ x, const float* __restrict__ b1,
    const float* __restrict__ b2){
  __shared__ __align__(16) __nv_bfloat16 xh[32*40], xl[32*40];
  __shared__ __align__(16) __nv_bfloat16 hh[32*136], hl[32*136];
  int t = threadIdx.x, lane = t&31, warp = t>>5;
  int wrow = warp>>2, wcol = warp&3;
  int n = blockIdx.y;
  long b0 = (long)blockIdx.x*32;
  stage_split<32,32,40,256>(x + b0*160 + n*32, 160, xh, xl, t);
  __syncthreads();
  float c[4][4];
  hmma_row<2,4,16,40>(xh, xl, &g_Wf[WF_ENC1 + n*2048], wcol*4, wrow*16, lane, c);
  __syncthreads();
  {
    int r0 = wrow*16 + (lane>>2);
#pragma unroll
    for (int nt=0;nt<4;nt++){
      int col = (wcol*4+nt)*8 + ((lane&3)<<1);
      float2 bb = *(const float2*)&b1[n*128 + col];
      float v00=fmaxf(c[nt][0]+bb.x,0.f), v01=fmaxf(c[nt][1]+bb.y,0.f);
      float v10=fmaxf(c[nt][2]+bb.x,0.f), v11=fmaxf(c[nt][3]+bb.y,0.f);
      *(unsigned*)&hh[r0*136+col] = pkh(v00,v01);
      *(unsigned*)&hl[r0*136+col] = pkh(v00-bf16f(v00), v01-bf16f(v01));
      *(unsigned*)&hh[(r0+8)*136+col] = pkh(v10,v11);
      *(unsigned*)&hl[(r0+8)*136+col] = pkh(v10-bf16f(v10), v11-bf16f(v11));
    }
  }
  __syncthreads();
  hmma_row<8,4,16,136>(hh, hl, &g_Wf[WF_ENC2 + n*8192], wcol*4, wrow*16, lane, c);
  {
    long r0 = b0 + wrow*16 + (lane>>2);
#pragma unroll
    for (int nt=0;nt<4;nt++){
      int col = (wcol*4+nt)*8 + ((lane&3)<<1);
      float2 bb = *(const float2*)&b2[n*128 + col];
      *(float2*)&g_bufA[r0*640 + n*128 + col] =
          make_float2(c[nt][0]+bb.x, c[nt][1]+bb.y);
      *(float2*)&g_bufA[(r0+8)*640 + n*128 + col] =
          make_float2(c[nt][2]+bb.x, c[nt][3]+bb.y);
    }
  }
}

// ------------------- GCN: fused aggregation + GEMM -------------------------
__global__ __launch_bounds__(256,5) void k_gcn(
    int l, const float* __restrict__ ew,
    const int* __restrict__ esrc, const int* __restrict__ edst,
    const float* __restrict__ bias){
  __shared__ __align__(16) __nv_bfloat16 sh[32*136], sl[32*136];
  __shared__ int s_src[NE], s_dst[NE];
  int t = threadIdx.x, lane = t&31, warp = t>>5;
  int wrow = warp>>2, wcol = warp&3;
  const float* gin  = (l==0) ? g_bufA : g_bufB;
  float*       gout = (l==0) ? g_bufB : g_bufA;
  long b0 = (long)blockIdx.x*32;
  if (t < NE){ s_src[t] = esrc[t]; s_dst[t] = edst[t]; }
  __syncthreads();
  for (int f=t; f<32*32; f+=256){
    int r = f>>5, c4 = (f&31)<<2;
    long R = b0 + r;
    int b = (int)(R/5), v = (int)(R - 5l*b);
    const float* row = gin + (long)b*640;
    float4 a = *(const float4*)&row[v*128 + c4];
#pragma unroll
    for (int e=0;e<NE;e++){
      if (s_dst[e] == v){
        float w = __ldg(&ew[b*NE + e]);
        float4 g = *(const float4*)&row[s_src[e]*128 + c4];
        a.x += w*g.x; a.y += w*g.y; a.z += w*g.z; a.w += w*g.w;
      }
    }
    split_st(a, sh, sl, r*136+c4);
  }
  __syncthreads();
  float c[4][4];
  hmma_row<8,4,16,136>(sh, sl, &g_Wf[WF_GCN + l*8192], wcol*4, wrow*16, lane, c);
  {
    long r0 = b0 + wrow*16 + (lane>>2);
#pragma unroll
    for (int nt=0;nt<4;nt++){
      int col = (wcol*4+nt)*8 + ((lane&3)<<1);
      float2 bb = *(const float2*)&bias[l*128 + col];
      *(float2*)&gout[r0*128 + col] = make_float2(
          fmaxf(c[nt][0]+bb.x,0.f), fmaxf(c[nt][1]+bb.y,0.f));
      *(float2*)&gout[(r0+8)*128 + col] = make_float2(
          fmaxf(c[nt][2]+bb.x,0.f), fmaxf(c[nt][3]+bb.y,0.f));
    }
  }
}

// ----------------------- mu/sig heads + KL ---------------------------------
__global__ __launch_bounds__(256,5) void k_musig(
    const float* __restrict__ mub, const float* __restrict__ sigb){
  __shared__ __align__(16) __nv_bfloat16 sh[32*136], sl[32*136];
  int t = threadIdx.x, lane = t&31, warp = t>>5;
  int wrow = warp>>2, wcol = warp&3;
  long b0 = (long)blockIdx.x*32;
  stage_split<32,128,136,256>(g_bufA + b0*128, 128, sh, sl, t);
  __syncthreads();
  float c[4][4];
  float kll = 0.f;
  hmma_row<8,4,16,136>(sh, sl, &g_Wf[WF_MU], wcol*4, wrow*16, lane, c);
  {
    long r0 = b0 + wrow*16 + (lane>>2);
#pragma unroll
    for (int nt=0;nt<4;nt++){
      int col = (wcol*4+nt)*8 + ((lane&3)<<1);
      float2 bb = *(const float2*)&mub[col];
      float m00=c[nt][0]+bb.x, m01=c[nt][1]+bb.y;
      float m10=c[nt][2]+bb.x, m11=c[nt][3]+bb.y;
      *(float2*)&g_mean[r0*128 + col]     = make_float2(m00,m01);
      *(float2*)&g_mean[(r0+8)*128 + col] = make_float2(m10,m11);
      kll += m00*m00 + m01*m01 + m10*m10 + m11*m11;
    }
  }
  hmma_row<8,4,16,136>(sh, sl, &g_Wf[WF_SIG], wcol*4, wrow*16, lane, c);
#pragma unroll
  for (int nt=0;nt<4;nt++){
    int col = (wcol*4+nt)*8 + ((lane&3)<<1);
    float2 bb = *(const float2*)&sigb[col];
#pragma unroll
    for (int i=0;i<4;i++){
      float sp = softplusf(c[nt][i] + ((i&1)?bb.y:bb.x));
      float var = sp*sp;
      kll += var - logf(var + 1e-8f) - 1.f;
    }
  }
  BLOCK_REDUCE8_TO(g_klpart, kll);
}

// ------------- GRU: fused dual-GEMM + gates (one kernel per layer) ---------
__global__ __launch_bounds__(256) void k_gru(
    int l, const float* __restrict__ xin, const float* __restrict__ hist,
    const float* __restrict__ bih, const float* __restrict__ bhh,
    float* __restrict__ hout){
  __shared__ __align__(16) __nv_bfloat16 xh[32*136], xl[32*136];
  __shared__ __align__(16) __nv_bfloat16 hhs[32*136], hls[32*136];
  int t = threadIdx.x, lane = t&31, warp = t>>5;   // 8 warps
  long b0 = (long)blockIdx.x*32;
  for (int f=t; f<32*32; f+=256){
    int r = f>>5, c4 = (f&31)<<2;
    long b = b0 + r;
    float4 v;
    if (xin){
      v = *(const float4*)&xin[b*128 + c4];
    } else {
      v = *(const float4*)&g_mean[b*640 + c4];
#pragma unroll
      for (int vv=1; vv<5; vv++){
        float4 m = *(const float4*)&g_mean[b*640 + vv*128 + c4];
        v.x+=m.x; v.y+=m.y; v.z+=m.z; v.w+=m.w;
      }
      v.x*=0.2f; v.y*=0.2f; v.z*=0.2f; v.w*=0.2f;
    }
    split_st(v, xh, xl, r*136+c4);
    float4 hv = *(const float4*)&hist[((long)l*BQ + b)*128 + c4];
    split_st(hv, hhs, hls, r*136+c4);
  }
  __syncthreads();
  float cr[2][2][4], cz[2][2][4], cin[2][2][4], chn[2][2][4];
#pragma unroll
  for (int mt=0;mt<2;mt++)
#pragma unroll
    for (int nt=0;nt<2;nt++)
#pragma unroll
      for (int i=0;i<4;i++){ cr[mt][nt][i]=0.f; cz[mt][nt][i]=0.f;
                             cin[mt][nt][i]=0.f; chn[mt][nt][i]=0.f; }
  int sub = lane>>3;
  int m_off = ((sub&1)<<3) + (lane&7);
  int k_off = (sub>>1)<<3;
  const uint2* Wi = &g_Wf[WF_GI + l*3*8192];
  const uint2* Wh = &g_Wf[WF_GH + l*3*8192];
#pragma unroll 1
  for (int kt=0; kt<8; kt++){
    unsigned axh[2][4], axl[2][4], ahh[2][4], ahl[2][4];
#pragma unroll
    for (int mt=0;mt<2;mt++){
      int ro = (mt*16 + m_off)*136 + kt*16 + k_off;
      ldsm4(sptr(&xh[ro]),  axh[mt][0],axh[mt][1],axh[mt][2],axh[mt][3]);
      ldsm4(sptr(&xl[ro]),  axl[mt][0],axl[mt][1],axl[mt][2],axl[mt][3]);
      ldsm4(sptr(&hhs[ro]), ahh[mt][0],ahh[mt][1],ahh[mt][2],ahh[mt][3]);
      ldsm4(sptr(&hls[ro]), ahl[mt][0],ahl[mt][1],ahl[mt][2],ahl[mt][3]);
    }
#pragma unroll
    for (int nt=0;nt<2;nt++){
      int fo = (((kt*16 + warp*2 + nt)*2)<<5) + lane;
      { uint2 bh=Wi[fo], bl=Wi[fo+32];
        uint2 ch=Wh[fo], cl=Wh[fo+32];
#pragma unroll
        for (int mt=0;mt<2;mt++){
          mma3(cr[mt][nt], axh[mt], axl[mt], bh, bl);
          mma3(cr[mt][nt], ahh[mt], ahl[mt], ch, cl);
        } }
      { uint2 bh=Wi[8192+fo], bl=Wi[8192+fo+32];
        uint2 ch=Wh[8192+fo], cl=Wh[8192+fo+32];
#pragma unroll
        for (int mt=0;mt<2;mt++){
          mma3(cz[mt][nt], axh[mt], axl[mt], bh, bl);
          mma3(cz[mt][nt], ahh[mt], ahl[mt], ch, cl);
        } }
      { uint2 bh=Wi[16384+fo], bl=Wi[16384+fo+32];
        uint2 ch=Wh[16384+fo], cl=Wh[16384+fo+32];
#pragma unroll
        for (int mt=0;mt<2;mt++){
          mma3(cin[mt][nt], axh[mt], axl[mt], bh, bl);
          mma3(chn[mt][nt], ahh[mt], ahl[mt], ch, cl);
        } }
    }
  }
#pragma unroll
  for (int mt=0;mt<2;mt++){
    long gb = b0 + mt*16 + (lane>>2);
#pragma unroll
    for (int nt=0;nt<2;nt++){
      int col = warp*16 + nt*8 + ((lane&3)<<1);
      float2 bir = *(const float2*)&bih[l*384 + col];
      float2 biz = *(const float2*)&bih[l*384 + 128 + col];
      float2 bin_= *(const float2*)&bih[l*384 + 256 + col];
      float2 bhr = *(const float2*)&bhh[l*384 + col];
      float2 bhz = *(const float2*)&bhh[l*384 + 128 + col];
      float2 bhn = *(const float2*)&bhh[l*384 + 256 + col];
      float2 hp0 = *(const float2*)&hist[((long)l*BQ + gb)*128 + col];
      float2 hp1 = *(const float2*)&hist[((long)l*BQ + gb + 8)*128 + col];
      float r0=sigmf(cr[mt][nt][0]+bir.x+bhr.x);
      float r1=sigmf(cr[mt][nt][1]+bir.y+bhr.y);
      float r2=sigmf(cr[mt][nt][2]+bir.x+bhr.x);
      float r3=sigmf(cr[mt][nt][3]+bir.y+bhr.y);
      float z0=sigmf(cz[mt][nt][0]+biz.x+bhz.x);
      float z1=sigmf(cz[mt][nt][1]+biz.y+bhz.y);
      float z2=sigmf(cz[mt][nt][2]+biz.x+bhz.x);
      float z3=sigmf(cz[mt][nt][3]+biz.y+bhz.y);
      float n0=tanhf(cin[mt][nt][0]+bin_.x + r0*(chn[mt][nt][0]+bhn.x));
      float n1=tanhf(cin[mt][nt][1]+bin_.y + r1*(chn[mt][nt][1]+bhn.y));
      float n2=tanhf(cin[mt][nt][2]+bin_.x + r2*(chn[mt][nt][2]+bhn.x));
      float n3=tanhf(cin[mt][nt][3]+bin_.y + r3*(chn[mt][nt][3]+bhn.y));
      *(float2*)&hout[gb*128 + col] =
          make_float2((1.f-z0)*n0 + z0*hp0.x, (1.f-z1)*n1 + z1*hp0.y);
      *(float2*)&hout[(gb+8)*128 + col] =
          make_float2((1.f-z2)*n2 + z2*hp1.x, (1.f-z3)*n3 + z3*hp1.y);
    }
  }
}

// --------------------- causal solve + parent_sum ---------------------------
__global__ __launch_bounds__(128) void k_causal(
    const float* __restrict__ ew, const float* __restrict__ cm,
    const int* __restrict__ esrc, const int* __restrict__ edst){
  int b = blockIdx.x, t = threadIdx.x;
  __shared__ float s_ew[NE], s_cm[NND*NND];
  __shared__ int s_src[NE], s_dst[NE];
  if (t < NE){ s_ew[t] = ew[b*NE + t]; s_src[t] = esrc[t]; s_dst[t] = edst[t]; }
  if (t < NND*NND) s_cm[t] = cm[t];
  __syncthreads();
  int base = b*NND*HDIM + t;
  float z[NND];
#pragma unroll
  for (int j=0;j<NND;j++) z[j] = g_mean[base + j*HDIM];
#pragma unroll
  for (int j=1;j<NND;j++){
    float add = 0.f;
#pragma unroll
    for (int e=0;e<NE;e++){
      if (s_dst[e] == j){
        int s = s_src[e];
        float zs = (s==0)?z[0]:((s==1)?z[1]:((s==2)?z[2]:z[3]));
        add += s_ew[e]*s_cm[s*NND + j]*zs;
      }
    }
    z[j] += add;
  }
#pragma unroll
  for (int j=0;j<NND;j++) g_z[base + j*HDIM] = z[j];
#pragma unroll
  for (int j=0;j<NND;j++){
    float ps = 0.f;
#pragma unroll
    for (int i=0;i<NND;i++)
      if (s_cm[i*NND + j] != 0.f) ps += z[i];
    g_ps[base + j*HDIM] = ps;
  }
}

// ------------------- cm MLP fused (2 GEMMs) + l_z --------------------------
__global__ __launch_bounds__(256,5) void k_cm(
    const float* __restrict__ b1, const float* __restrict__ b2){
  __shared__ __align__(16) __nv_bfloat16 sh[32*136], sl[32*136];
  int t = threadIdx.x, lane = t&31, warp = t>>5;
  int wrow = warp>>2, wcol = warp&3;
  long b0 = (long)blockIdx.x*32;
  stage_split<32,128,136,256>(g_ps + b0*128, 128, sh, sl, t);
  __syncthreads();
  float c[4][4];
  hmma_row<8,4,16,136>(sh, sl, &g_Wf[WF_CM1], wcol*4, wrow*16, lane, c);
  __syncthreads();
  {
    int r0 = wrow*16 + (lane>>2);
#pragma unroll
    for (int nt=0;nt<4;nt++){
      int col = (wcol*4+nt)*8 + ((lane&3)<<1);
      float2 bb = *(const float2*)&b1[col];
      float v00=mishf(c[nt][0]+bb.x), v01=mishf(c[nt][1]+bb.y);
      float v10=mishf(c[nt][2]+bb.x), v11=mishf(c[nt][3]+bb.y);
      *(unsigned*)&sh[r0*136+col] = pkh(v00,v01);
      *(unsigned*)&sl[r0*136+col] = pkh(v00-bf16f(v00), v01-bf16f(v01));
      *(unsigned*)&sh[(r0+8)*136+col] = pkh(v10,v11);
      *(unsigned*)&sl[(r0+8)*136+col] = pkh(v10-bf16f(v10), v11-bf16f(v11));
    }
  }
  __syncthreads();
  hmma_row<8,4,16,136>(sh, sl, &g_Wf[WF_CM2], wcol*4, wrow*16, lane, c);
  float lz = 0.f;
  {
    long r0 = b0 + wrow*16 + (lane>>2);
#pragma unroll
    for (int nt=0;nt<4;nt++){
      int col = (wcol*4+nt)*8 + ((lane&3)<<1);
      float2 bb = *(const float2*)&b2[col];
      float2 z0 = *(const float2*)&g_z[r0*128 + col];
      float2 z1 = *(const float2*)&g_z[(r0+8)*128 + col];
      float d0 = z0.x - (c[nt][0]+bb.x);
      float d1 = z0.y - (c[nt][1]+bb.y);
      float d2 = z1.x - (c[nt][2]+bb.x);
      float d3 = z1.y - (c[nt][3]+bb.y);
      lz += d0*d0 + d1*d1 + d2*d2 + d3*d3;
    }
  }
  BLOCK_REDUCE8_TO(g_lzpart, lz);
}

// ----------------- decoder fused (2 GEMMs) + losses ------------------------
__global__ __launch_bounds__(256,5) void k_dec(
    const float* __restrict__ b1, const float* __restrict__ b2,
    const float* __restrict__ yt_g, float* __restrict__ out){
  __shared__ __align__(16) __nv_bfloat16 sh[32*136], sl[32*136];
  __shared__ float s_piw[8][32], s_kd[8][32], s_mn[8][32], s_mx[8][32];
  __shared__ float s_sc[3][8];
  float* s_out = (float*)sh;     // 32*66 floats = 8448B <= 8704B ✓
  int t = threadIdx.x, lane = t&31, warp = t>>5;
  int wrow = warp>>2, wcol = warp&3;
  int n = blockIdx.y;
  long b0 = (long)blockIdx.x*32;
  stage_split<32,128,136,256>(g_z + b0*640 + n*128, 640, sh, sl, t);
  __syncthreads();
  float c[4][4];
  hmma_row<8,4,16,136>(sh, sl, &g_Wf[WF_DEC1 + n*8192], wcol*4, wrow*16, lane, c);
  __syncthreads();
  {
    int r0 = wrow*16 + (lane>>2);
#pragma unroll
    for (int nt=0;nt<4;nt++){
      int col = (wcol*4+nt)*8 + ((lane&3)<<1);
      float2 bb = *(const float2*)&b1[n*128 + col];
      float v00=mishf(c[nt][0]+bb.x), v01=mishf(c[nt][1]+bb.y);
      float v10=mishf(c[nt][2]+bb.x), v11=mishf(c[nt][3]+bb.y);
      *(unsigned*)&sh[r0*136+col] = pkh(v00,v01);
      *(unsigned*)&sl[r0*136+col] = pkh(v00-bf16f(v00), v01-bf16f(v01));
      *(unsigned*)&sh[(r0+8)*136+col] = pkh(v10,v11);
      *(unsigned*)&sl[(r0+8)*136+col] = pkh(v10-bf16f(v10), v11-bf16f(v11));
    }
  }
  __syncthreads();
  float c2[2][4];
  hmma_row<8,2,8,136>(sh, sl, &g_Wf[WF_DEC2 + n*4096], wcol*2, wrow*16, lane, c2);
  __syncthreads();   // all reads of sh done before aliasing as s_out
  {
    int r = wrow*16 + (lane>>2);
#pragma unroll
    for (int nt=0;nt<2;nt++){
      int col = (wcol*2+nt)*8 + ((lane&3)<<1);
      float2 bb = *(const float2*)&b2[n*64 + col];
      float v00=c2[nt][0]+bb.x, v01=c2[nt][1]+bb.y;
      float v10=c2[nt][2]+bb.x, v11=c2[nt][3]+bb.y;
      if (col >= 32){ v00=expf(v00); v01=expf(v01); v10=expf(v10); v11=expf(v11); }
      s_out[r*66+col]=v00;     s_out[r*66+col+1]=v01;
      s_out[(r+8)*66+col]=v10; s_out[(r+8)*66+col+1]=v11;
      long gb0, gb1;
      if (col < 32){
        gb0 = (b0+r)*160 + n*32 + col;
        gb1 = (b0+r+8)*160 + n*32 + col;
      } else {
        gb0 = (long)OFF_V + (b0+r)*160 + n*32 + col-32;
        gb1 = (long)OFF_V + (b0+r+8)*160 + n*32 + col-32;
      }
      *(float2*)&out[gb0] = make_float2(v00,v01);
      *(float2*)&out[gb1] = make_float2(v10,v11);
    }
  }
  __syncthreads();
  int d = lane;
  float ll=0.f, sq4=0.f, bce=0.f;
  float piw=0.f, kd=0.f, mn=1e30f, mx=-1e30f;
#pragma unroll
  for (int i=0;i<4;i++){
    int row = warp + 8*i;
    float ym = s_out[row*66 + d];
    float yv = s_out[row*66 + 32 + d];
    float yt = yt_g[(b0+row)*160 + n*32 + d];
    float vs = yv + 1e-6f;
    float df = yt - ym;
    ll += -0.5f*(df*df/vs + logf(6.2831853071795864f*vs));
    if (n < 4) sq4 += df*df;
    if (n == 4) bce += fmaxf(ym,0.f) - ym*yt + log1pf(expf(-fabsf(ym)));
    float s  = sqrtf(vs);
    float lo_ = ym - ZALPHA*s, up_ = ym + ZALPHA*s;
    float kf = (yt >= lo_ && yt <= up_) ? 1.f : 0.f;
    kd  += kf;
    piw += (up_-lo_)*kf;
    mn = fminf(mn, yt);
    mx = fmaxf(mx, yt);
  }
  ll  = warp_sum(ll);
  sq4 = warp_sum(sq4);
  bce = warp_sum(bce);
  if (lane == 0){ s_sc[0][warp]=ll; s_sc[1][warp]=sq4; s_sc[2][warp]=bce; }
  s_piw[warp][d]=piw; s_kd[warp][d]=kd; s_mn[warp][d]=mn; s_mx[warp][d]=mx;
  __syncthreads();
  int blk = blockIdx.y*gridDim.x + blockIdx.x;
  float* P = g_losspart + blk*132;
  if (t == 0){
    P[0] = ((s_sc[0][0]+s_sc[0][1]) + (s_sc[0][2]+s_sc[0][3]))
         + ((s_sc[0][4]+s_sc[0][5]) + (s_sc[0][6]+s_sc[0][7]));
    P[1] = ((s_sc[1][0]+s_sc[1][1]) + (s_sc[1][2]+s_sc[1][3]))
         + ((s_sc[1][4]+s_sc[1][5]) + (s_sc[1][6]+s_sc[1][7]));
    P[2] = ((s_sc[2][0]+s_sc[2][1]) + (s_sc[2][2]+s_sc[2][3]))
         + ((s_sc[2][4]+s_sc[2][5]) + (s_sc[2][6]+s_sc[2][7]));
    P[3] = 0.f;
  }
  if (t < 32){
    float p=0.f, k=0.f, m=1e30f, xx=-1e30f;
#pragma unroll
    for (int g=0; g<8; g++){
      p += s_piw[g][t]; k += s_kd[g][t];
      m = fminf(m, s_mn[g][t]); xx = fmaxf(xx, s_mx[g][t]);
    }
    P[4+t] = p; P[36+t] = k; P[68+t] = m; P[100+t] = xx;
  }
}

// ---------------------- stage-1 reduce + final -----------------------------
__global__ void k_reduce1(){
  int col = blockIdx.x, t = threadIdx.x;
  bool ismin = (col >= 68 && col < 100);
  bool ismax = (col >= 100 && col < 132);
  float v = ismin ? 1e30f : (ismax ? -1e30f : 0.f);
  if (col < 132){
    for (int i=t; i<5120; i+=256){
      float x = g_losspart[i*132 + col];
      v = ismin ? fminf(v,x) : (ismax ? fmaxf(v,x) : v + x);
    }
  } else if (col == 132){
    for (int i=t; i<5120; i+=256) v += g_klpart[i];
  } else {
    for (int i=t; i<5120; i+=256) v += g_lzpart[i];
  }
  __shared__ float sm[256];
  sm[t] = v;
  __syncthreads();
  for (int s=128; s>0; s>>=1){
    if (t < s){
      float a = sm[t], b = sm[t+s];
      sm[t] = ismin ? fminf(a,b) : (ismax ? fmaxf(a,b) : a + b);
    }
    __syncthreads();
  }
  if (t == 0) g_facc[col] = sm[0];
}

__global__ void k_final(float* __restrict__ out){
  if (threadIdx.x != 0 || blockIdx.x != 0) return;
  float S_ll = g_facc[0], S_sq4 = g_facc[1], S_bce = g_facc[2];
  float kl = 0.5f*g_facc[132];
  float S_lz = g_facc[133];
  float mean_ll = S_ll / 5242880.0f;
  float elbo = kl/32768.0f - mean_ll;
  float l_reg = (S_sq4/32.0f) / (4.0f*32768.0f + 1e-6f);
  float l_cls = (S_bce/32.0f) / (32768.0f + 1e-6f);
  float l_rec = l_reg + l_cls;
  float Sk = 0.f, pin = 0.f;
  for (int d=0; d<32; d++){
    float kdv = g_facc[36+d];
    Sk += kdv;
    pin += g_facc[4+d] / (kdv + 1e-6f) / (g_facc[100+d] - g_facc[68+d] + 1e-6f);
  }
  float picp  = Sk / 5242880.0f;
  float pinaw = pin / 32.0f;
  float l_pi  = pinaw - sqrtf(5.0f)*picp;
  float l_z   = S_lz / 20971520.0f;
  float dag   = 0.0f;  // exact: diag((I+ac)^5)==1 for strictly-upper ac
  float total = powf(elbo*l_rec*l_pi*l_z*(dag + 1e-6f), 0.2f);
  out[OFF_LOSS+0] = total;
  out[OFF_LOSS+1] = elbo;
  out[OFF_LOSS+2] = l_rec;
  out[OFF_LOSS+3] = l_pi;
  out[OFF_LOSS+4] = l_z;
  out[OFF_LOSS+5] = dag;
}

// ------------------------------ launcher -----------------------------------
extern "C" void kernel_launch(void* const* d_in, const int* in_sizes, int n_in,
                              void* d_out, int out_size){
  const float* x       = (const float*)d_in[0];
  const float* y_true  = (const float*)d_in[1];
  const float* ew      = (const float*)d_in[2];
  const float* hist    = (const float*)d_in[3];
  const float* enc_W1  = (const float*)d_in[4];
  const float* enc_b1  = (const float*)d_in[5];
  const float* enc_W2  = (const float*)d_in[6];
  const float* enc_b2  = (const float*)d_in[7];
  const float* gcn_W   = (const float*)d_in[8];
  const float* gcn_b   = (const float*)d_in[9];
  const float* mu_W    = (const float*)d_in[10];
  const float* mu_b    = (const float*)d_in[11];
  const float* sig_W   = (const float*)d_in[12];
  const float* sig_b   = (const float*)d_in[13];
  const float* gru_Wih = (const float*)d_in[14];
  const float* gru_Whh = (const float*)d_in[15];
  const float* gru_bih = (const float*)d_in[16];
  const float* gru_bhh = (const float*)d_in[17];
  const float* cm      = (const float*)d_in[18];
  const float* cm_W1   = (const float*)d_in[19];
  const float* cm_b1   = (const float*)d_in[20];
  const float* cm_W2   = (const float*)d_in[21];
  const float* cm_b2   = (const float*)d_in[22];
  const float* dec_W1  = (const float*)d_in[23];
  const float* dec_b1  = (const float*)d_in[24];
  const float* dec_W2  = (const float*)d_in[25];
  const float* dec_b2  = (const float*)d_in[26];
  const int*   esrc    = (const int*)d_in[27];
  const int*   edst    = (const int*)d_in[28];
  float* out = (float*)d_out;

  static cudaStream_t s2 = 0, s3 = 0;
  static cudaEvent_t evFork = 0, evJoin = 0, evC = 0, evJoin3 = 0;
  if (!s2){
    cudaStreamCreateWithFlags(&s2, cudaStreamNonBlocking);
    cudaStreamCreateWithFlags(&s3, cudaStreamNonBlocking);
    cudaEventCreateWithFlags(&evFork, cudaEventDisableTiming);
    cudaEventCreateWithFlags(&evJoin, cudaEventDisableTiming);
    cudaEventCreateWithFlags(&evC, cudaEventDisableTiming);
    cudaEventCreateWithFlags(&evJoin3, cudaEventDisableTiming);
  }

  k_packall<<<(WF_TOT+255)/256, 256>>>(enc_W1, enc_W2, gcn_W, mu_W, sig_W,
                                       cm_W1, cm_W2, dec_W1, dec_W2,
                                       gru_Wih, gru_Whh);
  k_enc<<<dim3(BQ/32, NND), 256>>>(x, enc_b1, enc_b2);
  k_gcn<<<5120, 256>>>(0, ew, esrc, edst, gcn_b);
  k_gcn<<<5120, 256>>>(1, ew, esrc, edst, gcn_b);
  k_musig<<<5120, 256>>>(mu_b, sig_b);

  // fork A: GRU chain on s2
  cudaEventRecord(evFork, 0);
  cudaStreamWaitEvent(s2, evFork, 0);
  k_gru<<<BQ/32, 256, 0, s2>>>(0, nullptr, hist, gru_bih, gru_bhh,
                               out + OFF_HID);
  k_gru<<<BQ/32, 256, 0, s2>>>(1, out + OFF_HID, hist, gru_bih, gru_bhh,
                               out + OFF_HID + BQ*HDIM);
  cudaEventRecord(evJoin, s2);

  // main: causal, then fork B: cm on s3 parallel with dec on default
  k_causal<<<BQ, 128>>>(ew, cm, esrc, edst);
  cudaEventRecord(evC, 0);
  cudaStreamWaitEvent(s3, evC, 0);
  k_cm<<<5120, 256, 0, s3>>>(cm_b1, cm_b2);
  cudaEventRecord(evJoin3, s3);

  k_dec<<<dim3(BQ/32, NND), 256>>>(dec_b1, dec_b2, y_true, out);

  // join both branches before final reductions
  cudaStreamWaitEvent(0, evJoin, 0);
  cudaStreamWaitEvent(0, evJoin3, 0);
  k_reduce1<<<134, 256>>>();
  k_final<<<1, 32>>>(out);
}

// round 13
// speedup vs baseline: 1.1823x; 1.0295x over previous
#include <cuda_runtime.h>
#include <cuda_bf16.h>
#include <math.h>

#define BQ   32768
#define NND  5
#define HDIM 128
#define NE   10

#define OFF_V    (BQ*NND*32)
#define OFF_HID  (2*BQ*NND*32)
#define OFF_LOSS (OFF_HID + 2*BQ*HDIM)

#define ZALPHA 1.959963984540054f

// fragment arena offsets (uint2 units)
#define WF_ENC1 0
#define WF_ENC2 10240
#define WF_GCN  51200
#define WF_MU   67584
#define WF_SIG  75776
#define WF_CM1  83968
#define WF_CM2  92160
#define WF_DEC1 100352
#define WF_DEC2 141312
#define WF_GI   161792
#define WF_GH   210944
#define WF_TOT  260096

// ----------------------------- device scratch -----------------------------
__device__ float g_bufA[BQ*NND*HDIM];
__device__ float g_bufB[BQ*NND*HDIM];
__device__ float g_mean[BQ*NND*HDIM];
__device__ float g_z  [BQ*NND*HDIM];
__device__ float g_ps [BQ*NND*HDIM];
__device__ uint2 g_Wf [WF_TOT];
__device__ float g_klpart[5120];
__device__ float g_lzpart[5120];
__device__ float g_losspart[5120*132];
__device__ float g_facc[134];

// ------------------------------- helpers ----------------------------------
__device__ __forceinline__ float warp_sum(float v){
#pragma unroll
  for (int o=16;o>0;o>>=1) v += __shfl_xor_sync(0xffffffffu, v, o);
  return v;
}
__device__ __forceinline__ float softplusf(float x){
  return fmaxf(x,0.f) + log1pf(expf(-fabsf(x)));
}
__device__ __forceinline__ float mishf(float x){ return x*tanhf(softplusf(x)); }
__device__ __forceinline__ float sigmf(float x){ return 1.f/(1.f+expf(-x)); }

#define BLOCK_REDUCE8_TO(part, val)                                     \
  do {                                                                  \
    float _v = warp_sum(val);                                           \
    __shared__ float _sred[8];                                          \
    if ((threadIdx.x & 31) == 0) _sred[threadIdx.x >> 5] = _v;          \
    __syncthreads();                                                    \
    if (threadIdx.x == 0)                                               \
      part[blockIdx.x] = ((_sred[0]+_sred[1]) + (_sred[2]+_sred[3]))    \
                       + ((_sred[4]+_sred[5]) + (_sred[6]+_sred[7]));   \
  } while (0)

__device__ __forceinline__ unsigned pkh(float x, float y){
  unsigned short a = __bfloat16_as_ushort(__float2bfloat16_rn(x));
  unsigned short b = __bfloat16_as_ushort(__float2bfloat16_rn(y));
  return ((unsigned)b<<16) | (unsigned)a;
}
__device__ __forceinline__ float bf16f(float x){
  return __bfloat162float(__float2bfloat16_rn(x));
}
__device__ __forceinline__ unsigned sptr(const void* p){
  return (unsigned)__cvta_generic_to_shared(p);
}
__device__ __forceinline__ void ldsm4(unsigned a, unsigned &r0, unsigned &r1,
                                      unsigned &r2, unsigned &r3){
  asm volatile("ldmatrix.sync.aligned.m8n8.x4.shared.b16 {%0,%1,%2,%3}, [%4];"
               : "=r"(r0),"=r"(r1),"=r"(r2),"=r"(r3) : "r"(a));
}
__device__ __forceinline__ void mma16816(float* c, const unsigned* a,
                                         unsigned b0, unsigned b1){
  asm volatile("mma.sync.aligned.m16n8k16.row.col.f32.bf16.bf16.f32 "
      "{%0,%1,%2,%3},{%4,%5,%6,%7},{%8,%9},{%0,%1,%2,%3};"
      : "+f"(c[0]),"+f"(c[1]),"+f"(c[2]),"+f"(c[3])
      : "r"(a[0]),"r"(a[1]),"r"(a[2]),"r"(a[3]),"r"(b0),"r"(b1));
}
__device__ __forceinline__ void mma3(float* c, const unsigned* ah,
    const unsigned* al, uint2 bh, uint2 bl){
  mma16816(c, ah, bh.x, bh.y);
  mma16816(c, al, bh.x, bh.y);
  mma16816(c, ah, bl.x, bl.y);
}

__device__ __forceinline__ void split_st(float4 v, __nv_bfloat16* sh,
    __nv_bfloat16* sl, int off){
  *(uint2*)&sh[off] = make_uint2(pkh(v.x,v.y), pkh(v.z,v.w));
  *(uint2*)&sl[off] = make_uint2(pkh(v.x-bf16f(v.x), v.y-bf16f(v.y)),
                                 pkh(v.z-bf16f(v.z), v.w-bf16f(v.w)));
}

template<int ROWS, int KC, int LDA, int NT_>
__device__ __forceinline__ void stage_split(const float* __restrict__ A, int arst,
    __nv_bfloat16* sh, __nv_bfloat16* sl, int t){
  const int C4 = KC/4;
  for (int f=t; f<ROWS*C4; f+=NT_){
    int r = f/C4, c4 = (f%C4)*4;
    float4 v = *(const float4*)&A[(long)r*arst + c4];
    split_st(v, sh, sl, r*LDA+c4);
  }
}

// 3-term bf16 split mainloop, 1 m16-tile per warp, NT n8-tiles
template<int KT, int NT, int NTOT, int LDA>
__device__ __forceinline__ void hmma_row(const __nv_bfloat16* sh,
    const __nv_bfloat16* sl, const uint2* __restrict__ Wf,
    int n8base, int rowbase, int lane, float (&c)[NT][4]){
#pragma unroll
  for (int nt=0;nt<NT;nt++)
#pragma unroll
    for (int i=0;i<4;i++) c[nt][i] = 0.f;
  int sub = lane>>3;
  int m_off = ((sub&1)<<3) + (lane&7);
  int k_off = (sub>>1)<<3;
#pragma unroll 1
  for (int kt=0; kt<KT; kt++){
    uint2 bh[NT], bl[NT];
#pragma unroll
    for (int nt=0;nt<NT;nt++){
      const uint2* wp = Wf + (((kt*NTOT + n8base + nt)*2)<<5) + lane;
      bh[nt] = wp[0];
      bl[nt] = wp[32];
    }
    unsigned ah[4], al[4];
    int ro = (rowbase + m_off)*LDA + kt*16 + k_off;
    ldsm4(sptr(&sh[ro]), ah[0],ah[1],ah[2],ah[3]);
    ldsm4(sptr(&sl[ro]), al[0],al[1],al[2],al[3]);
#pragma unroll
    for (int nt=0;nt<NT;nt++)
      mma3(c[nt], ah, al, bh[nt], bl[nt]);
  }
}

// --------------------------- single pack kernel ----------------------------
__global__ void k_packall(
    const float* __restrict__ encW1, const float* __restrict__ encW2,
    const float* __restrict__ gcnW,  const float* __restrict__ muW,
    const float* __restrict__ sigW,  const float* __restrict__ cmW1,
    const float* __restrict__ cmW2,  const float* __restrict__ decW1,
    const float* __restrict__ decW2, const float* __restrict__ giW,
    const float* __restrict__ ghW){
  int idx = blockIdx.x*256 + threadIdx.x;
  if (idx >= WF_TOT) return;
  const float* src; int K, N, trans, base, per, mst;
  if      (idx < WF_ENC2){ src=encW1; K=32; N=128; trans=0; base=WF_ENC1; per=2048; mst=4096; }
  else if (idx < WF_GCN ){ src=encW2; K=128;N=128; trans=0; base=WF_ENC2; per=8192; mst=16384;}
  else if (idx < WF_MU  ){ src=gcnW;  K=128;N=128; trans=0; base=WF_GCN;  per=8192; mst=16384;}
  else if (idx < WF_SIG ){ src=muW;   K=128;N=128; trans=0; base=WF_MU;   per=8192; mst=16384;}
  else if (idx < WF_CM1 ){ src=sigW;  K=128;N=128; trans=0; base=WF_SIG;  per=8192; mst=16384;}
  else if (idx < WF_CM2 ){ src=cmW1;  K=128;N=128; trans=0; base=WF_CM1;  per=8192; mst=16384;}
  else if (idx < WF_DEC1){ src=cmW2;  K=128;N=128; trans=0; base=WF_CM2;  per=8192; mst=16384;}
  else if (idx < WF_DEC2){ src=decW1; K=128;N=128; trans=0; base=WF_DEC1; per=8192; mst=16384;}
  else if (idx < WF_GI  ){ src=decW2; K=128;N=64;  trans=0; base=WF_DEC2; per=4096; mst=8192; }
  else if (idx < WF_GH  ){ src=giW;   K=128;N=128; trans=1; base=WF_GI;   per=8192; mst=16384;}
  else                   { src=ghW;   K=128;N=128; trans=1; base=WF_GH;   per=8192; mst=16384;}
  int rr = idx - base;
  int m = rr / per, r = rr % per;
  int lane = r & 31, term = (r>>5)&1;
  int n8 = (r>>6) % (N>>3);
  int kt = (r>>6) / (N>>3);
  int n = n8*8 + (lane>>2);
  int k0 = kt*16 + ((lane&3)<<1);
  const float* S = src + (long)m*mst;
  float w0,w1,w2,w3;
  if (trans){
    w0=S[n*K+k0]; w1=S[n*K+k0+1]; w2=S[n*K+k0+8]; w3=S[n*K+k0+9];
  } else {
    w0=S[k0*N+n]; w1=S[(k0+1)*N+n]; w2=S[(k0+8)*N+n]; w3=S[(k0+9)*N+n];
  }
  uint2 o;
  if (term==0){ o = make_uint2(pkh(w0,w1), pkh(w2,w3)); }
  else {
    o = make_uint2(pkh(w0-bf16f(w0), w1-bf16f(w1)),
                   pkh(w2-bf16f(w2), w3-bf16f(w3)));
  }
  g_Wf[idx] = o;
}

// ------------------------------ encoder ------------------------------------
__global__ __launch_bounds__(256,5) void k_enc(
    const float* __restrict__ x, const float* __restrict__ b1,
    const float* __restrict__ b2){
  __shared__ __align__(16) __nv_bfloat16 xh[32*40], xl[32*40];
  __shared__ __align__(16) __nv_bfloat16 hh[32*136], hl[32*136];
  int t = threadIdx.x, lane = t&31, warp = t>>5;
  int wrow = warp>>2, wcol = warp&3;
  int n = blockIdx.y;
  long b0 = (long)blockIdx.x*32;
  stage_split<32,32,40,256>(x + b0*160 + n*32, 160, xh, xl, t);
  __syncthreads();
  float c[4][4];
  hmma_row<2,4,16,40>(xh, xl, &g_Wf[WF_ENC1 + n*2048], wcol*4, wrow*16, lane, c);
  __syncthreads();
  {
    int r0 = wrow*16 + (lane>>2);
#pragma unroll
    for (int nt=0;nt<4;nt++){
      int col = (wcol*4+nt)*8 + ((lane&3)<<1);
      float2 bb = *(const float2*)&b1[n*128 + col];
      float v00=fmaxf(c[nt][0]+bb.x,0.f), v01=fmaxf(c[nt][1]+bb.y,0.f);
      float v10=fmaxf(c[nt][2]+bb.x,0.f), v11=fmaxf(c[nt][3]+bb.y,0.f);
      *(unsigned*)&hh[r0*136+col] = pkh(v00,v01);
      *(unsigned*)&hl[r0*136+col] = pkh(v00-bf16f(v00), v01-bf16f(v01));
      *(unsigned*)&hh[(r0+8)*136+col] = pkh(v10,v11);
      *(unsigned*)&hl[(r0+8)*136+col] = pkh(v10-bf16f(v10), v11-bf16f(v11));
    }
  }
  __syncthreads();
  hmma_row<8,4,16,136>(hh, hl, &g_Wf[WF_ENC2 + n*8192], wcol*4, wrow*16, lane, c);
  {
    long r0 = b0 + wrow*16 + (lane>>2);
#pragma unroll
    for (int nt=0;nt<4;nt++){
      int col = (wcol*4+nt)*8 + ((lane&3)<<1);
      float2 bb = *(const float2*)&b2[n*128 + col];
      *(float2*)&g_bufA[r0*640 + n*128 + col] =
          make_float2(c[nt][0]+bb.x, c[nt][1]+bb.y);
      *(float2*)&g_bufA[(r0+8)*640 + n*128 + col] =
          make_float2(c[nt][2]+bb.x, c[nt][3]+bb.y);
    }
  }
}

// ------------------- GCN layer 0: aggregation + GEMM -----------------------
__global__ __launch_bounds__(256,5) void k_gcn(
    const float* __restrict__ ew,
    const int* __restrict__ esrc, const int* __restrict__ edst,
    const float* __restrict__ bias){
  __shared__ __align__(16) __nv_bfloat16 sh[32*136], sl[32*136];
  __shared__ int s_src[NE], s_dst[NE];
  int t = threadIdx.x, lane = t&31, warp = t>>5;
  int wrow = warp>>2, wcol = warp&3;
  long b0 = (long)blockIdx.x*32;
  if (t < NE){ s_src[t] = esrc[t]; s_dst[t] = edst[t]; }
  __syncthreads();
  for (int f=t; f<32*32; f+=256){
    int r = f>>5, c4 = (f&31)<<2;
    long R = b0 + r;
    int b = (int)(R/5), v = (int)(R - 5l*b);
    const float* row = g_bufA + (long)b*640;
    float4 a = *(const float4*)&row[v*128 + c4];
#pragma unroll
    for (int e=0;e<NE;e++){
      if (s_dst[e] == v){
        float w = __ldg(&ew[b*NE + e]);
        float4 g = *(const float4*)&row[s_src[e]*128 + c4];
        a.x += w*g.x; a.y += w*g.y; a.z += w*g.z; a.w += w*g.w;
      }
    }
    split_st(a, sh, sl, r*136+c4);
  }
  __syncthreads();
  float c[4][4];
  hmma_row<8,4,16,136>(sh, sl, &g_Wf[WF_GCN], wcol*4, wrow*16, lane, c);
  {
    long r0 = b0 + wrow*16 + (lane>>2);
#pragma unroll
    for (int nt=0;nt<4;nt++){
      int col = (wcol*4+nt)*8 + ((lane&3)<<1);
      float2 bb = *(const float2*)&bias[col];
      *(float2*)&g_bufB[r0*128 + col] = make_float2(
          fmaxf(c[nt][0]+bb.x,0.f), fmaxf(c[nt][1]+bb.y,0.f));
      *(float2*)&g_bufB[(r0+8)*128 + col] = make_float2(
          fmaxf(c[nt][2]+bb.x,0.f), fmaxf(c[nt][3]+bb.y,0.f));
    }
  }
}

// ------- GCN layer 1 + mu/sig heads fused (agg + 3 GEMMs + KL) -------------
__global__ __launch_bounds__(256,5) void k_gcnms(
    const float* __restrict__ ew,
    const int* __restrict__ esrc, const int* __restrict__ edst,
    const float* __restrict__ bias,
    const float* __restrict__ mub, const float* __restrict__ sigb){
  __shared__ __align__(16) __nv_bfloat16 sh[32*136], sl[32*136];
  __shared__ int s_src[NE], s_dst[NE];
  int t = threadIdx.x, lane = t&31, warp = t>>5;
  int wrow = warp>>2, wcol = warp&3;
  long b0 = (long)blockIdx.x*32;
  if (t < NE){ s_src[t] = esrc[t]; s_dst[t] = edst[t]; }
  __syncthreads();
  // stage with aggregation (input = gcn layer-0 output in g_bufB)
  for (int f=t; f<32*32; f+=256){
    int r = f>>5, c4 = (f&31)<<2;
    long R = b0 + r;
    int b = (int)(R/5), v = (int)(R - 5l*b);
    const float* row = g_bufB + (long)b*640;
    float4 a = *(const float4*)&row[v*128 + c4];
#pragma unroll
    for (int e=0;e<NE;e++){
      if (s_dst[e] == v){
        float w = __ldg(&ew[b*NE + e]);
        float4 g = *(const float4*)&row[s_src[e]*128 + c4];
        a.x += w*g.x; a.y += w*g.y; a.z += w*g.z; a.w += w*g.w;
      }
    }
    split_st(a, sh, sl, r*136+c4);
  }
  __syncthreads();
  // GEMM: gcn layer 1 weights + ReLU, restage into sh/sl
  float c[4][4];
  hmma_row<8,4,16,136>(sh, sl, &g_Wf[WF_GCN + 8192], wcol*4, wrow*16, lane, c);
  __syncthreads();
  {
    int r0 = wrow*16 + (lane>>2);
#pragma unroll
    for (int nt=0;nt<4;nt++){
      int col = (wcol*4+nt)*8 + ((lane&3)<<1);
      float2 bb = *(const float2*)&bias[128 + col];
      float v00=fmaxf(c[nt][0]+bb.x,0.f), v01=fmaxf(c[nt][1]+bb.y,0.f);
      float v10=fmaxf(c[nt][2]+bb.x,0.f), v11=fmaxf(c[nt][3]+bb.y,0.f);
      *(unsigned*)&sh[r0*136+col] = pkh(v00,v01);
      *(unsigned*)&sl[r0*136+col] = pkh(v00-bf16f(v00), v01-bf16f(v01));
      *(unsigned*)&sh[(r0+8)*136+col] = pkh(v10,v11);
      *(unsigned*)&sl[(r0+8)*136+col] = pkh(v10-bf16f(v10), v11-bf16f(v11));
    }
  }
  __syncthreads();
  // mu head -> g_mean + m^2 KL
  float kll = 0.f;
  hmma_row<8,4,16,136>(sh, sl, &g_Wf[WF_MU], wcol*4, wrow*16, lane, c);
  {
    long r0 = b0 + wrow*16 + (lane>>2);
#pragma unroll
    for (int nt=0;nt<4;nt++){
      int col = (wcol*4+nt)*8 + ((lane&3)<<1);
      float2 bb = *(const float2*)&mub[col];
      float m00=c[nt][0]+bb.x, m01=c[nt][1]+bb.y;
      float m10=c[nt][2]+bb.x, m11=c[nt][3]+bb.y;
      *(float2*)&g_mean[r0*128 + col]     = make_float2(m00,m01);
      *(float2*)&g_mean[(r0+8)*128 + col] = make_float2(m10,m11);
      kll += m00*m00 + m01*m01 + m10*m10 + m11*m11;
    }
  }
  // sig head -> softplus KL
  hmma_row<8,4,16,136>(sh, sl, &g_Wf[WF_SIG], wcol*4, wrow*16, lane, c);
#pragma unroll
  for (int nt=0;nt<4;nt++){
    int col = (wcol*4+nt)*8 + ((lane&3)<<1);
    float2 bb = *(const float2*)&sigb[col];
#pragma unroll
    for (int i=0;i<4;i++){
      float sp = softplusf(c[nt][i] + ((i&1)?bb.y:bb.x));
      float var = sp*sp;
      kll += var - logf(var + 1e-8f) - 1.f;
    }
  }
  BLOCK_REDUCE8_TO(g_klpart, kll);
}

// ------------- GRU: fused dual-GEMM + gates (one kernel per layer) ---------
__global__ __launch_bounds__(256) void k_gru(
    int l, const float* __restrict__ xin, const float* __restrict__ hist,
    const float* __restrict__ bih, const float* __restrict__ bhh,
    float* __restrict__ hout){
  __shared__ __align__(16) __nv_bfloat16 xh[32*136], xl[32*136];
  __shared__ __align__(16) __nv_bfloat16 hhs[32*136], hls[32*136];
  int t = threadIdx.x, lane = t&31, warp = t>>5;   // 8 warps
  long b0 = (long)blockIdx.x*32;
  for (int f=t; f<32*32; f+=256){
    int r = f>>5, c4 = (f&31)<<2;
    long b = b0 + r;
    float4 v;
    if (xin){
      v = *(const float4*)&xin[b*128 + c4];
    } else {
      v = *(const float4*)&g_mean[b*640 + c4];
#pragma unroll
      for (int vv=1; vv<5; vv++){
        float4 m = *(const float4*)&g_mean[b*640 + vv*128 + c4];
        v.x+=m.x; v.y+=m.y; v.z+=m.z; v.w+=m.w;
      }
      v.x*=0.2f; v.y*=0.2f; v.z*=0.2f; v.w*=0.2f;
    }
    split_st(v, xh, xl, r*136+c4);
    float4 hv = *(const float4*)&hist[((long)l*BQ + b)*128 + c4];
    split_st(hv, hhs, hls, r*136+c4);
  }
  __syncthreads();
  float cr[2][2][4], cz[2][2][4], cin[2][2][4], chn[2][2][4];
#pragma unroll
  for (int mt=0;mt<2;mt++)
#pragma unroll
    for (int nt=0;nt<2;nt++)
#pragma unroll
      for (int i=0;i<4;i++){ cr[mt][nt][i]=0.f; cz[mt][nt][i]=0.f;
                             cin[mt][nt][i]=0.f; chn[mt][nt][i]=0.f; }
  int sub = lane>>3;
  int m_off = ((sub&1)<<3) + (lane&7);
  int k_off = (sub>>1)<<3;
  const uint2* Wi = &g_Wf[WF_GI + l*3*8192];
  const uint2* Wh = &g_Wf[WF_GH + l*3*8192];
#pragma unroll 1
  for (int kt=0; kt<8; kt++){
    unsigned axh[2][4], axl[2][4], ahh[2][4], ahl[2][4];
#pragma unroll
    for (int mt=0;mt<2;mt++){
      int ro = (mt*16 + m_off)*136 + kt*16 + k_off;
      ldsm4(sptr(&xh[ro]),  axh[mt][0],axh[mt][1],axh[mt][2],axh[mt][3]);
      ldsm4(sptr(&xl[ro]),  axl[mt][0],axl[mt][1],axl[mt][2],axl[mt][3]);
      ldsm4(sptr(&hhs[ro]), ahh[mt][0],ahh[mt][1],ahh[mt][2],ahh[mt][3]);
      ldsm4(sptr(&hls[ro]), ahl[mt][0],ahl[mt][1],ahl[mt][2],ahl[mt][3]);
    }
#pragma unroll
    for (int nt=0;nt<2;nt++){
      int fo = (((kt*16 + warp*2 + nt)*2)<<5) + lane;
      { uint2 bh=Wi[fo], bl=Wi[fo+32];
        uint2 ch=Wh[fo], cl=Wh[fo+32];
#pragma unroll
        for (int mt=0;mt<2;mt++){
          mma3(cr[mt][nt], axh[mt], axl[mt], bh, bl);
          mma3(cr[mt][nt], ahh[mt], ahl[mt], ch, cl);
        } }
      { uint2 bh=Wi[8192+fo], bl=Wi[8192+fo+32];
        uint2 ch=Wh[8192+fo], cl=Wh[8192+fo+32];
#pragma unroll
        for (int mt=0;mt<2;mt++){
          mma3(cz[mt][nt], axh[mt], axl[mt], bh, bl);
          mma3(cz[mt][nt], ahh[mt], ahl[mt], ch, cl);
        } }
      { uint2 bh=Wi[16384+fo], bl=Wi[16384+fo+32];
        uint2 ch=Wh[16384+fo], cl=Wh[16384+fo+32];
#pragma unroll
        for (int mt=0;mt<2;mt++){
          mma3(cin[mt][nt], axh[mt], axl[mt], bh, bl);
          mma3(chn[mt][nt], ahh[mt], ahl[mt], ch, cl);
        } }
    }
  }
#pragma unroll
  for (int mt=0;mt<2;mt++){
    long gb = b0 + mt*16 + (lane>>2);
#pragma unroll
    for (int nt=0;nt<2;nt++){
      int col = warp*16 + nt*8 + ((lane&3)<<1);
      float2 bir = *(const float2*)&bih[l*384 + col];
      float2 biz = *(const float2*)&bih[l*384 + 128 + col];
      float2 bin_= *(const float2*)&bih[l*384 + 256 + col];
      float2 bhr = *(const float2*)&bhh[l*384 + col];
      float2 bhz = *(const float2*)&bhh[l*384 + 128 + col];
      float2 bhn = *(const float2*)&bhh[l*384 + 256 + col];
      float2 hp0 = *(const float2*)&hist[((long)l*BQ + gb)*128 + col];
      float2 hp1 = *(const float2*)&hist[((long)l*BQ + gb + 8)*128 + col];
      float r0=sigmf(cr[mt][nt][0]+bir.x+bhr.x);
      float r1=sigmf(cr[mt][nt][1]+bir.y+bhr.y);
      float r2=sigmf(cr[mt][nt][2]+bir.x+bhr.x);
      float r3=sigmf(cr[mt][nt][3]+bir.y+bhr.y);
      float z0=sigmf(cz[mt][nt][0]+biz.x+bhz.x);
      float z1=sigmf(cz[mt][nt][1]+biz.y+bhz.y);
      float z2=sigmf(cz[mt][nt][2]+biz.x+bhz.x);
      float z3=sigmf(cz[mt][nt][3]+biz.y+bhz.y);
      float n0=tanhf(cin[mt][nt][0]+bin_.x + r0*(chn[mt][nt][0]+bhn.x));
      float n1=tanhf(cin[mt][nt][1]+bin_.y + r1*(chn[mt][nt][1]+bhn.y));
      float n2=tanhf(cin[mt][nt][2]+bin_.x + r2*(chn[mt][nt][2]+bhn.x));
      float n3=tanhf(cin[mt][nt][3]+bin_.y + r3*(chn[mt][nt][3]+bhn.y));
      *(float2*)&hout[gb*128 + col] =
          make_float2((1.f-z0)*n0 + z0*hp0.x, (1.f-z1)*n1 + z1*hp0.y);
      *(float2*)&hout[(gb+8)*128 + col] =
          make_float2((1.f-z2)*n2 + z2*hp1.x, (1.f-z3)*n3 + z3*hp1.y);
    }
  }
}

// --------------------- causal solve + parent_sum ---------------------------
__global__ __launch_bounds__(128) void k_causal(
    const float* __restrict__ ew, const float* __restrict__ cm,
    const int* __restrict__ esrc, const int* __restrict__ edst){
  int b = blockIdx.x, t = threadIdx.x;
  __shared__ float s_ew[NE], s_cm[NND*NND];
  __shared__ int s_src[NE], s_dst[NE];
  if (t < NE){ s_ew[t] = ew[b*NE + t]; s_src[t] = esrc[t]; s_dst[t] = edst[t]; }
  if (t < NND*NND) s_cm[t] = cm[t];
  __syncthreads();
  int base = b*NND*HDIM + t;
  float z[NND];
#pragma unroll
  for (int j=0;j<NND;j++) z[j] = g_mean[base + j*HDIM];
#pragma unroll
  for (int j=1;j<NND;j++){
    float add = 0.f;
#pragma unroll
    for (int e=0;e<NE;e++){
      if (s_dst[e] == j){
        int s = s_src[e];
        float zs = (s==0)?z[0]:((s==1)?z[1]:((s==2)?z[2]:z[3]));
        add += s_ew[e]*s_cm[s*NND + j]*zs;
      }
    }
    z[j] += add;
  }
#pragma unroll
  for (int j=0;j<NND;j++) g_z[base + j*HDIM] = z[j];
#pragma unroll
  for (int j=0;j<NND;j++){
    float ps = 0.f;
#pragma unroll
    for (int i=0;i<NND;i++)
      if (s_cm[i*NND + j] != 0.f) ps += z[i];
    g_ps[base + j*HDIM] = ps;
  }
}

// ------------------- cm MLP fused (2 GEMMs) + l_z --------------------------
__global__ __launch_bounds__(256,5) void k_cm(
    const float* __restrict__ b1, const float* __restrict__ b2){
  __shared__ __align__(16) __nv_bfloat16 sh[32*136], sl[32*136];
  int t = threadIdx.x, lane = t&31, warp = t>>5;
  int wrow = warp>>2, wcol = warp&3;
  long b0 = (long)blockIdx.x*32;
  stage_split<32,128,136,256>(g_ps + b0*128, 128, sh, sl, t);
  __syncthreads();
  float c[4][4];
  hmma_row<8,4,16,136>(sh, sl, &g_Wf[WF_CM1], wcol*4, wrow*16, lane, c);
  __syncthreads();
  {
    int r0 = wrow*16 + (lane>>2);
#pragma unroll
    for (int nt=0;nt<4;nt++){
      int col = (wcol*4+nt)*8 + ((lane&3)<<1);
      float2 bb = *(const float2*)&b1[col];
      float v00=mishf(c[nt][0]+bb.x), v01=mishf(c[nt][1]+bb.y);
      float v10=mishf(c[nt][2]+bb.x), v11=mishf(c[nt][3]+bb.y);
      *(unsigned*)&sh[r0*136+col] = pkh(v00,v01);
      *(unsigned*)&sl[r0*136+col] = pkh(v00-bf16f(v00), v01-bf16f(v01));
      *(unsigned*)&sh[(r0+8)*136+col] = pkh(v10,v11);
      *(unsigned*)&sl[(r0+8)*136+col] = pkh(v10-bf16f(v10), v11-bf16f(v11));
    }
  }
  __syncthreads();
  hmma_row<8,4,16,136>(sh, sl, &g_Wf[WF_CM2], wcol*4, wrow*16, lane, c);
  float lz = 0.f;
  {
    long r0 = b0 + wrow*16 + (lane>>2);
#pragma unroll
    for (int nt=0;nt<4;nt++){
      int col = (wcol*4+nt)*8 + ((lane&3)<<1);
      float2 bb = *(const float2*)&b2[col];
      float2 z0 = *(const float2*)&g_z[r0*128 + col];
      float2 z1 = *(const float2*)&g_z[(r0+8)*128 + col];
      float d0 = z0.x - (c[nt][0]+bb.x);
      float d1 = z0.y - (c[nt][1]+bb.y);
      float d2 = z1.x - (c[nt][2]+bb.x);
      float d3 = z1.y - (c[nt][3]+bb.y);
      lz += d0*d0 + d1*d1 + d2*d2 + d3*d3;
    }
  }
  BLOCK_REDUCE8_TO(g_lzpart, lz);
}

// ----------------- decoder fused (2 GEMMs) + losses ------------------------
__global__ __launch_bounds__(256,5) void k_dec(
    const float* __restrict__ b1, const float* __restrict__ b2,
    const float* __restrict__ yt_g, float* __restrict__ out){
  __shared__ __align__(16) __nv_bfloat16 sh[32*136], sl[32*136];
  __shared__ float s_piw[8][32], s_kd[8][32], s_mn[8][32], s_mx[8][32];
  __shared__ float s_sc[3][8];
  float* s_out = (float*)sh;     // 32*66 floats = 8448B <= 8704B ✓
  int t = threadIdx.x, lane = t&31, warp = t>>5;
  int wrow = warp>>2, wcol = warp&3;
  int n = blockIdx.y;
  long b0 = (long)blockIdx.x*32;
  stage_split<32,128,136,256>(g_z + b0*640 + n*128, 640, sh, sl, t);
  __syncthreads();
  float c[4][4];
  hmma_row<8,4,16,136>(sh, sl, &g_Wf[WF_DEC1 + n*8192], wcol*4, wrow*16, lane, c);
  __syncthreads();
  {
    int r0 = wrow*16 + (lane>>2);
#pragma unroll
    for (int nt=0;nt<4;nt++){
      int col = (wcol*4+nt)*8 + ((lane&3)<<1);
      float2 bb = *(const float2*)&b1[n*128 + col];
      float v00=mishf(c[nt][0]+bb.x), v01=mishf(c[nt][1]+bb.y);
      float v10=mishf(c[nt][2]+bb.x), v11=mishf(c[nt][3]+bb.y);
      *(unsigned*)&sh[r0*136+col] = pkh(v00,v01);
      *(unsigned*)&sl[r0*136+col] = pkh(v00-bf16f(v00), v01-bf16f(v01));
      *(unsigned*)&sh[(r0+8)*136+col] = pkh(v10,v11);
      *(unsigned*)&sl[(r0+8)*136+col] = pkh(v10-bf16f(v10), v11-bf16f(v11));
    }
  }
  __syncthreads();
  float c2[2][4];
  hmma_row<8,2,8,136>(sh, sl, &g_Wf[WF_DEC2 + n*4096], wcol*2, wrow*16, lane, c2);
  __syncthreads();   // all reads of sh done before aliasing as s_out
  {
    int r = wrow*16 + (lane>>2);
#pragma unroll
    for (int nt=0;nt<2;nt++){
      int col = (wcol*2+nt)*8 + ((lane&3)<<1);
      float2 bb = *(const float2*)&b2[n*64 + col];
      float v00=c2[nt][0]+bb.x, v01=c2[nt][1]+bb.y;
      float v10=c2[nt][2]+bb.x, v11=c2[nt][3]+bb.y;
      if (col >= 32){ v00=expf(v00); v01=expf(v01); v10=expf(v10); v11=expf(v11); }
      s_out[r*66+col]=v00;     s_out[r*66+col+1]=v01;
      s_out[(r+8)*66+col]=v10; s_out[(r+8)*66+col+1]=v11;
      long gb0, gb1;
      if (col < 32){
        gb0 = (b0+r)*160 + n*32 + col;
        gb1 = (b0+r+8)*160 + n*32 + col;
      } else {
        gb0 = (long)OFF_V + (b0+r)*160 + n*32 + col-32;
        gb1 = (long)OFF_V + (b0+r+8)*160 + n*32 + col-32;
      }
      *(float2*)&out[gb0] = make_float2(v00,v01);
      *(float2*)&out[gb1] = make_float2(v10,v11);
    }
  }
  __syncthreads();
  int d = lane;
  float ll=0.f, sq4=0.f, bce=0.f;
  float piw=0.f, kd=0.f, mn=1e30f, mx=-1e30f;
#pragma unroll
  for (int i=0;i<4;i++){
    int row = warp + 8*i;
    float ym = s_out[row*66 + d];
    float yv = s_out[row*66 + 32 + d];
    float yt = yt_g[(b0+row)*160 + n*32 + d];
    float vs = yv + 1e-6f;
    float df = yt - ym;
    ll += -0.5f*(df*df/vs + logf(6.2831853071795864f*vs));
    if (n < 4) sq4 += df*df;
    if (n == 4) bce += fmaxf(ym,0.f) - ym*yt + log1pf(expf(-fabsf(ym)));
    float s  = sqrtf(vs);
    float lo_ = ym - ZALPHA*s, up_ = ym + ZALPHA*s;
    float kf = (yt >= lo_ && yt <= up_) ? 1.f : 0.f;
    kd  += kf;
    piw += (up_-lo_)*kf;
    mn = fminf(mn, yt);
    mx = fmaxf(mx, yt);
  }
  ll  = warp_sum(ll);
  sq4 = warp_sum(sq4);
  bce = warp_sum(bce);
  if (lane == 0){ s_sc[0][warp]=ll; s_sc[1][warp]=sq4; s_sc[2][warp]=bce; }
  s_piw[warp][d]=piw; s_kd[warp][d]=kd; s_mn[warp][d]=mn; s_mx[warp][d]=mx;
  __syncthreads();
  int blk = blockIdx.y*gridDim.x + blockIdx.x;
  float* P = g_losspart + blk*132;
  if (t == 0){
    P[0] = ((s_sc[0][0]+s_sc[0][1]) + (s_sc[0][2]+s_sc[0][3]))
         + ((s_sc[0][4]+s_sc[0][5]) + (s_sc[0][6]+s_sc[0][7]));
    P[1] = ((s_sc[1][0]+s_sc[1][1]) + (s_sc[1][2]+s_sc[1][3]))
         + ((s_sc[1][4]+s_sc[1][5]) + (s_sc[1][6]+s_sc[1][7]));
    P[2] = ((s_sc[2][0]+s_sc[2][1]) + (s_sc[2][2]+s_sc[2][3]))
         + ((s_sc[2][4]+s_sc[2][5]) + (s_sc[2][6]+s_sc[2][7]));
    P[3] = 0.f;
  }
  if (t < 32){
    float p=0.f, k=0.f, m=1e30f, xx=-1e30f;
#pragma unroll
    for (int g=0; g<8; g++){
      p += s_piw[g][t]; k += s_kd[g][t];
      m = fminf(m, s_mn[g][t]); xx = fmaxf(xx, s_mx[g][t]);
    }
    P[4+t] = p; P[36+t] = k; P[68+t] = m; P[100+t] = xx;
  }
}

// ---------------------- stage-1 reduce + final -----------------------------
__global__ void k_reduce1(){
  int col = blockIdx.x, t = threadIdx.x;
  bool ismin = (col >= 68 && col < 100);
  bool ismax = (col >= 100 && col < 132);
  float v = ismin ? 1e30f : (ismax ? -1e30f : 0.f);
  if (col < 132){
    for (int i=t; i<5120; i+=256){
      float x = g_losspart[i*132 + col];
      v = ismin ? fminf(v,x) : (ismax ? fmaxf(v,x) : v + x);
    }
  } else if (col == 132){
    for (int i=t; i<5120; i+=256) v += g_klpart[i];
  } else {
    for (int i=t; i<5120; i+=256) v += g_lzpart[i];
  }
  __shared__ float sm[256];
  sm[t] = v;
  __syncthreads();
  for (int s=128; s>0; s>>=1){
    if (t < s){
      float a = sm[t], b = sm[t+s];
      sm[t] = ismin ? fminf(a,b) : (ismax ? fmaxf(a,b) : a + b);
    }
    __syncthreads();
  }
  if (t == 0) g_facc[col] = sm[0];
}

__global__ void k_final(float* __restrict__ out){
  if (threadIdx.x != 0 || blockIdx.x != 0) return;
  float S_ll = g_facc[0], S_sq4 = g_facc[1], S_bce = g_facc[2];
  float kl = 0.5f*g_facc[132];
  float S_lz = g_facc[133];
  float mean_ll = S_ll / 5242880.0f;
  float elbo = kl/32768.0f - mean_ll;
  float l_reg = (S_sq4/32.0f) / (4.0f*32768.0f + 1e-6f);
  float l_cls = (S_bce/32.0f) / (32768.0f + 1e-6f);
  float l_rec = l_reg + l_cls;
  float Sk = 0.f, pin = 0.f;
  for (int d=0; d<32; d++){
    float kdv = g_facc[36+d];
    Sk += kdv;
    pin += g_facc[4+d] / (kdv + 1e-6f) / (g_facc[100+d] - g_facc[68+d] + 1e-6f);
  }
  float picp  = Sk / 5242880.0f;
  float pinaw = pin / 32.0f;
  float l_pi  = pinaw - sqrtf(5.0f)*picp;
  float l_z   = S_lz / 20971520.0f;
  float dag   = 0.0f;  // exact: diag((I+ac)^5)==1 for strictly-upper ac
  float total = powf(elbo*l_rec*l_pi*l_z*(dag + 1e-6f), 0.2f);
  out[OFF_LOSS+0] = total;
  out[OFF_LOSS+1] = elbo;
  out[OFF_LOSS+2] = l_rec;
  out[OFF_LOSS+3] = l_pi;
  out[OFF_LOSS+4] = l_z;
  out[OFF_LOSS+5] = dag;
}

// ------------------------------ launcher -----------------------------------
extern "C" void kernel_launch(void* const* d_in, const int* in_sizes, int n_in,
                              void* d_out, int out_size){
  const float* x       = (const float*)d_in[0];
  const float* y_true  = (const float*)d_in[1];
  const float* ew      = (const float*)d_in[2];
  const float* hist    = (const float*)d_in[3];
  const float* enc_W1  = (const float*)d_in[4];
  const float* enc_b1  = (const float*)d_in[5];
  const float* enc_W2  = (const float*)d_in[6];
  const float* enc_b2  = (const float*)d_in[7];
  const float* gcn_W   = (const float*)d_in[8];
  const float* gcn_b   = (const float*)d_in[9];
  const float* mu_W    = (const float*)d_in[10];
  const float* mu_b    = (const float*)d_in[11];
  const float* sig_W   = (const float*)d_in[12];
  const float* sig_b   = (const float*)d_in[13];
  const float* gru_Wih = (const float*)d_in[14];
  const float* gru_Whh = (const float*)d_in[15];
  const float* gru_bih = (const float*)d_in[16];
  const float* gru_bhh = (const float*)d_in[17];
  const float* cm      = (const float*)d_in[18];
  const float* cm_W1   = (const float*)d_in[19];
  const float* cm_b1   = (const float*)d_in[20];
  const float* cm_W2   = (const float*)d_in[21];
  const float* cm_b2   = (const float*)d_in[22];
  const float* dec_W1  = (const float*)d_in[23];
  const float* dec_b1  = (const float*)d_in[24];
  const float* dec_W2  = (const float*)d_in[25];
  const float* dec_b2  = (const float*)d_in[26];
  const int*   esrc    = (const int*)d_in[27];
  const int*   edst    = (const int*)d_in[28];
  float* out = (float*)d_out;

  static cudaStream_t s2 = 0, s3 = 0;
  static cudaEvent_t evFork = 0, evJoin = 0, evC = 0, evJoin3 = 0;
  if (!s2){
    cudaStreamCreateWithFlags(&s2, cudaStreamNonBlocking);
    cudaStreamCreateWithFlags(&s3, cudaStreamNonBlocking);
    cudaEventCreateWithFlags(&evFork, cudaEventDisableTiming);
    cudaEventCreateWithFlags(&evJoin, cudaEventDisableTiming);
    cudaEventCreateWithFlags(&evC, cudaEventDisableTiming);
    cudaEventCreateWithFlags(&evJoin3, cudaEventDisableTiming);
  }

  k_packall<<<(WF_TOT+255)/256, 256>>>(enc_W1, enc_W2, gcn_W, mu_W, sig_W,
                                       cm_W1, cm_W2, dec_W1, dec_W2,
                                       gru_Wih, gru_Whh);
  k_enc<<<dim3(BQ/32, NND), 256>>>(x, enc_b1, enc_b2);
  k_gcn<<<5120, 256>>>(ew, esrc, edst, gcn_b);
  k_gcnms<<<5120, 256>>>(ew, esrc, edst, gcn_b, mu_b, sig_b);

  // fork A: GRU chain on s2
  cudaEventRecord(evFork, 0);
  cudaStreamWaitEvent(s2, evFork, 0);
  k_gru<<<BQ/32, 256, 0, s2>>>(0, nullptr, hist, gru_bih, gru_bhh,
                               out + OFF_HID);
  k_gru<<<BQ/32, 256, 0, s2>>>(1, out + OFF_HID, hist, gru_bih, gru_bhh,
                               out + OFF_HID + BQ*HDIM);
  cudaEventRecord(evJoin, s2);

  // main: causal, then fork B: cm on s3 parallel with dec on default
  k_causal<<<BQ, 128>>>(ew, cm, esrc, edst);
  cudaEventRecord(evC, 0);
  cudaStreamWaitEvent(s3, evC, 0);
  k_cm<<<5120, 256, 0, s3>>>(cm_b1, cm_b2);
  cudaEventRecord(evJoin3, s3);

  k_dec<<<dim3(BQ/32, NND), 256>>>(dec_b1, dec_b2, y_true, out);

  // join both branches before final reductions
  cudaStreamWaitEvent(0, evJoin, 0);
  cudaStreamWaitEvent(0, evJoin3, 0);
  k_reduce1<<<134, 256>>>();
  k_final<<<1, 32>>>(out);
}

// round 14
// speedup vs baseline: 1.3049x; 1.1037x over previous
#include <cuda_runtime.h>
#include <cuda_bf16.h>
#include <math.h>

#define BQ   32768
#define NND  5
#define HDIM 128
#define NE   10
#define GMSG 5462            /* ceil(163840/30) batch-aligned gcnms grid */

#define OFF_V    (BQ*NND*32)
#define OFF_HID  (2*BQ*NND*32)
#define OFF_LOSS (OFF_HID + 2*BQ*HDIM)

#define ZALPHA 1.959963984540054f

// fragment arena offsets (uint2 units)
#define WF_ENC1 0
#define WF_ENC2 10240
#define WF_GCN  51200
#define WF_MU   67584
#define WF_SIG  75776
#define WF_CM1  83968
#define WF_CM2  92160
#define WF_DEC1 100352
#define WF_DEC2 141312
#define WF_GI   161792
#define WF_GH   210944
#define WF_TOT  260096

// ----------------------------- device scratch -----------------------------
__device__ float g_bufA[BQ*NND*HDIM];
__device__ float g_bufB[BQ*NND*HDIM];
__device__ float g_z  [BQ*NND*HDIM];
__device__ float g_ps [BQ*NND*HDIM];
__device__ float g_gf [BQ*HDIM];
__device__ uint2 g_Wf [WF_TOT];
__device__ float g_klpart[5504];
__device__ float g_lzpart[5120];
__device__ float g_losspart[5120*132];
__device__ float g_facc[134];

// ------------------------------- helpers ----------------------------------
__device__ __forceinline__ float warp_sum(float v){
#pragma unroll
  for (int o=16;o>0;o>>=1) v += __shfl_xor_sync(0xffffffffu, v, o);
  return v;
}
__device__ __forceinline__ float softplusf(float x){
  return fmaxf(x,0.f) + log1pf(expf(-fabsf(x)));
}
__device__ __forceinline__ float mishf(float x){ return x*tanhf(softplusf(x)); }
__device__ __forceinline__ float sigmf(float x){ return 1.f/(1.f+expf(-x)); }

#define BLOCK_REDUCE8_TO(part, val)                                     \
  do {                                                                  \
    float _v = warp_sum(val);                                           \
    __shared__ float _sred[8];                                          \
    if ((threadIdx.x & 31) == 0) _sred[threadIdx.x >> 5] = _v;          \
    __syncthreads();                                                    \
    if (threadIdx.x == 0)                                               \
      part[blockIdx.x] = ((_sred[0]+_sred[1]) + (_sred[2]+_sred[3]))    \
                       + ((_sred[4]+_sred[5]) + (_sred[6]+_sred[7]));   \
  } while (0)

__device__ __forceinline__ unsigned pkh(float x, float y){
  unsigned short a = __bfloat16_as_ushort(__float2bfloat16_rn(x));
  unsigned short b = __bfloat16_as_ushort(__float2bfloat16_rn(y));
  return ((unsigned)b<<16) | (unsigned)a;
}
__device__ __forceinline__ float bf16f(float x){
  return __bfloat162float(__float2bfloat16_rn(x));
}
__device__ __forceinline__ unsigned sptr(const void* p){
  return (unsigned)__cvta_generic_to_shared(p);
}
__device__ __forceinline__ void ldsm4(unsigned a, unsigned &r0, unsigned &r1,
                                      unsigned &r2, unsigned &r3){
  asm volatile("ldmatrix.sync.aligned.m8n8.x4.shared.b16 {%0,%1,%2,%3}, [%4];"
               : "=r"(r0),"=r"(r1),"=r"(r2),"=r"(r3) : "r"(a));
}
__device__ __forceinline__ void mma16816(float* c, const unsigned* a,
                                         unsigned b0, unsigned b1){
  asm volatile("mma.sync.aligned.m16n8k16.row.col.f32.bf16.bf16.f32 "
      "{%0,%1,%2,%3},{%4,%5,%6,%7},{%8,%9},{%0,%1,%2,%3};"
      : "+f"(c[0]),"+f"(c[1]),"+f"(c[2]),"+f"(c[3])
      : "r"(a[0]),"r"(a[1]),"r"(a[2]),"r"(a[3]),"r"(b0),"r"(b1));
}
__device__ __forceinline__ void mma3(float* c, const unsigned* ah,
    const unsigned* al, uint2 bh, uint2 bl){
  mma16816(c, ah, bh.x, bh.y);
  mma16816(c, al, bh.x, bh.y);
  mma16816(c, ah, bl.x, bl.y);
}

__device__ __forceinline__ void split_st(float4 v, __nv_bfloat16* sh,
    __nv_bfloat16* sl, int off){
  *(uint2*)&sh[off] = make_uint2(pkh(v.x,v.y), pkh(v.z,v.w));
  *(uint2*)&sl[off] = make_uint2(pkh(v.x-bf16f(v.x), v.y-bf16f(v.y)),
                                 pkh(v.z-bf16f(v.z), v.w-bf16f(v.w)));
}

template<int ROWS, int KC, int LDA, int NT_>
__device__ __forceinline__ void stage_split(const float* __restrict__ A, int arst,
    __nv_bfloat16* sh, __nv_bfloat16* sl, int t){
  const int C4 = KC/4;
  for (int f=t; f<ROWS*C4; f+=NT_){
    int r = f/C4, c4 = (f%C4)*4;
    float4 v = *(const float4*)&A[(long)r*arst + c4];
    split_st(v, sh, sl, r*LDA+c4);
  }
}

// 3-term bf16 split mainloop, 1 m16-tile per warp, NT n8-tiles
template<int KT, int NT, int NTOT, int LDA>
__device__ __forceinline__ void hmma_row(const __nv_bfloat16* sh,
    const __nv_bfloat16* sl, const uint2* __restrict__ Wf,
    int n8base, int rowbase, int lane, float (&c)[NT][4]){
#pragma unroll
  for (int nt=0;nt<NT;nt++)
#pragma unroll
    for (int i=0;i<4;i++) c[nt][i] = 0.f;
  int sub = lane>>3;
  int m_off = ((sub&1)<<3) + (lane&7);
  int k_off = (sub>>1)<<3;
#pragma unroll 1
  for (int kt=0; kt<KT; kt++){
    uint2 bh[NT], bl[NT];
#pragma unroll
    for (int nt=0;nt<NT;nt++){
      const uint2* wp = Wf + (((kt*NTOT + n8base + nt)*2)<<5) + lane;
      bh[nt] = wp[0];
      bl[nt] = wp[32];
    }
    unsigned ah[4], al[4];
    int ro = (rowbase + m_off)*LDA + kt*16 + k_off;
    ldsm4(sptr(&sh[ro]), ah[0],ah[1],ah[2],ah[3]);
    ldsm4(sptr(&sl[ro]), al[0],al[1],al[2],al[3]);
#pragma unroll
    for (int nt=0;nt<NT;nt++)
      mma3(c[nt], ah, al, bh[nt], bl[nt]);
  }
}

// --------------------------- single pack kernel ----------------------------
__global__ void k_packall(
    const float* __restrict__ encW1, const float* __restrict__ encW2,
    const float* __restrict__ gcnW,  const float* __restrict__ muW,
    const float* __restrict__ sigW,  const float* __restrict__ cmW1,
    const float* __restrict__ cmW2,  const float* __restrict__ decW1,
    const float* __restrict__ decW2, const float* __restrict__ giW,
    const float* __restrict__ ghW){
  int idx = blockIdx.x*256 + threadIdx.x;
  if (idx >= WF_TOT) return;
  const float* src; int K, N, trans, base, per, mst;
  if      (idx < WF_ENC2){ src=encW1; K=32; N=128; trans=0; base=WF_ENC1; per=2048; mst=4096; }
  else if (idx < WF_GCN ){ src=encW2; K=128;N=128; trans=0; base=WF_ENC2; per=8192; mst=16384;}
  else if (idx < WF_MU  ){ src=gcnW;  K=128;N=128; trans=0; base=WF_GCN;  per=8192; mst=16384;}
  else if (idx < WF_SIG ){ src=muW;   K=128;N=128; trans=0; base=WF_MU;   per=8192; mst=16384;}
  else if (idx < WF_CM1 ){ src=sigW;  K=128;N=128; trans=0; base=WF_SIG;  per=8192; mst=16384;}
  else if (idx < WF_CM2 ){ src=cmW1;  K=128;N=128; trans=0; base=WF_CM1;  per=8192; mst=16384;}
  else if (idx < WF_DEC1){ src=cmW2;  K=128;N=128; trans=0; base=WF_CM2;  per=8192; mst=16384;}
  else if (idx < WF_DEC2){ src=decW1; K=128;N=128; trans=0; base=WF_DEC1; per=8192; mst=16384;}
  else if (idx < WF_GI  ){ src=decW2; K=128;N=64;  trans=0; base=WF_DEC2; per=4096; mst=8192; }
  else if (idx < WF_GH  ){ src=giW;   K=128;N=128; trans=1; base=WF_GI;   per=8192; mst=16384;}
  else                   { src=ghW;   K=128;N=128; trans=1; base=WF_GH;   per=8192; mst=16384;}
  int rr = idx - base;
  int m = rr / per, r = rr % per;
  int lane = r & 31, term = (r>>5)&1;
  int n8 = (r>>6) % (N>>3);
  int kt = (r>>6) / (N>>3);
  int n = n8*8 + (lane>>2);
  int k0 = kt*16 + ((lane&3)<<1);
  const float* S = src + (long)m*mst;
  float w0,w1,w2,w3;
  if (trans){
    w0=S[n*K+k0]; w1=S[n*K+k0+1]; w2=S[n*K+k0+8]; w3=S[n*K+k0+9];
  } else {
    w0=S[k0*N+n]; w1=S[(k0+1)*N+n]; w2=S[(k0+8)*N+n]; w3=S[(k0+9)*N+n];
  }
  uint2 o;
  if (term==0){ o = make_uint2(pkh(w0,w1), pkh(w2,w3)); }
  else {
    o = make_uint2(pkh(w0-bf16f(w0), w1-bf16f(w1)),
                   pkh(w2-bf16f(w2), w3-bf16f(w3)));
  }
  g_Wf[idx] = o;
}

// ------------------------------ encoder ------------------------------------
__global__ __launch_bounds__(256,5) void k_enc(
    const float* __restrict__ x, const float* __restrict__ b1,
    const float* __restrict__ b2){
  __shared__ __align__(16) __nv_bfloat16 xh[32*40], xl[32*40];
  __shared__ __align__(16) __nv_bfloat16 hh[32*136], hl[32*136];
  int t = threadIdx.x, lane = t&31, warp = t>>5;
  int wrow = warp>>2, wcol = warp&3;
  int n = blockIdx.y;
  long b0 = (long)blockIdx.x*32;
  stage_split<32,32,40,256>(x + b0*160 + n*32, 160, xh, xl, t);
  __syncthreads();
  float c[4][4];
  hmma_row<2,4,16,40>(xh, xl, &g_Wf[WF_ENC1 + n*2048], wcol*4, wrow*16, lane, c);
  __syncthreads();
  {
    int r0 = wrow*16 + (lane>>2);
#pragma unroll
    for (int nt=0;nt<4;nt++){
      int col = (wcol*4+nt)*8 + ((lane&3)<<1);
      float2 bb = *(const float2*)&b1[n*128 + col];
      float v00=fmaxf(c[nt][0]+bb.x,0.f), v01=fmaxf(c[nt][1]+bb.y,0.f);
      float v10=fmaxf(c[nt][2]+bb.x,0.f), v11=fmaxf(c[nt][3]+bb.y,0.f);
      *(unsigned*)&hh[r0*136+col] = pkh(v00,v01);
      *(unsigned*)&hl[r0*136+col] = pkh(v00-bf16f(v00), v01-bf16f(v01));
      *(unsigned*)&hh[(r0+8)*136+col] = pkh(v10,v11);
      *(unsigned*)&hl[(r0+8)*136+col] = pkh(v10-bf16f(v10), v11-bf16f(v11));
    }
  }
  __syncthreads();
  hmma_row<8,4,16,136>(hh, hl, &g_Wf[WF_ENC2 + n*8192], wcol*4, wrow*16, lane, c);
  {
    long r0 = b0 + wrow*16 + (lane>>2);
#pragma unroll
    for (int nt=0;nt<4;nt++){
      int col = (wcol*4+nt)*8 + ((lane&3)<<1);
      float2 bb = *(const float2*)&b2[n*128 + col];
      *(float2*)&g_bufA[r0*640 + n*128 + col] =
          make_float2(c[nt][0]+bb.x, c[nt][1]+bb.y);
      *(float2*)&g_bufA[(r0+8)*640 + n*128 + col] =
          make_float2(c[nt][2]+bb.x, c[nt][3]+bb.y);
    }
  }
}

// ------------------- GCN layer 0: aggregation + GEMM -----------------------
__global__ __launch_bounds__(256,5) void k_gcn(
    const float* __restrict__ ew,
    const int* __restrict__ esrc, const int* __restrict__ edst,
    const float* __restrict__ bias){
  __shared__ __align__(16) __nv_bfloat16 sh[32*136], sl[32*136];
  __shared__ int s_src[NE], s_dst[NE];
  int t = threadIdx.x, lane = t&31, warp = t>>5;
  int wrow = warp>>2, wcol = warp&3;
  long b0 = (long)blockIdx.x*32;
  if (t < NE){ s_src[t] = esrc[t]; s_dst[t] = edst[t]; }
  __syncthreads();
  for (int f=t; f<32*32; f+=256){
    int r = f>>5, c4 = (f&31)<<2;
    long R = b0 + r;
    int b = (int)(R/5), v = (int)(R - 5l*b);
    const float* row = g_bufA + (long)b*640;
    float4 a = *(const float4*)&row[v*128 + c4];
#pragma unroll
    for (int e=0;e<NE;e++){
      if (s_dst[e] == v){
        float w = __ldg(&ew[b*NE + e]);
        float4 g = *(const float4*)&row[s_src[e]*128 + c4];
        a.x += w*g.x; a.y += w*g.y; a.z += w*g.z; a.w += w*g.w;
      }
    }
    split_st(a, sh, sl, r*136+c4);
  }
  __syncthreads();
  float c[4][4];
  hmma_row<8,4,16,136>(sh, sl, &g_Wf[WF_GCN], wcol*4, wrow*16, lane, c);
  {
    long r0 = b0 + wrow*16 + (lane>>2);
#pragma unroll
    for (int nt=0;nt<4;nt++){
      int col = (wcol*4+nt)*8 + ((lane&3)<<1);
      float2 bb = *(const float2*)&bias[col];
      *(float2*)&g_bufB[r0*128 + col] = make_float2(
          fmaxf(c[nt][0]+bb.x,0.f), fmaxf(c[nt][1]+bb.y,0.f));
      *(float2*)&g_bufB[(r0+8)*128 + col] = make_float2(
          fmaxf(c[nt][2]+bb.x,0.f), fmaxf(c[nt][3]+bb.y,0.f));
    }
  }
}

// -- GCN layer1 + mu/sig + KL + causal solve + parent_sum + graph_feat ------
// batch-aligned: 30 rows (6 batches) per CTA, rows 30-31 padded.
__global__ __launch_bounds__(256,5) void k_gcnms(
    const float* __restrict__ ew,
    const int* __restrict__ esrc, const int* __restrict__ edst,
    const float* __restrict__ bias,
    const float* __restrict__ mub, const float* __restrict__ sigb,
    const float* __restrict__ cmw){
  __shared__ __align__(16) __nv_bfloat16 sh[32*136], sl[32*136];
  __shared__ float mf[32*132];
  __shared__ float s_cm[25], s_ew[60];
  __shared__ int s_src[NE], s_dst[NE];
  int t = threadIdx.x, lane = t&31, warp = t>>5;
  int wrow = warp>>2, wcol = warp&3;
  long b0 = (long)blockIdx.x*30;
  if (t < NE){ s_src[t] = esrc[t]; s_dst[t] = edst[t]; }
  if (t < 25) s_cm[t] = cmw[t];
  if (t >= 32 && t < 92){
    int q = t - 32;
    int bb = q/10, e = q%10;
    long Bg = (long)blockIdx.x*6 + bb;
    s_ew[q] = (Bg < 32768L) ? __ldg(&ew[Bg*NE + e]) : 0.f;
  }
  __syncthreads();
  // stage with aggregation (input = gcn layer-0 output in g_bufB)
  for (int f=t; f<32*32; f+=256){
    int r = f>>5, c4 = (f&31)<<2;
    long R = b0 + r;
    float4 a = make_float4(0.f,0.f,0.f,0.f);
    if (r < 30 && R < 163840L){
      int bb = r/5, v = r - 5*bb;
      int b = (int)(R/5);
      const float* row = g_bufB + (long)b*640;
      a = *(const float4*)&row[v*128 + c4];
#pragma unroll
      for (int e=0;e<NE;e++){
        if (s_dst[e] == v){
          float w = s_ew[bb*10 + e];
          float4 g = *(const float4*)&row[s_src[e]*128 + c4];
          a.x += w*g.x; a.y += w*g.y; a.z += w*g.z; a.w += w*g.w;
        }
      }
    }
    split_st(a, sh, sl, r*136+c4);
  }
  __syncthreads();
  // GEMM gcn layer 1 + ReLU, restage
  float c[4][4];
  hmma_row<8,4,16,136>(sh, sl, &g_Wf[WF_GCN + 8192], wcol*4, wrow*16, lane, c);
  __syncthreads();
  {
    int r0 = wrow*16 + (lane>>2);
#pragma unroll
    for (int nt=0;nt<4;nt++){
      int col = (wcol*4+nt)*8 + ((lane&3)<<1);
      float2 bb = *(const float2*)&bias[128 + col];
      float v00=fmaxf(c[nt][0]+bb.x,0.f), v01=fmaxf(c[nt][1]+bb.y,0.f);
      float v10=fmaxf(c[nt][2]+bb.x,0.f), v11=fmaxf(c[nt][3]+bb.y,0.f);
      *(unsigned*)&sh[r0*136+col] = pkh(v00,v01);
      *(unsigned*)&sl[r0*136+col] = pkh(v00-bf16f(v00), v01-bf16f(v01));
      *(unsigned*)&sh[(r0+8)*136+col] = pkh(v10,v11);
      *(unsigned*)&sl[(r0+8)*136+col] = pkh(v10-bf16f(v10), v11-bf16f(v11));
    }
  }
  __syncthreads();
  // mu head -> mf (smem) + masked m^2 KL
  float kll = 0.f;
  int r0m = wrow*16 + (lane>>2);
  bool v0 = (b0 + r0m) < 163840L;                       // r0m <= 23 < 30
  bool v1 = ((r0m+8) < 30) && ((b0 + r0m + 8) < 163840L);
  hmma_row<8,4,16,136>(sh, sl, &g_Wf[WF_MU], wcol*4, wrow*16, lane, c);
#pragma unroll
  for (int nt=0;nt<4;nt++){
    int col = (wcol*4+nt)*8 + ((lane&3)<<1);
    float2 bb = *(const float2*)&mub[col];
    float m00=c[nt][0]+bb.x, m01=c[nt][1]+bb.y;
    float m10=c[nt][2]+bb.x, m11=c[nt][3]+bb.y;
    mf[r0m*132 + col]     = m00;  mf[r0m*132 + col + 1]     = m01;
    mf[(r0m+8)*132 + col] = m10;  mf[(r0m+8)*132 + col + 1] = m11;
    if (v0) kll += m00*m00 + m01*m01;
    if (v1) kll += m10*m10 + m11*m11;
  }
  // sig head -> masked softplus KL (sh/sl still hold activations)
  hmma_row<8,4,16,136>(sh, sl, &g_Wf[WF_SIG], wcol*4, wrow*16, lane, c);
#pragma unroll
  for (int nt=0;nt<4;nt++){
    int col = (wcol*4+nt)*8 + ((lane&3)<<1);
    float2 bb = *(const float2*)&sigb[col];
    if (v0){
      float sp0 = softplusf(c[nt][0]+bb.x), sp1 = softplusf(c[nt][1]+bb.y);
      float va0 = sp0*sp0, va1 = sp1*sp1;
      kll += va0 - logf(va0 + 1e-8f) - 1.f;
      kll += va1 - logf(va1 + 1e-8f) - 1.f;
    }
    if (v1){
      float sp2 = softplusf(c[nt][2]+bb.x), sp3 = softplusf(c[nt][3]+bb.y);
      float va2 = sp2*sp2, va3 = sp3*sp3;
      kll += va2 - logf(va2 + 1e-8f) - 1.f;
      kll += va3 - logf(va3 + 1e-8f) - 1.f;
    }
  }
  __syncthreads();   // mf fully written
  // causal solve + parent_sum + graph_feat (scalar per (batch, col))
  for (int f=t; f<768; f+=256){
    int bb = f>>7, cc = f&127;
    long Bg = (long)blockIdx.x*6 + bb;
    if (Bg < 32768L){
      int lr = bb*5;
      float z0 = mf[lr*132+cc],     z1 = mf[(lr+1)*132+cc];
      float z2 = mf[(lr+2)*132+cc], z3 = mf[(lr+3)*132+cc];
      float z4 = mf[(lr+4)*132+cc];
      // graph_feat from node_mean (pre-solve), same order as old k_gru path
      float gf = z0; gf += z1; gf += z2; gf += z3; gf += z4;
      g_gf[Bg*128 + cc] = gf*0.2f;
      // forward substitution (identical order to old k_causal)
#pragma unroll
      for (int j=1;j<NND;j++){
        float add = 0.f;
#pragma unroll
        for (int e=0;e<NE;e++){
          if (s_dst[e] == j){
            int s = s_src[e];
            float zs = (s==0)?z0:((s==1)?z1:((s==2)?z2:z3));
            add += s_ew[bb*10+e]*s_cm[s*NND + j]*zs;
          }
        }
        if (j==1) z1 += add; else if (j==2) z2 += add;
        else if (j==3) z3 += add; else z4 += add;
      }
      long gb = Bg*5*128 + cc;
      g_z[gb]       = z0; g_z[gb+128]   = z1; g_z[gb+256] = z2;
      g_z[gb+384]   = z3; g_z[gb+512]   = z4;
#pragma unroll
      for (int j=0;j<NND;j++){
        float ps = 0.f;
#pragma unroll
        for (int i=0;i<NND;i++){
          if (s_cm[i*NND + j] != 0.f)
            ps += (i==0)?z0:((i==1)?z1:((i==2)?z2:((i==3)?z3:z4)));
        }
        g_ps[gb + j*128] = ps;
      }
    }
  }
  BLOCK_REDUCE8_TO(g_klpart, kll);
}

// ------------- GRU: fused dual-GEMM + gates (one kernel per layer) ---------
__global__ __launch_bounds__(256) void k_gru(
    int l, const float* __restrict__ xin, const float* __restrict__ hist,
    const float* __restrict__ bih, const float* __restrict__ bhh,
    float* __restrict__ hout){
  __shared__ __align__(16) __nv_bfloat16 xh[32*136], xl[32*136];
  __shared__ __align__(16) __nv_bfloat16 hhs[32*136], hls[32*136];
  int t = threadIdx.x, lane = t&31, warp = t>>5;   // 8 warps
  long b0 = (long)blockIdx.x*32;
  for (int f=t; f<32*32; f+=256){
    int r = f>>5, c4 = (f&31)<<2;
    long b = b0 + r;
    float4 v;
    if (xin) v = *(const float4*)&xin[b*128 + c4];
    else     v = *(const float4*)&g_gf[b*128 + c4];
    split_st(v, xh, xl, r*136+c4);
    float4 hv = *(const float4*)&hist[((long)l*BQ + b)*128 + c4];
    split_st(hv, hhs, hls, r*136+c4);
  }
  __syncthreads();
  float cr[2][2][4], cz[2][2][4], cin[2][2][4], chn[2][2][4];
#pragma unroll
  for (int mt=0;mt<2;mt++)
#pragma unroll
    for (int nt=0;nt<2;nt++)
#pragma unroll
      for (int i=0;i<4;i++){ cr[mt][nt][i]=0.f; cz[mt][nt][i]=0.f;
                             cin[mt][nt][i]=0.f; chn[mt][nt][i]=0.f; }
  int sub = lane>>3;
  int m_off = ((sub&1)<<3) + (lane&7);
  int k_off = (sub>>1)<<3;
  const uint2* Wi = &g_Wf[WF_GI + l*3*8192];
  const uint2* Wh = &g_Wf[WF_GH + l*3*8192];
#pragma unroll 1
  for (int kt=0; kt<8; kt++){
    unsigned axh[2][4], axl[2][4], ahh[2][4], ahl[2][4];
#pragma unroll
    for (int mt=0;mt<2;mt++){
      int ro = (mt*16 + m_off)*136 + kt*16 + k_off;
      ldsm4(sptr(&xh[ro]),  axh[mt][0],axh[mt][1],axh[mt][2],axh[mt][3]);
      ldsm4(sptr(&xl[ro]),  axl[mt][0],axl[mt][1],axl[mt][2],axl[mt][3]);
      ldsm4(sptr(&hhs[ro]), ahh[mt][0],ahh[mt][1],ahh[mt][2],ahh[mt][3]);
      ldsm4(sptr(&hls[ro]), ahl[mt][0],ahl[mt][1],ahl[mt][2],ahl[mt][3]);
    }
#pragma unroll
    for (int nt=0;nt<2;nt++){
      int fo = (((kt*16 + warp*2 + nt)*2)<<5) + lane;
      { uint2 bh=Wi[fo], bl=Wi[fo+32];
        uint2 ch=Wh[fo], cl=Wh[fo+32];
#pragma unroll
        for (int mt=0;mt<2;mt++){
          mma3(cr[mt][nt], axh[mt], axl[mt], bh, bl);
          mma3(cr[mt][nt], ahh[mt], ahl[mt], ch, cl);
        } }
      { uint2 bh=Wi[8192+fo], bl=Wi[8192+fo+32];
        uint2 ch=Wh[8192+fo], cl=Wh[8192+fo+32];
#pragma unroll
        for (int mt=0;mt<2;mt++){
          mma3(cz[mt][nt], axh[mt], axl[mt], bh, bl);
          mma3(cz[mt][nt], ahh[mt], ahl[mt], ch, cl);
        } }
      { uint2 bh=Wi[16384+fo], bl=Wi[16384+fo+32];
        uint2 ch=Wh[16384+fo], cl=Wh[16384+fo+32];
#pragma unroll
        for (int mt=0;mt<2;mt++){
          mma3(cin[mt][nt], axh[mt], axl[mt], bh, bl);
          mma3(chn[mt][nt], ahh[mt], ahl[mt], ch, cl);
        } }
    }
  }
#pragma unroll
  for (int mt=0;mt<2;mt++){
    long gb = b0 + mt*16 + (lane>>2);
#pragma unroll
    for (int nt=0;nt<2;nt++){
      int col = warp*16 + nt*8 + ((lane&3)<<1);
      float2 bir = *(const float2*)&bih[l*384 + col];
      float2 biz = *(const float2*)&bih[l*384 + 128 + col];
      float2 bin_= *(const float2*)&bih[l*384 + 256 + col];
      float2 bhr = *(const float2*)&bhh[l*384 + col];
      float2 bhz = *(const float2*)&bhh[l*384 + 128 + col];
      float2 bhn = *(const float2*)&bhh[l*384 + 256 + col];
      float2 hp0 = *(const float2*)&hist[((long)l*BQ + gb)*128 + col];
      float2 hp1 = *(const float2*)&hist[((long)l*BQ + gb + 8)*128 + col];
      float r0=sigmf(cr[mt][nt][0]+bir.x+bhr.x);
      float r1=sigmf(cr[mt][nt][1]+bir.y+bhr.y);
      float r2=sigmf(cr[mt][nt][2]+bir.x+bhr.x);
      float r3=sigmf(cr[mt][nt][3]+bir.y+bhr.y);
      float z0=sigmf(cz[mt][nt][0]+biz.x+bhz.x);
      float z1=sigmf(cz[mt][nt][1]+biz.y+bhz.y);
      float z2=sigmf(cz[mt][nt][2]+biz.x+bhz.x);
      float z3=sigmf(cz[mt][nt][3]+biz.y+bhz.y);
      float n0=tanhf(cin[mt][nt][0]+bin_.x + r0*(chn[mt][nt][0]+bhn.x));
      float n1=tanhf(cin[mt][nt][1]+bin_.y + r1*(chn[mt][nt][1]+bhn.y));
      float n2=tanhf(cin[mt][nt][2]+bin_.x + r2*(chn[mt][nt][2]+bhn.x));
      float n3=tanhf(cin[mt][nt][3]+bin_.y + r3*(chn[mt][nt][3]+bhn.y));
      *(float2*)&hout[gb*128 + col] =
          make_float2((1.f-z0)*n0 + z0*hp0.x, (1.f-z1)*n1 + z1*hp0.y);
      *(float2*)&hout[(gb+8)*128 + col] =
          make_float2((1.f-z2)*n2 + z2*hp1.x, (1.f-z3)*n3 + z3*hp1.y);
    }
  }
}

// ------------------- cm MLP fused (2 GEMMs) + l_z --------------------------
__global__ __launch_bounds__(256,5) void k_cm(
    const float* __restrict__ b1, const float* __restrict__ b2){
  __shared__ __align__(16) __nv_bfloat16 sh[32*136], sl[32*136];
  int t = threadIdx.x, lane = t&31, warp = t>>5;
  int wrow = warp>>2, wcol = warp&3;
  long b0 = (long)blockIdx.x*32;
  stage_split<32,128,136,256>(g_ps + b0*128, 128, sh, sl, t);
  __syncthreads();
  float c[4][4];
  hmma_row<8,4,16,136>(sh, sl, &g_Wf[WF_CM1], wcol*4, wrow*16, lane, c);
  __syncthreads();
  {
    int r0 = wrow*16 + (lane>>2);
#pragma unroll
    for (int nt=0;nt<4;nt++){
      int col = (wcol*4+nt)*8 + ((lane&3)<<1);
      float2 bb = *(const float2*)&b1[col];
      float v00=mishf(c[nt][0]+bb.x), v01=mishf(c[nt][1]+bb.y);
      float v10=mishf(c[nt][2]+bb.x), v11=mishf(c[nt][3]+bb.y);
      *(unsigned*)&sh[r0*136+col] = pkh(v00,v01);
      *(unsigned*)&sl[r0*136+col] = pkh(v00-bf16f(v00), v01-bf16f(v01));
      *(unsigned*)&sh[(r0+8)*136+col] = pkh(v10,v11);
      *(unsigned*)&sl[(r0+8)*136+col] = pkh(v10-bf16f(v10), v11-bf16f(v11));
    }
  }
  __syncthreads();
  hmma_row<8,4,16,136>(sh, sl, &g_Wf[WF_CM2], wcol*4, wrow*16, lane, c);
  float lz = 0.f;
  {
    long r0 = b0 + wrow*16 + (lane>>2);
#pragma unroll
    for (int nt=0;nt<4;nt++){
      int col = (wcol*4+nt)*8 + ((lane&3)<<1);
      float2 bb = *(const float2*)&b2[col];
      float2 z0 = *(const float2*)&g_z[r0*128 + col];
      float2 z1 = *(const float2*)&g_z[(r0+8)*128 + col];
      float d0 = z0.x - (c[nt][0]+bb.x);
      float d1 = z0.y - (c[nt][1]+bb.y);
      float d2 = z1.x - (c[nt][2]+bb.x);
      float d3 = z1.y - (c[nt][3]+bb.y);
      lz += d0*d0 + d1*d1 + d2*d2 + d3*d3;
    }
  }
  BLOCK_REDUCE8_TO(g_lzpart, lz);
}

// ----------------- decoder fused (2 GEMMs) + losses ------------------------
__global__ __launch_bounds__(256,5) void k_dec(
    const float* __restrict__ b1, const float* __restrict__ b2,
    const float* __restrict__ yt_g, float* __restrict__ out){
  __shared__ __align__(16) __nv_bfloat16 sh[32*136], sl[32*136];
  __shared__ float s_piw[8][32], s_kd[8][32], s_mn[8][32], s_mx[8][32];
  __shared__ float s_sc[3][8];
  float* s_out = (float*)sh;     // 32*66 floats = 8448B <= 8704B ✓
  int t = threadIdx.x, lane = t&31, warp = t>>5;
  int wrow = warp>>2, wcol = warp&3;
  int n = blockIdx.y;
  long b0 = (long)blockIdx.x*32;
  stage_split<32,128,136,256>(g_z + b0*640 + n*128, 640, sh, sl, t);
  __syncthreads();
  float c[4][4];
  hmma_row<8,4,16,136>(sh, sl, &g_Wf[WF_DEC1 + n*8192], wcol*4, wrow*16, lane, c);
  __syncthreads();
  {
    int r0 = wrow*16 + (lane>>2);
#pragma unroll
    for (int nt=0;nt<4;nt++){
      int col = (wcol*4+nt)*8 + ((lane&3)<<1);
      float2 bb = *(const float2*)&b1[n*128 + col];
      float v00=mishf(c[nt][0]+bb.x), v01=mishf(c[nt][1]+bb.y);
      float v10=mishf(c[nt][2]+bb.x), v11=mishf(c[nt][3]+bb.y);
      *(unsigned*)&sh[r0*136+col] = pkh(v00,v01);
      *(unsigned*)&sl[r0*136+col] = pkh(v00-bf16f(v00), v01-bf16f(v01));
      *(unsigned*)&sh[(r0+8)*136+col] = pkh(v10,v11);
      *(unsigned*)&sl[(r0+8)*136+col] = pkh(v10-bf16f(v10), v11-bf16f(v11));
    }
  }
  __syncthreads();
  float c2[2][4];
  hmma_row<8,2,8,136>(sh, sl, &g_Wf[WF_DEC2 + n*4096], wcol*2, wrow*16, lane, c2);
  __syncthreads();   // all reads of sh done before aliasing as s_out
  {
    int r = wrow*16 + (lane>>2);
#pragma unroll
    for (int nt=0;nt<2;nt++){
      int col = (wcol*2+nt)*8 + ((lane&3)<<1);
      float2 bb = *(const float2*)&b2[n*64 + col];
      float v00=c2[nt][0]+bb.x, v01=c2[nt][1]+bb.y;
      float v10=c2[nt][2]+bb.x, v11=c2[nt][3]+bb.y;
      if (col >= 32){ v00=expf(v00); v01=expf(v01); v10=expf(v10); v11=expf(v11); }
      s_out[r*66+col]=v00;     s_out[r*66+col+1]=v01;
      s_out[(r+8)*66+col]=v10; s_out[(r+8)*66+col+1]=v11;
      long gb0, gb1;
      if (col < 32){
        gb0 = (b0+r)*160 + n*32 + col;
        gb1 = (b0+r+8)*160 + n*32 + col;
      } else {
        gb0 = (long)OFF_V + (b0+r)*160 + n*32 + col-32;
        gb1 = (long)OFF_V + (b0+r+8)*160 + n*32 + col-32;
      }
      *(float2*)&out[gb0] = make_float2(v00,v01);
      *(float2*)&out[gb1] = make_float2(v10,v11);
    }
  }
  __syncthreads();
  int d = lane;
  float ll=0.f, sq4=0.f, bce=0.f;
  float piw=0.f, kd=0.f, mn=1e30f, mx=-1e30f;
#pragma unroll
  for (int i=0;i<4;i++){
    int row = warp + 8*i;
    float ym = s_out[row*66 + d];
    float yv = s_out[row*66 + 32 + d];
    float yt = yt_g[(b0+row)*160 + n*32 + d];
    float vs = yv + 1e-6f;
    float df = yt - ym;
    ll += -0.5f*(df*df/vs + logf(6.2831853071795864f*vs));
    if (n < 4) sq4 += df*df;
    if (n == 4) bce += fmaxf(ym,0.f) - ym*yt + log1pf(expf(-fabsf(ym)));
    float s  = sqrtf(vs);
    float lo_ = ym - ZALPHA*s, up_ = ym + ZALPHA*s;
    float kf = (yt >= lo_ && yt <= up_) ? 1.f : 0.f;
    kd  += kf;
    piw += (up_-lo_)*kf;
    mn = fminf(mn, yt);
    mx = fmaxf(mx, yt);
  }
  ll  = warp_sum(ll);
  sq4 = warp_sum(sq4);
  bce = warp_sum(bce);
  if (lane == 0){ s_sc[0][warp]=ll; s_sc[1][warp]=sq4; s_sc[2][warp]=bce; }
  s_piw[warp][d]=piw; s_kd[warp][d]=kd; s_mn[warp][d]=mn; s_mx[warp][d]=mx;
  __syncthreads();
  int blk = blockIdx.y*gridDim.x + blockIdx.x;
  float* P = g_losspart + blk*132;
  if (t == 0){
    P[0] = ((s_sc[0][0]+s_sc[0][1]) + (s_sc[0][2]+s_sc[0][3]))
         + ((s_sc[0][4]+s_sc[0][5]) + (s_sc[0][6]+s_sc[0][7]));
    P[1] = ((s_sc[1][0]+s_sc[1][1]) + (s_sc[1][2]+s_sc[1][3]))
         + ((s_sc[1][4]+s_sc[1][5]) + (s_sc[1][6]+s_sc[1][7]));
    P[2] = ((s_sc[2][0]+s_sc[2][1]) + (s_sc[2][2]+s_sc[2][3]))
         + ((s_sc[2][4]+s_sc[2][5]) + (s_sc[2][6]+s_sc[2][7]));
    P[3] = 0.f;
  }
  if (t < 32){
    float p=0.f, k=0.f, m=1e30f, xx=-1e30f;
#pragma unroll
    for (int g=0; g<8; g++){
      p += s_piw[g][t]; k += s_kd[g][t];
      m = fminf(m, s_mn[g][t]); xx = fmaxf(xx, s_mx[g][t]);
    }
    P[4+t] = p; P[36+t] = k; P[68+t] = m; P[100+t] = xx;
  }
}

// ---------------------- stage-1 reduce + final -----------------------------
__global__ void k_reduce1(){
  int col = blockIdx.x, t = threadIdx.x;
  bool ismin = (col >= 68 && col < 100);
  bool ismax = (col >= 100 && col < 132);
  float v = ismin ? 1e30f : (ismax ? -1e30f : 0.f);
  if (col < 132){
    for (int i=t; i<5120; i+=256){
      float x = g_losspart[i*132 + col];
      v = ismin ? fminf(v,x) : (ismax ? fmaxf(v,x) : v + x);
    }
  } else if (col == 132){
    for (int i=t; i<GMSG; i+=256) v += g_klpart[i];
  } else {
    for (int i=t; i<5120; i+=256) v += g_lzpart[i];
  }
  __shared__ float sm[256];
  sm[t] = v;
  __syncthreads();
  for (int s=128; s>0; s>>=1){
    if (t < s){
      float a = sm[t], b = sm[t+s];
      sm[t] = ismin ? fminf(a,b) : (ismax ? fmaxf(a,b) : a + b);
    }
    __syncthreads();
  }
  if (t == 0) g_facc[col] = sm[0];
}

__global__ void k_final(float* __restrict__ out){
  if (threadIdx.x != 0 || blockIdx.x != 0) return;
  float S_ll = g_facc[0], S_sq4 = g_facc[1], S_bce = g_facc[2];
  float kl = 0.5f*g_facc[132];
  float S_lz = g_facc[133];
  float mean_ll = S_ll / 5242880.0f;
  float elbo = kl/32768.0f - mean_ll;
  float l_reg = (S_sq4/32.0f) / (4.0f*32768.0f + 1e-6f);
  float l_cls = (S_bce/32.0f) / (32768.0f + 1e-6f);
  float l_rec = l_reg + l_cls;
  float Sk = 0.f, pin = 0.f;
  for (int d=0; d<32; d++){
    float kdv = g_facc[36+d];
    Sk += kdv;
    pin += g_facc[4+d] / (kdv + 1e-6f) / (g_facc[100+d] - g_facc[68+d] + 1e-6f);
  }
  float picp  = Sk / 5242880.0f;
  float pinaw = pin / 32.0f;
  float l_pi  = pinaw - sqrtf(5.0f)*picp;
  float l_z   = S_lz / 20971520.0f;
  float dag   = 0.0f;  // exact: diag((I+ac)^5)==1 for strictly-upper ac
  float total = powf(elbo*l_rec*l_pi*l_z*(dag + 1e-6f), 0.2f);
  out[OFF_LOSS+0] = total;
  out[OFF_LOSS+1] = elbo;
  out[OFF_LOSS+2] = l_rec;
  out[OFF_LOSS+3] = l_pi;
  out[OFF_LOSS+4] = l_z;
  out[OFF_LOSS+5] = dag;
}

// ------------------------------ launcher -----------------------------------
extern "C" void kernel_launch(void* const* d_in, const int* in_sizes, int n_in,
                              void* d_out, int out_size){
  const float* x       = (const float*)d_in[0];
  const float* y_true  = (const float*)d_in[1];
  const float* ew      = (const float*)d_in[2];
  const float* hist    = (const float*)d_in[3];
  const float* enc_W1  = (const float*)d_in[4];
  const float* enc_b1  = (const float*)d_in[5];
  const float* enc_W2  = (const float*)d_in[6];
  const float* enc_b2  = (const float*)d_in[7];
  const float* gcn_W   = (const float*)d_in[8];
  const float* gcn_b   = (const float*)d_in[9];
  const float* mu_W    = (const float*)d_in[10];
  const float* mu_b    = (const float*)d_in[11];
  const float* sig_W   = (const float*)d_in[12];
  const float* sig_b   = (const float*)d_in[13];
  const float* gru_Wih = (const float*)d_in[14];
  const float* gru_Whh = (const float*)d_in[15];
  const float* gru_bih = (const float*)d_in[16];
  const float* gru_bhh = (const float*)d_in[17];
  const float* cm      = (const float*)d_in[18];
  const float* cm_W1   = (const float*)d_in[19];
  const float* cm_b1   = (const float*)d_in[20];
  const float* cm_W2   = (const float*)d_in[21];
  const float* cm_b2   = (const float*)d_in[22];
  const float* dec_W1  = (const float*)d_in[23];
  const float* dec_b1  = (const float*)d_in[24];
  const float* dec_W2  = (const float*)d_in[25];
  const float* dec_b2  = (const float*)d_in[26];
  const int*   esrc    = (const int*)d_in[27];
  const int*   edst    = (const int*)d_in[28];
  float* out = (float*)d_out;

  static cudaStream_t s2 = 0, s3 = 0;
  static cudaEvent_t evFork = 0, evJoin = 0, evJoin3 = 0;
  if (!s2){
    cudaStreamCreateWithFlags(&s2, cudaStreamNonBlocking);
    cudaStreamCreateWithFlags(&s3, cudaStreamNonBlocking);
    cudaEventCreateWithFlags(&evFork, cudaEventDisableTiming);
    cudaEventCreateWithFlags(&evJoin, cudaEventDisableTiming);
    cudaEventCreateWithFlags(&evJoin3, cudaEventDisableTiming);
  }

  k_packall<<<(WF_TOT+255)/256, 256>>>(enc_W1, enc_W2, gcn_W, mu_W, sig_W,
                                       cm_W1, cm_W2, dec_W1, dec_W2,
                                       gru_Wih, gru_Whh);
  k_enc<<<dim3(BQ/32, NND), 256>>>(x, enc_b1, enc_b2);
  k_gcn<<<5120, 256>>>(ew, esrc, edst, gcn_b);
  k_gcnms<<<GMSG, 256>>>(ew, esrc, edst, gcn_b, mu_b, sig_b, cm);

  // fork: all three consumers depend only on k_gcnms outputs
  cudaEventRecord(evFork, 0);
  cudaStreamWaitEvent(s2, evFork, 0);
  k_gru<<<BQ/32, 256, 0, s2>>>(0, nullptr, hist, gru_bih, gru_bhh,
                               out + OFF_HID);
  k_gru<<<BQ/32, 256, 0, s2>>>(1, out + OFF_HID, hist, gru_bih, gru_bhh,
                               out + OFF_HID + BQ*HDIM);
  cudaEventRecord(evJoin, s2);

  cudaStreamWaitEvent(s3, evFork, 0);
  k_cm<<<5120, 256, 0, s3>>>(cm_b1, cm_b2);
  cudaEventRecord(evJoin3, s3);

  k_dec<<<dim3(BQ/32, NND), 256>>>(dec_b1, dec_b2, y_true, out);

  cudaStreamWaitEvent(0, evJoin, 0);
  cudaStreamWaitEvent(0, evJoin3, 0);
  k_reduce1<<<134, 256>>>();
  k_final<<<1, 32>>>(out);
}

// round 15
// speedup vs baseline: 1.3495x; 1.0342x over previous
#include <cuda_runtime.h>
#include <cuda_bf16.h>
#include <math.h>

#define BQ   32768
#define NND  5
#define HDIM 128
#define NE   10
#define GMSG 5462            /* ceil(163840/30) batch-aligned gcnms grid */

#define OFF_V    (BQ*NND*32)
#define OFF_HID  (2*BQ*NND*32)
#define OFF_LOSS (OFF_HID + 2*BQ*HDIM)

#define ZALPHA 1.959963984540054f

// fragment arena offsets (uint2 units)
#define WF_ENC1 0
#define WF_ENC2 10240
#define WF_GCN  51200
#define WF_MU   67584
#define WF_SIG  75776
#define WF_CM1  83968
#define WF_CM2  92160
#define WF_DEC1 100352
#define WF_DEC2 141312
#define WF_GI   161792
#define WF_GH   210944
#define WF_TOT  260096

// ----------------------------- device scratch -----------------------------
__device__ float g_bufA[BQ*NND*HDIM];
__device__ float g_z  [BQ*NND*HDIM];
__device__ float g_ps [BQ*NND*HDIM];
__device__ float g_gf [BQ*HDIM];
__device__ uint2 g_Wf [WF_TOT];
__device__ float g_klpart[5504];
__device__ float g_lzpart[5120];
__device__ float g_losspart[5120*132];
__device__ float g_facc[134];

// ------------------------------- helpers ----------------------------------
__device__ __forceinline__ float warp_sum(float v){
#pragma unroll
  for (int o=16;o>0;o>>=1) v += __shfl_xor_sync(0xffffffffu, v, o);
  return v;
}
__device__ __forceinline__ float softplusf(float x){
  return fmaxf(x,0.f) + log1pf(expf(-fabsf(x)));
}
__device__ __forceinline__ float mishf(float x){ return x*tanhf(softplusf(x)); }
__device__ __forceinline__ float sigmf(float x){ return 1.f/(1.f+expf(-x)); }

#define BLOCK_REDUCE8_TO(part, val)                                     \
  do {                                                                  \
    float _v = warp_sum(val);                                           \
    __shared__ float _sred[8];                                          \
    if ((threadIdx.x & 31) == 0) _sred[threadIdx.x >> 5] = _v;          \
    __syncthreads();                                                    \
    if (threadIdx.x == 0)                                               \
      part[blockIdx.x] = ((_sred[0]+_sred[1]) + (_sred[2]+_sred[3]))    \
                       + ((_sred[4]+_sred[5]) + (_sred[6]+_sred[7]));   \
  } while (0)

__device__ __forceinline__ unsigned pkh(float x, float y){
  unsigned short a = __bfloat16_as_ushort(__float2bfloat16_rn(x));
  unsigned short b = __bfloat16_as_ushort(__float2bfloat16_rn(y));
  return ((unsigned)b<<16) | (unsigned)a;
}
__device__ __forceinline__ float bf16f(float x){
  return __bfloat162float(__float2bfloat16_rn(x));
}
__device__ __forceinline__ unsigned sptr(const void* p){
  return (unsigned)__cvta_generic_to_shared(p);
}
__device__ __forceinline__ void ldsm4(unsigned a, unsigned &r0, unsigned &r1,
                                      unsigned &r2, unsigned &r3){
  asm volatile("ldmatrix.sync.aligned.m8n8.x4.shared.b16 {%0,%1,%2,%3}, [%4];"
               : "=r"(r0),"=r"(r1),"=r"(r2),"=r"(r3) : "r"(a));
}
__device__ __forceinline__ void mma16816(float* c, const unsigned* a,
                                         unsigned b0, unsigned b1){
  asm volatile("mma.sync.aligned.m16n8k16.row.col.f32.bf16.bf16.f32 "
      "{%0,%1,%2,%3},{%4,%5,%6,%7},{%8,%9},{%0,%1,%2,%3};"
      : "+f"(c[0]),"+f"(c[1]),"+f"(c[2]),"+f"(c[3])
      : "r"(a[0]),"r"(a[1]),"r"(a[2]),"r"(a[3]),"r"(b0),"r"(b1));
}
__device__ __forceinline__ void mma3(float* c, const unsigned* ah,
    const unsigned* al, uint2 bh, uint2 bl){
  mma16816(c, ah, bh.x, bh.y);
  mma16816(c, al, bh.x, bh.y);
  mma16816(c, ah, bl.x, bl.y);
}

__device__ __forceinline__ void split_st(float4 v, __nv_bfloat16* sh,
    __nv_bfloat16* sl, int off){
  *(uint2*)&sh[off] = make_uint2(pkh(v.x,v.y), pkh(v.z,v.w));
  *(uint2*)&sl[off] = make_uint2(pkh(v.x-bf16f(v.x), v.y-bf16f(v.y)),
                                 pkh(v.z-bf16f(v.z), v.w-bf16f(v.w)));
}

template<int ROWS, int KC, int LDA, int NT_>
__device__ __forceinline__ void stage_split(const float* __restrict__ A, int arst,
    __nv_bfloat16* sh, __nv_bfloat16* sl, int t){
  const int C4 = KC/4;
  for (int f=t; f<ROWS*C4; f+=NT_){
    int r = f/C4, c4 = (f%C4)*4;
    float4 v = *(const float4*)&A[(long)r*arst + c4];
    split_st(v, sh, sl, r*LDA+c4);
  }
}

// 3-term bf16 split mainloop, 1 m16-tile per warp, NT n8-tiles
template<int KT, int NT, int NTOT, int LDA>
__device__ __forceinline__ void hmma_row(const __nv_bfloat16* sh,
    const __nv_bfloat16* sl, const uint2* __restrict__ Wf,
    int n8base, int rowbase, int lane, float (&c)[NT][4]){
#pragma unroll
  for (int nt=0;nt<NT;nt++)
#pragma unroll
    for (int i=0;i<4;i++) c[nt][i] = 0.f;
  int sub = lane>>3;
  int m_off = ((sub&1)<<3) + (lane&7);
  int k_off = (sub>>1)<<3;
#pragma unroll 1
  for (int kt=0; kt<KT; kt++){
    uint2 bh[NT], bl[NT];
#pragma unroll
    for (int nt=0;nt<NT;nt++){
      const uint2* wp = Wf + (((kt*NTOT + n8base + nt)*2)<<5) + lane;
      bh[nt] = wp[0];
      bl[nt] = wp[32];
    }
    unsigned ah[4], al[4];
    int ro = (rowbase + m_off)*LDA + kt*16 + k_off;
    ldsm4(sptr(&sh[ro]), ah[0],ah[1],ah[2],ah[3]);
    ldsm4(sptr(&sl[ro]), al[0],al[1],al[2],al[3]);
#pragma unroll
    for (int nt=0;nt<NT;nt++)
      mma3(c[nt], ah, al, bh[nt], bl[nt]);
  }
}

// --------------------------- single pack kernel ----------------------------
__global__ void k_packall(
    const float* __restrict__ encW1, const float* __restrict__ encW2,
    const float* __restrict__ gcnW,  const float* __restrict__ muW,
    const float* __restrict__ sigW,  const float* __restrict__ cmW1,
    const float* __restrict__ cmW2,  const float* __restrict__ decW1,
    const float* __restrict__ decW2, const float* __restrict__ giW,
    const float* __restrict__ ghW){
  int idx = blockIdx.x*256 + threadIdx.x;
  if (idx >= WF_TOT) return;
  const float* src; int K, N, trans, base, per, mst;
  if      (idx < WF_ENC2){ src=encW1; K=32; N=128; trans=0; base=WF_ENC1; per=2048; mst=4096; }
  else if (idx < WF_GCN ){ src=encW2; K=128;N=128; trans=0; base=WF_ENC2; per=8192; mst=16384;}
  else if (idx < WF_MU  ){ src=gcnW;  K=128;N=128; trans=0; base=WF_GCN;  per=8192; mst=16384;}
  else if (idx < WF_SIG ){ src=muW;   K=128;N=128; trans=0; base=WF_MU;   per=8192; mst=16384;}
  else if (idx < WF_CM1 ){ src=sigW;  K=128;N=128; trans=0; base=WF_SIG;  per=8192; mst=16384;}
  else if (idx < WF_CM2 ){ src=cmW1;  K=128;N=128; trans=0; base=WF_CM1;  per=8192; mst=16384;}
  else if (idx < WF_DEC1){ src=cmW2;  K=128;N=128; trans=0; base=WF_CM2;  per=8192; mst=16384;}
  else if (idx < WF_DEC2){ src=decW1; K=128;N=128; trans=0; base=WF_DEC1; per=8192; mst=16384;}
  else if (idx < WF_GI  ){ src=decW2; K=128;N=64;  trans=0; base=WF_DEC2; per=4096; mst=8192; }
  else if (idx < WF_GH  ){ src=giW;   K=128;N=128; trans=1; base=WF_GI;   per=8192; mst=16384;}
  else                   { src=ghW;   K=128;N=128; trans=1; base=WF_GH;   per=8192; mst=16384;}
  int rr = idx - base;
  int m = rr / per, r = rr % per;
  int lane = r & 31, term = (r>>5)&1;
  int n8 = (r>>6) % (N>>3);
  int kt = (r>>6) / (N>>3);
  int n = n8*8 + (lane>>2);
  int k0 = kt*16 + ((lane&3)<<1);
  const float* S = src + (long)m*mst;
  float w0,w1,w2,w3;
  if (trans){
    w0=S[n*K+k0]; w1=S[n*K+k0+1]; w2=S[n*K+k0+8]; w3=S[n*K+k0+9];
  } else {
    w0=S[k0*N+n]; w1=S[(k0+1)*N+n]; w2=S[(k0+8)*N+n]; w3=S[(k0+9)*N+n];
  }
  uint2 o;
  if (term==0){ o = make_uint2(pkh(w0,w1), pkh(w2,w3)); }
  else {
    o = make_uint2(pkh(w0-bf16f(w0), w1-bf16f(w1)),
                   pkh(w2-bf16f(w2), w3-bf16f(w3)));
  }
  g_Wf[idx] = o;
}

// ------------------------------ encoder ------------------------------------
__global__ __launch_bounds__(256,5) void k_enc(
    const float* __restrict__ x, const float* __restrict__ b1,
    const float* __restrict__ b2){
  __shared__ __align__(16) __nv_bfloat16 xh[32*40], xl[32*40];
  __shared__ __align__(16) __nv_bfloat16 hh[32*136], hl[32*136];
  int t = threadIdx.x, lane = t&31, warp = t>>5;
  int wrow = warp>>2, wcol = warp&3;
  int n = blockIdx.y;
  long b0 = (long)blockIdx.x*32;
  stage_split<32,32,40,256>(x + b0*160 + n*32, 160, xh, xl, t);
  __syncthreads();
  float c[4][4];
  hmma_row<2,4,16,40>(xh, xl, &g_Wf[WF_ENC1 + n*2048], wcol*4, wrow*16, lane, c);
  __syncthreads();
  {
    int r0 = wrow*16 + (lane>>2);
#pragma unroll
    for (int nt=0;nt<4;nt++){
      int col = (wcol*4+nt)*8 + ((lane&3)<<1);
      float2 bb = *(const float2*)&b1[n*128 + col];
      float v00=fmaxf(c[nt][0]+bb.x,0.f), v01=fmaxf(c[nt][1]+bb.y,0.f);
      float v10=fmaxf(c[nt][2]+bb.x,0.f), v11=fmaxf(c[nt][3]+bb.y,0.f);
      *(unsigned*)&hh[r0*136+col] = pkh(v00,v01);
      *(unsigned*)&hl[r0*136+col] = pkh(v00-bf16f(v00), v01-bf16f(v01));
      *(unsigned*)&hh[(r0+8)*136+col] = pkh(v10,v11);
      *(unsigned*)&hl[(r0+8)*136+col] = pkh(v10-bf16f(v10), v11-bf16f(v11));
    }
  }
  __syncthreads();
  hmma_row<8,4,16,136>(hh, hl, &g_Wf[WF_ENC2 + n*8192], wcol*4, wrow*16, lane, c);
  {
    long r0 = b0 + wrow*16 + (lane>>2);
#pragma unroll
    for (int nt=0;nt<4;nt++){
      int col = (wcol*4+nt)*8 + ((lane&3)<<1);
      float2 bb = *(const float2*)&b2[n*128 + col];
      *(float2*)&g_bufA[r0*640 + n*128 + col] =
          make_float2(c[nt][0]+bb.x, c[nt][1]+bb.y);
      *(float2*)&g_bufA[(r0+8)*640 + n*128 + col] =
          make_float2(c[nt][2]+bb.x, c[nt][3]+bb.y);
    }
  }
}

// - GCN l0 + l1 + mu/sig + KL + causal solve + parent_sum + graph_feat ------
// batch-aligned: 30 rows (6 batches) per CTA, rows 30-31 padded.
__global__ __launch_bounds__(256,5) void k_gcnms(
    const float* __restrict__ ew,
    const int* __restrict__ esrc, const int* __restrict__ edst,
    const float* __restrict__ bias,
    const float* __restrict__ mub, const float* __restrict__ sigb,
    const float* __restrict__ cmw){
  __shared__ __align__(16) __nv_bfloat16 sh[32*136], sl[32*136];
  __shared__ float mf[32*132];
  __shared__ float s_cm[25], s_ew[60];
  __shared__ int s_src[NE], s_dst[NE];
  int t = threadIdx.x, lane = t&31, warp = t>>5;
  int wrow = warp>>2, wcol = warp&3;
  long b0 = (long)blockIdx.x*30;
  if (t < NE){ s_src[t] = esrc[t]; s_dst[t] = edst[t]; }
  if (t < 25) s_cm[t] = cmw[t];
  if (t >= 32 && t < 92){
    int q = t - 32;
    int bb = q/10, e = q%10;
    long Bg = (long)blockIdx.x*6 + bb;
    s_ew[q] = (Bg < 32768L) ? __ldg(&ew[Bg*NE + e]) : 0.f;
  }
  __syncthreads();
  // ---- stage 0: aggregate enc output (g_bufA), split to sh/sl ----
  for (int f=t; f<32*32; f+=256){
    int r = f>>5, c4 = (f&31)<<2;
    long R = b0 + r;
    float4 a = make_float4(0.f,0.f,0.f,0.f);
    if (r < 30 && R < 163840L){
      int bb = r/5, v = r - 5*bb;
      int b = (int)(R/5);
      const float* row = g_bufA + (long)b*640;
      a = *(const float4*)&row[v*128 + c4];
#pragma unroll
      for (int e=0;e<NE;e++){
        if (s_dst[e] == v){
          float w = s_ew[bb*10 + e];
          float4 g = *(const float4*)&row[s_src[e]*128 + c4];
          a.x += w*g.x; a.y += w*g.y; a.z += w*g.z; a.w += w*g.w;
        }
      }
    }
    split_st(a, sh, sl, r*136+c4);
  }
  __syncthreads();
  // ---- GEMM gcn layer 0 + ReLU -> fp32 into mf ----
  float c[4][4];
  hmma_row<8,4,16,136>(sh, sl, &g_Wf[WF_GCN], wcol*4, wrow*16, lane, c);
  __syncthreads();
  {
    int r0 = wrow*16 + (lane>>2);
#pragma unroll
    for (int nt=0;nt<4;nt++){
      int col = (wcol*4+nt)*8 + ((lane&3)<<1);
      float2 bb = *(const float2*)&bias[col];
      mf[r0*132 + col]       = fmaxf(c[nt][0]+bb.x,0.f);
      mf[r0*132 + col + 1]   = fmaxf(c[nt][1]+bb.y,0.f);
      mf[(r0+8)*132 + col]   = fmaxf(c[nt][2]+bb.x,0.f);
      mf[(r0+8)*132 + col+1] = fmaxf(c[nt][3]+bb.y,0.f);
    }
  }
  __syncthreads();
  // ---- stage 1: aggregate layer-0 output (mf), split to sh/sl ----
  for (int f=t; f<32*32; f+=256){
    int r = f>>5, c4 = (f&31)<<2;
    long R = b0 + r;
    float4 a = make_float4(0.f,0.f,0.f,0.f);
    if (r < 30 && R < 163840L){
      int bb = r/5, v = r - 5*bb;
      int lr = bb*5;
      a.x = mf[(lr+v)*132 + c4];   a.y = mf[(lr+v)*132 + c4+1];
      a.z = mf[(lr+v)*132 + c4+2]; a.w = mf[(lr+v)*132 + c4+3];
#pragma unroll
      for (int e=0;e<NE;e++){
        if (s_dst[e] == v){
          float w = s_ew[bb*10 + e];
          int sr = (lr + s_src[e])*132 + c4;
          a.x += w*mf[sr];   a.y += w*mf[sr+1];
          a.z += w*mf[sr+2]; a.w += w*mf[sr+3];
        }
      }
    }
    split_st(a, sh, sl, r*136+c4);
  }
  __syncthreads();
  // ---- GEMM gcn layer 1 + ReLU, restage ----
  hmma_row<8,4,16,136>(sh, sl, &g_Wf[WF_GCN + 8192], wcol*4, wrow*16, lane, c);
  __syncthreads();
  {
    int r0 = wrow*16 + (lane>>2);
#pragma unroll
    for (int nt=0;nt<4;nt++){
      int col = (wcol*4+nt)*8 + ((lane&3)<<1);
      float2 bb = *(const float2*)&bias[128 + col];
      float v00=fmaxf(c[nt][0]+bb.x,0.f), v01=fmaxf(c[nt][1]+bb.y,0.f);
      float v10=fmaxf(c[nt][2]+bb.x,0.f), v11=fmaxf(c[nt][3]+bb.y,0.f);
      *(unsigned*)&sh[r0*136+col] = pkh(v00,v01);
      *(unsigned*)&sl[r0*136+col] = pkh(v00-bf16f(v00), v01-bf16f(v01));
      *(unsigned*)&sh[(r0+8)*136+col] = pkh(v10,v11);
      *(unsigned*)&sl[(r0+8)*136+col] = pkh(v10-bf16f(v10), v11-bf16f(v11));
    }
  }
  __syncthreads();
  // ---- mu head -> mf (smem) + masked m^2 KL ----
  float kll = 0.f;
  int r0m = wrow*16 + (lane>>2);
  bool v0 = (b0 + r0m) < 163840L;
  bool v1 = ((r0m+8) < 30) && ((b0 + r0m + 8) < 163840L);
  hmma_row<8,4,16,136>(sh, sl, &g_Wf[WF_MU], wcol*4, wrow*16, lane, c);
#pragma unroll
  for (int nt=0;nt<4;nt++){
    int col = (wcol*4+nt)*8 + ((lane&3)<<1);
    float2 bb = *(const float2*)&mub[col];
    float m00=c[nt][0]+bb.x, m01=c[nt][1]+bb.y;
    float m10=c[nt][2]+bb.x, m11=c[nt][3]+bb.y;
    mf[r0m*132 + col]     = m00;  mf[r0m*132 + col + 1]     = m01;
    mf[(r0m+8)*132 + col] = m10;  mf[(r0m+8)*132 + col + 1] = m11;
    if (v0) kll += m00*m00 + m01*m01;
    if (v1) kll += m10*m10 + m11*m11;
  }
  // ---- sig head -> masked softplus KL ----
  hmma_row<8,4,16,136>(sh, sl, &g_Wf[WF_SIG], wcol*4, wrow*16, lane, c);
#pragma unroll
  for (int nt=0;nt<4;nt++){
    int col = (wcol*4+nt)*8 + ((lane&3)<<1);
    float2 bb = *(const float2*)&sigb[col];
    if (v0){
      float sp0 = softplusf(c[nt][0]+bb.x), sp1 = softplusf(c[nt][1]+bb.y);
      float va0 = sp0*sp0, va1 = sp1*sp1;
      kll += va0 - logf(va0 + 1e-8f) - 1.f;
      kll += va1 - logf(va1 + 1e-8f) - 1.f;
    }
    if (v1){
      float sp2 = softplusf(c[nt][2]+bb.x), sp3 = softplusf(c[nt][3]+bb.y);
      float va2 = sp2*sp2, va3 = sp3*sp3;
      kll += va2 - logf(va2 + 1e-8f) - 1.f;
      kll += va3 - logf(va3 + 1e-8f) - 1.f;
    }
  }
  __syncthreads();   // mf fully written
  // ---- causal solve + parent_sum + graph_feat ----
  for (int f=t; f<768; f+=256){
    int bb = f>>7, cc = f&127;
    long Bg = (long)blockIdx.x*6 + bb;
    if (Bg < 32768L){
      int lr = bb*5;
      float z0 = mf[lr*132+cc],     z1 = mf[(lr+1)*132+cc];
      float z2 = mf[(lr+2)*132+cc], z3 = mf[(lr+3)*132+cc];
      float z4 = mf[(lr+4)*132+cc];
      float gf = z0; gf += z1; gf += z2; gf += z3; gf += z4;
      g_gf[Bg*128 + cc] = gf*0.2f;
#pragma unroll
      for (int j=1;j<NND;j++){
        float add = 0.f;
#pragma unroll
        for (int e=0;e<NE;e++){
          if (s_dst[e] == j){
            int s = s_src[e];
            float zs = (s==0)?z0:((s==1)?z1:((s==2)?z2:z3));
            add += s_ew[bb*10+e]*s_cm[s*NND + j]*zs;
          }
        }
        if (j==1) z1 += add; else if (j==2) z2 += add;
        else if (j==3) z3 += add; else z4 += add;
      }
      long gb = Bg*5*128 + cc;
      g_z[gb]       = z0; g_z[gb+128]   = z1; g_z[gb+256] = z2;
      g_z[gb+384]   = z3; g_z[gb+512]   = z4;
#pragma unroll
      for (int j=0;j<NND;j++){
        float ps = 0.f;
#pragma unroll
        for (int i=0;i<NND;i++){
          if (s_cm[i*NND + j] != 0.f)
            ps += (i==0)?z0:((i==1)?z1:((i==2)?z2:((i==3)?z3:z4)));
        }
        g_ps[gb + j*128] = ps;
      }
    }
  }
  BLOCK_REDUCE8_TO(g_klpart, kll);
}

// ------------- GRU: fused dual-GEMM + gates (one kernel per layer) ---------
__global__ __launch_bounds__(256) void k_gru(
    int l, const float* __restrict__ xin, const float* __restrict__ hist,
    const float* __restrict__ bih, const float* __restrict__ bhh,
    float* __restrict__ hout){
  __shared__ __align__(16) __nv_bfloat16 xh[32*136], xl[32*136];
  __shared__ __align__(16) __nv_bfloat16 hhs[32*136], hls[32*136];
  int t = threadIdx.x, lane = t&31, warp = t>>5;   // 8 warps
  long b0 = (long)blockIdx.x*32;
  for (int f=t; f<32*32; f+=256){
    int r = f>>5, c4 = (f&31)<<2;
    long b = b0 + r;
    float4 v;
    if (xin) v = *(const float4*)&xin[b*128 + c4];
    else     v = *(const float4*)&g_gf[b*128 + c4];
    split_st(v, xh, xl, r*136+c4);
    float4 hv = *(const float4*)&hist[((long)l*BQ + b)*128 + c4];
    split_st(hv, hhs, hls, r*136+c4);
  }
  __syncthreads();
  float cr[2][2][4], cz[2][2][4], cin[2][2][4], chn[2][2][4];
#pragma unroll
  for (int mt=0;mt<2;mt++)
#pragma unroll
    for (int nt=0;nt<2;nt++)
#pragma unroll
      for (int i=0;i<4;i++){ cr[mt][nt][i]=0.f; cz[mt][nt][i]=0.f;
                             cin[mt][nt][i]=0.f; chn[mt][nt][i]=0.f; }
  int sub = lane>>3;
  int m_off = ((sub&1)<<3) + (lane&7);
  int k_off = (sub>>1)<<3;
  const uint2* Wi = &g_Wf[WF_GI + l*3*8192];
  const uint2* Wh = &g_Wf[WF_GH + l*3*8192];
#pragma unroll 1
  for (int kt=0; kt<8; kt++){
    unsigned axh[2][4], axl[2][4], ahh[2][4], ahl[2][4];
#pragma unroll
    for (int mt=0;mt<2;mt++){
      int ro = (mt*16 + m_off)*136 + kt*16 + k_off;
      ldsm4(sptr(&xh[ro]),  axh[mt][0],axh[mt][1],axh[mt][2],axh[mt][3]);
      ldsm4(sptr(&xl[ro]),  axl[mt][0],axl[mt][1],axl[mt][2],axl[mt][3]);
      ldsm4(sptr(&hhs[ro]), ahh[mt][0],ahh[mt][1],ahh[mt][2],ahh[mt][3]);
      ldsm4(sptr(&hls[ro]), ahl[mt][0],ahl[mt][1],ahl[mt][2],ahl[mt][3]);
    }
#pragma unroll
    for (int nt=0;nt<2;nt++){
      int fo = (((kt*16 + warp*2 + nt)*2)<<5) + lane;
      { uint2 bh=Wi[fo], bl=Wi[fo+32];
        uint2 ch=Wh[fo], cl=Wh[fo+32];
#pragma unroll
        for (int mt=0;mt<2;mt++){
          mma3(cr[mt][nt], axh[mt], axl[mt], bh, bl);
          mma3(cr[mt][nt], ahh[mt], ahl[mt], ch, cl);
        } }
      { uint2 bh=Wi[8192+fo], bl=Wi[8192+fo+32];
        uint2 ch=Wh[8192+fo], cl=Wh[8192+fo+32];
#pragma unroll
        for (int mt=0;mt<2;mt++){
          mma3(cz[mt][nt], axh[mt], axl[mt], bh, bl);
          mma3(cz[mt][nt], ahh[mt], ahl[mt], ch, cl);
        } }
      { uint2 bh=Wi[16384+fo], bl=Wi[16384+fo+32];
        uint2 ch=Wh[16384+fo], cl=Wh[16384+fo+32];
#pragma unroll
        for (int mt=0;mt<2;mt++){
          mma3(cin[mt][nt], axh[mt], axl[mt], bh, bl);
          mma3(chn[mt][nt], ahh[mt], ahl[mt], ch, cl);
        } }
    }
  }
#pragma unroll
  for (int mt=0;mt<2;mt++){
    long gb = b0 + mt*16 + (lane>>2);
#pragma unroll
    for (int nt=0;nt<2;nt++){
      int col = warp*16 + nt*8 + ((lane&3)<<1);
      float2 bir = *(const float2*)&bih[l*384 + col];
      float2 biz = *(const float2*)&bih[l*384 + 128 + col];
      float2 bin_= *(const float2*)&bih[l*384 + 256 + col];
      float2 bhr = *(const float2*)&bhh[l*384 + col];
      float2 bhz = *(const float2*)&bhh[l*384 + 128 + col];
      float2 bhn = *(const float2*)&bhh[l*384 + 256 + col];
      float2 hp0 = *(const float2*)&hist[((long)l*BQ + gb)*128 + col];
      float2 hp1 = *(const float2*)&hist[((long)l*BQ + gb + 8)*128 + col];
      float r0=sigmf(cr[mt][nt][0]+bir.x+bhr.x);
      float r1=sigmf(cr[mt][nt][1]+bir.y+bhr.y);
      float r2=sigmf(cr[mt][nt][2]+bir.x+bhr.x);
      float r3=sigmf(cr[mt][nt][3]+bir.y+bhr.y);
      float z0=sigmf(cz[mt][nt][0]+biz.x+bhz.x);
      float z1=sigmf(cz[mt][nt][1]+biz.y+bhz.y);
      float z2=sigmf(cz[mt][nt][2]+biz.x+bhz.x);
      float z3=sigmf(cz[mt][nt][3]+biz.y+bhz.y);
      float n0=tanhf(cin[mt][nt][0]+bin_.x + r0*(chn[mt][nt][0]+bhn.x));
      float n1=tanhf(cin[mt][nt][1]+bin_.y + r1*(chn[mt][nt][1]+bhn.y));
      float n2=tanhf(cin[mt][nt][2]+bin_.x + r2*(chn[mt][nt][2]+bhn.x));
      float n3=tanhf(cin[mt][nt][3]+bin_.y + r3*(chn[mt][nt][3]+bhn.y));
      *(float2*)&hout[gb*128 + col] =
          make_float2((1.f-z0)*n0 + z0*hp0.x, (1.f-z1)*n1 + z1*hp0.y);
      *(float2*)&hout[(gb+8)*128 + col] =
          make_float2((1.f-z2)*n2 + z2*hp1.x, (1.f-z3)*n3 + z3*hp1.y);
    }
  }
}

// ------------------- cm MLP fused (2 GEMMs) + l_z --------------------------
__global__ __launch_bounds__(256,5) void k_cm(
    const float* __restrict__ b1, const float* __restrict__ b2){
  __shared__ __align__(16) __nv_bfloat16 sh[32*136], sl[32*136];
  int t = threadIdx.x, lane = t&31, warp = t>>5;
  int wrow = warp>>2, wcol = warp&3;
  long b0 = (long)blockIdx.x*32;
  stage_split<32,128,136,256>(g_ps + b0*128, 128, sh, sl, t);
  __syncthreads();
  float c[4][4];
  hmma_row<8,4,16,136>(sh, sl, &g_Wf[WF_CM1], wcol*4, wrow*16, lane, c);
  __syncthreads();
  {
    int r0 = wrow*16 + (lane>>2);
#pragma unroll
    for (int nt=0;nt<4;nt++){
      int col = (wcol*4+nt)*8 + ((lane&3)<<1);
      float2 bb = *(const float2*)&b1[col];
      float v00=mishf(c[nt][0]+bb.x), v01=mishf(c[nt][1]+bb.y);
      float v10=mishf(c[nt][2]+bb.x), v11=mishf(c[nt][3]+bb.y);
      *(unsigned*)&sh[r0*136+col] = pkh(v00,v01);
      *(unsigned*)&sl[r0*136+col] = pkh(v00-bf16f(v00), v01-bf16f(v01));
      *(unsigned*)&sh[(r0+8)*136+col] = pkh(v10,v11);
      *(unsigned*)&sl[(r0+8)*136+col] = pkh(v10-bf16f(v10), v11-bf16f(v11));
    }
  }
  __syncthreads();
  hmma_row<8,4,16,136>(sh, sl, &g_Wf[WF_CM2], wcol*4, wrow*16, lane, c);
  float lz = 0.f;
  {
    long r0 = b0 + wrow*16 + (lane>>2);
#pragma unroll
    for (int nt=0;nt<4;nt++){
      int col = (wcol*4+nt)*8 + ((lane&3)<<1);
      float2 bb = *(const float2*)&b2[col];
      float2 z0 = *(const float2*)&g_z[r0*128 + col];
      float2 z1 = *(const float2*)&g_z[(r0+8)*128 + col];
      float d0 = z0.x - (c[nt][0]+bb.x);
      float d1 = z0.y - (c[nt][1]+bb.y);
      float d2 = z1.x - (c[nt][2]+bb.x);
      float d3 = z1.y - (c[nt][3]+bb.y);
      lz += d0*d0 + d1*d1 + d2*d2 + d3*d3;
    }
  }
  BLOCK_REDUCE8_TO(g_lzpart, lz);
}

// ----------------- decoder fused (2 GEMMs) + losses ------------------------
__global__ __launch_bounds__(256,5) void k_dec(
    const float* __restrict__ b1, const float* __restrict__ b2,
    const float* __restrict__ yt_g, float* __restrict__ out){
  __shared__ __align__(16) __nv_bfloat16 sh[32*136], sl[32*136];
  __shared__ float s_piw[8][32], s_kd[8][32], s_mn[8][32], s_mx[8][32];
  __shared__ float s_sc[3][8];
  float* s_out = (float*)sh;     // 32*66 floats = 8448B <= 8704B ✓
  int t = threadIdx.x, lane = t&31, warp = t>>5;
  int wrow = warp>>2, wcol = warp&3;
  int n = blockIdx.y;
  long b0 = (long)blockIdx.x*32;
  stage_split<32,128,136,256>(g_z + b0*640 + n*128, 640, sh, sl, t);
  __syncthreads();
  float c[4][4];
  hmma_row<8,4,16,136>(sh, sl, &g_Wf[WF_DEC1 + n*8192], wcol*4, wrow*16, lane, c);
  __syncthreads();
  {
    int r0 = wrow*16 + (lane>>2);
#pragma unroll
    for (int nt=0;nt<4;nt++){
      int col = (wcol*4+nt)*8 + ((lane&3)<<1);
      float2 bb = *(const float2*)&b1[n*128 + col];
      float v00=mishf(c[nt][0]+bb.x), v01=mishf(c[nt][1]+bb.y);
      float v10=mishf(c[nt][2]+bb.x), v11=mishf(c[nt][3]+bb.y);
      *(unsigned*)&sh[r0*136+col] = pkh(v00,v01);
      *(unsigned*)&sl[r0*136+col] = pkh(v00-bf16f(v00), v01-bf16f(v01));
      *(unsigned*)&sh[(r0+8)*136+col] = pkh(v10,v11);
      *(unsigned*)&sl[(r0+8)*136+col] = pkh(v10-bf16f(v10), v11-bf16f(v11));
    }
  }
  __syncthreads();
  float c2[2][4];
  hmma_row<8,2,8,136>(sh, sl, &g_Wf[WF_DEC2 + n*4096], wcol*2, wrow*16, lane, c2);
  __syncthreads();   // all reads of sh done before aliasing as s_out
  {
    int r = wrow*16 + (lane>>2);
#pragma unroll
    for (int nt=0;nt<2;nt++){
      int col = (wcol*2+nt)*8 + ((lane&3)<<1);
      float2 bb = *(const float2*)&b2[n*64 + col];
      float v00=c2[nt][0]+bb.x, v01=c2[nt][1]+bb.y;
      float v10=c2[nt][2]+bb.x, v11=c2[nt][3]+bb.y;
      if (col >= 32){ v00=expf(v00); v01=expf(v01); v10=expf(v10); v11=expf(v11); }
      s_out[r*66+col]=v00;     s_out[r*66+col+1]=v01;
      s_out[(r+8)*66+col]=v10; s_out[(r+8)*66+col+1]=v11;
      long gb0, gb1;
      if (col < 32){
        gb0 = (b0+r)*160 + n*32 + col;
        gb1 = (b0+r+8)*160 + n*32 + col;
      } else {
        gb0 = (long)OFF_V + (b0+r)*160 + n*32 + col-32;
        gb1 = (long)OFF_V + (b0+r+8)*160 + n*32 + col-32;
      }
      *(float2*)&out[gb0] = make_float2(v00,v01);
      *(float2*)&out[gb1] = make_float2(v10,v11);
    }
  }
  __syncthreads();
  int d = lane;
  float ll=0.f, sq4=0.f, bce=0.f;
  float piw=0.f, kd=0.f, mn=1e30f, mx=-1e30f;
#pragma unroll
  for (int i=0;i<4;i++){
    int row = warp + 8*i;
    float ym = s_out[row*66 + d];
    float yv = s_out[row*66 + 32 + d];
    float yt = yt_g[(b0+row)*160 + n*32 + d];
    float vs = yv + 1e-6f;
    float df = yt - ym;
    ll += -0.5f*(df*df/vs + logf(6.2831853071795864f*vs));
    if (n < 4) sq4 += df*df;
    if (n == 4) bce += fmaxf(ym,0.f) - ym*yt + log1pf(expf(-fabsf(ym)));
    float s  = sqrtf(vs);
    float lo_ = ym - ZALPHA*s, up_ = ym + ZALPHA*s;
    float kf = (yt >= lo_ && yt <= up_) ? 1.f : 0.f;
    kd  += kf;
    piw += (up_-lo_)*kf;
    mn = fminf(mn, yt);
    mx = fmaxf(mx, yt);
  }
  ll  = warp_sum(ll);
  sq4 = warp_sum(sq4);
  bce = warp_sum(bce);
  if (lane == 0){ s_sc[0][warp]=ll; s_sc[1][warp]=sq4; s_sc[2][warp]=bce; }
  s_piw[warp][d]=piw; s_kd[warp][d]=kd; s_mn[warp][d]=mn; s_mx[warp][d]=mx;
  __syncthreads();
  int blk = blockIdx.y*gridDim.x + blockIdx.x;
  float* P = g_losspart + blk*132;
  if (t == 0){
    P[0] = ((s_sc[0][0]+s_sc[0][1]) + (s_sc[0][2]+s_sc[0][3]))
         + ((s_sc[0][4]+s_sc[0][5]) + (s_sc[0][6]+s_sc[0][7]));
    P[1] = ((s_sc[1][0]+s_sc[1][1]) + (s_sc[1][2]+s_sc[1][3]))
         + ((s_sc[1][4]+s_sc[1][5]) + (s_sc[1][6]+s_sc[1][7]));
    P[2] = ((s_sc[2][0]+s_sc[2][1]) + (s_sc[2][2]+s_sc[2][3]))
         + ((s_sc[2][4]+s_sc[2][5]) + (s_sc[2][6]+s_sc[2][7]));
    P[3] = 0.f;
  }
  if (t < 32){
    float p=0.f, k=0.f, m=1e30f, xx=-1e30f;
#pragma unroll
    for (int g=0; g<8; g++){
      p += s_piw[g][t]; k += s_kd[g][t];
      m = fminf(m, s_mn[g][t]); xx = fmaxf(xx, s_mx[g][t]);
    }
    P[4+t] = p; P[36+t] = k; P[68+t] = m; P[100+t] = xx;
  }
}

// ---------------------- stage-1 reduce + final -----------------------------
__global__ void k_reduce1(){
  int col = blockIdx.x, t = threadIdx.x;
  bool ismin = (col >= 68 && col < 100);
  bool ismax = (col >= 100 && col < 132);
  float v = ismin ? 1e30f : (ismax ? -1e30f : 0.f);
  if (col < 132){
    for (int i=t; i<5120; i+=256){
      float x = g_losspart[i*132 + col];
      v = ismin ? fminf(v,x) : (ismax ? fmaxf(v,x) : v + x);
    }
  } else if (col == 132){
    for (int i=t; i<GMSG; i+=256) v += g_klpart[i];
  } else {
    for (int i=t; i<5120; i+=256) v += g_lzpart[i];
  }
  __shared__ float sm[256];
  sm[t] = v;
  __syncthreads();
  for (int s=128; s>0; s>>=1){
    if (t < s){
      float a = sm[t], b = sm[t+s];
      sm[t] = ismin ? fminf(a,b) : (ismax ? fmaxf(a,b) : a + b);
    }
    __syncthreads();
  }
  if (t == 0) g_facc[col] = sm[0];
}

__global__ void k_final(float* __restrict__ out){
  if (threadIdx.x != 0 || blockIdx.x != 0) return;
  float S_ll = g_facc[0], S_sq4 = g_facc[1], S_bce = g_facc[2];
  float kl = 0.5f*g_facc[132];
  float S_lz = g_facc[133];
  float mean_ll = S_ll / 5242880.0f;
  float elbo = kl/32768.0f - mean_ll;
  float l_reg = (S_sq4/32.0f) / (4.0f*32768.0f + 1e-6f);
  float l_cls = (S_bce/32.0f) / (32768.0f + 1e-6f);
  float l_rec = l_reg + l_cls;
  float Sk = 0.f, pin = 0.f;
  for (int d=0; d<32; d++){
    float kdv = g_facc[36+d];
    Sk += kdv;
    pin += g_facc[4+d] / (kdv + 1e-6f) / (g_facc[100+d] - g_facc[68+d] + 1e-6f);
  }
  float picp  = Sk / 5242880.0f;
  float pinaw = pin / 32.0f;
  float l_pi  = pinaw - sqrtf(5.0f)*picp;
  float l_z   = S_lz / 20971520.0f;
  float dag   = 0.0f;  // exact: diag((I+ac)^5)==1 for strictly-upper ac
  float total = powf(elbo*l_rec*l_pi*l_z*(dag + 1e-6f), 0.2f);
  out[OFF_LOSS+0] = total;
  out[OFF_LOSS+1] = elbo;
  out[OFF_LOSS+2] = l_rec;
  out[OFF_LOSS+3] = l_pi;
  out[OFF_LOSS+4] = l_z;
  out[OFF_LOSS+5] = dag;
}

// ------------------------------ launcher -----------------------------------
extern "C" void kernel_launch(void* const* d_in, const int* in_sizes, int n_in,
                              void* d_out, int out_size){
  const float* x       = (const float*)d_in[0];
  const float* y_true  = (const float*)d_in[1];
  const float* ew      = (const float*)d_in[2];
  const float* hist    = (const float*)d_in[3];
  const float* enc_W1  = (const float*)d_in[4];
  const float* enc_b1  = (const float*)d_in[5];
  const float* enc_W2  = (const float*)d_in[6];
  const float* enc_b2  = (const float*)d_in[7];
  const float* gcn_W   = (const float*)d_in[8];
  const float* gcn_b   = (const float*)d_in[9];
  const float* mu_W    = (const float*)d_in[10];
  const float* mu_b    = (const float*)d_in[11];
  const float* sig_W   = (const float*)d_in[12];
  const float* sig_b   = (const float*)d_in[13];
  const float* gru_Wih = (const float*)d_in[14];
  const float* gru_Whh = (const float*)d_in[15];
  const float* gru_bih = (const float*)d_in[16];
  const float* gru_bhh = (const float*)d_in[17];
  const float* cm      = (const float*)d_in[18];
  const float* cm_W1   = (const float*)d_in[19];
  const float* cm_b1   = (const float*)d_in[20];
  const float* cm_W2   = (const float*)d_in[21];
  const float* cm_b2   = (const float*)d_in[22];
  const float* dec_W1  = (const float*)d_in[23];
  const float* dec_b1  = (const float*)d_in[24];
  const float* dec_W2  = (const float*)d_in[25];
  const float* dec_b2  = (const float*)d_in[26];
  const int*   esrc    = (const int*)d_in[27];
  const int*   edst    = (const int*)d_in[28];
  float* out = (float*)d_out;

  static cudaStream_t s2 = 0, s3 = 0;
  static cudaEvent_t evFork = 0, evJoin = 0, evJoin3 = 0;
  if (!s2){
    cudaStreamCreateWithFlags(&s2, cudaStreamNonBlocking);
    cudaStreamCreateWithFlags(&s3, cudaStreamNonBlocking);
    cudaEventCreateWithFlags(&evFork, cudaEventDisableTiming);
    cudaEventCreateWithFlags(&evJoin, cudaEventDisableTiming);
    cudaEventCreateWithFlags(&evJoin3, cudaEventDisableTiming);
  }

  k_packall<<<(WF_TOT+255)/256, 256>>>(enc_W1, enc_W2, gcn_W, mu_W, sig_W,
                                       cm_W1, cm_W2, dec_W1, dec_W2,
                                       gru_Wih, gru_Whh);
  k_enc<<<dim3(BQ/32, NND), 256>>>(x, enc_b1, enc_b2);
  k_gcnms<<<GMSG, 256>>>(ew, esrc, edst, gcn_b, mu_b, sig_b, cm);

  // fork: all three consumers depend only on k_gcnms outputs
  cudaEventRecord(evFork, 0);
  cudaStreamWaitEvent(s2, evFork, 0);
  k_gru<<<BQ/32, 256, 0, s2>>>(0, nullptr, hist, gru_bih, gru_bhh,
                               out + OFF_HID);
  k_gru<<<BQ/32, 256, 0, s2>>>(1, out + OFF_HID, hist, gru_bih, gru_bhh,
                               out + OFF_HID + BQ*HDIM);
  cudaEventRecord(evJoin, s2);

  cudaStreamWaitEvent(s3, evFork, 0);
  k_cm<<<5120, 256, 0, s3>>>(cm_b1, cm_b2);
  cudaEventRecord(evJoin3, s3);

  k_dec<<<dim3(BQ/32, NND), 256>>>(dec_b1, dec_b2, y_true, out);

  cudaStreamWaitEvent(0, evJoin, 0);
  cudaStreamWaitEvent(0, evJoin3, 0);
  k_reduce1<<<134, 256>>>();
  k_final<<<1, 32>>>(out);
}